// round 5
// baseline (speedup 1.0000x reference)
#include <cuda_runtime.h>
#include <math.h>
#include <stdint.h>

#define BATCH 8192
#define DIM   512
#define MEM   1000
#define MEMP  1024
#define HEADS 8
#define DH    64

// ==================== helpers ====================
__device__ __forceinline__ uint32_t smem_u32(const void* p) {
    uint32_t a;
    asm("{ .reg .u64 t; cvta.to.shared.u64 t, %1; cvt.u32.u64 %0, t; }" : "=r"(a) : "l"(p));
    return a;
}
__device__ __forceinline__ uint32_t f2tf(float x) {
    uint32_t u; asm("cvt.rna.tf32.f32 %0, %1;" : "=r"(u) : "f"(x)); return u;
}
__device__ __forceinline__ float f2tf_f(float x) { return __uint_as_float(f2tf(x)); }
__device__ __forceinline__ void mma_tf32(float* c, uint32_t a0, uint32_t a1,
                                         uint32_t a2, uint32_t a3,
                                         uint32_t b0, uint32_t b1) {
    asm volatile(
        "mma.sync.aligned.m16n8k8.row.col.f32.tf32.tf32.f32 "
        "{%0,%1,%2,%3}, {%4,%5,%6,%7}, {%8,%9}, {%0,%1,%2,%3};"
        : "+f"(c[0]), "+f"(c[1]), "+f"(c[2]), "+f"(c[3])
        : "r"(a0), "r"(a1), "r"(a2), "r"(a3), "r"(b0), "r"(b1));
}
__device__ __forceinline__ void cp_async16(uint32_t dst, const void* src, int srcsize) {
    asm volatile("cp.async.cg.shared.global [%0], [%1], 16, %2;"
                 :: "r"(dst), "l"(src), "r"(srcsize));
}
#define CP_COMMIT() asm volatile("cp.async.commit_group;" ::: "memory")
#define CP_WAIT(N)  asm volatile("cp.async.wait_group %0;" :: "n"(N) : "memory")

// ==================== scratch ====================
__device__ float g_h[BATCH*DIM];
__device__ float g_hn[BATCH*DIM];
__device__ float g_enc[BATCH*DIM];
__device__ float g_enc_t[BATCH*DIM];
__device__ float g_q[BATCH*DIM];
__device__ float g_ctx[BATCH*DIM];
__device__ float g_fused[BATCH*DIM];
__device__ float g_ns_t[BATCH*DIM];
__device__ float g_k[MEMP*DIM];
__device__ float g_v[MEMP*DIM];
__device__ float g_obs_t[BATCH*DIM];
__device__ float g_ego_t[BATCH*16];
__device__ float g_wm_t[MEM*DIM];
#define W_ENC1 0
#define W_ENC2 262144
#define W_WQ   524288
#define W_WK   786432
#define W_WV   1048576
#define W_WO   1310720
#define W_TR1  1572864
#define W_TR2  1843200
#define W_Q1   2105344
#define W_TOT  2170880
__device__ float g_w_t[W_TOT];
__device__ int   g_midx[BATCH];
__device__ int   g_mcount;

// ==================== prep: fp32 -> tf32-rounded fp32 ====================
struct PrepArgs {
    const float* src[12];
    float*       dst[12];
    int          n4[12];
};
__global__ void __launch_bounds__(256) prep_kernel(PrepArgs p) {
    int seg = blockIdx.y;
    int n4 = p.n4[seg];
    const float4* s = (const float4*)p.src[seg];
    float4* d = (float4*)p.dst[seg];
    for (int i = blockIdx.x * 256 + threadIdx.x; i < n4; i += gridDim.x * 256) {
        float4 v = s[i];
        float4 o;
        o.x = f2tf_f(v.x); o.y = f2tf_f(v.y);
        o.z = f2tf_f(v.z); o.w = f2tf_f(v.w);
        d[i] = o;
    }
}

// ==================== tf32 mma GEMM, 512 threads, 16 warps ====================
// CTA tile 128 x NT, warp tile 32 x NT/4 (4 row-warps x 4 col-warps), BK=32.
// EPI: 1 relu f32, 2 fuse->tf32, 3 quality, 4 tf32 (z-dual), 5 dual f32+tf32
#define GS 36
template<int NT, int EPI>
__global__ void __launch_bounds__(512) gemm_mma(
    const float* __restrict__ A, const float* __restrict__ A2,
    const float* __restrict__ W, const float* __restrict__ bias,
    const float* __restrict__ F, const float* __restrict__ w2,
    const float* __restrict__ b2, float* __restrict__ C, float* __restrict__ C2,
    int Mrows, int Kw, int Ktiles)
{
    constexpr int NF  = NT / 32;           // n-fragments per warp (warp cols = NT/4)
    constexpr int ASZ = 128 * GS;
    constexpr int WSZ = NT * GS;
    extern __shared__ float sm[];
    float* Asm = sm;
    float* Wsm = sm + 2 * ASZ;
    const uint32_t sA = smem_u32(Asm);
    const uint32_t sW = smem_u32(Wsm);

    // KV combined launch: z=1 -> second weight/output set (EPI==4 only)
    if (EPI == 4 && blockIdx.z) { W = F; C = C2; bias = w2; }

    const int tid = threadIdx.x;
    const int wid = tid >> 5, lane = tid & 31;
    const int g = lane >> 2, t = lane & 3;
    const int wr = wid & 3, wc = wid >> 2;
    const int row0 = blockIdx.y * 128;
    const int col0 = blockIdx.x * NT;

    float acc[2][NF][4];
    #pragma unroll
    for (int mf = 0; mf < 2; ++mf)
        #pragma unroll
        for (int nf = 0; nf < NF; ++nf)
            #pragma unroll
            for (int c = 0; c < 4; ++c) acc[mf][nf][c] = 0.f;

    auto load_chunk = [&](int ct, int buf) {
        const int kbase = ct * 32;
        constexpr int NLOAD = (1024 + NT * 8) / 512;
        #pragma unroll
        for (int it = 0; it < NLOAD; ++it) {
            int vid = tid + it * 512;
            if (vid < 1024) {
                int r = vid >> 3, q = vid & 7;
                int kel = kbase + q * 4;
                int grow = row0 + r;
                const float* src = A;
                int sz = 0;
                if (grow < Mrows) {
                    if (kel < 512) { src = A + (size_t)grow * 512 + kel; sz = 16; }
                    else if (A2 != nullptr && kel < 528) {
                        src = A2 + (size_t)grow * 16 + (kel - 512); sz = 16;
                    }
                }
                cp_async16(sA + (buf * ASZ + r * GS + q * 4) * 4, src, sz);
            } else {
                int vid2 = vid - 1024;
                int r = vid2 >> 3, q = vid2 & 7;
                int kel = kbase + q * 4;
                const float* src = W + (size_t)(col0 + r) * Kw + kel;
                int sz = (kel < Kw) ? 16 : 0;
                cp_async16(sW + (buf * WSZ + r * GS + q * 4) * 4, src, sz);
            }
        }
        CP_COMMIT();
    };

    load_chunk(0, 0);

    for (int ct = 0; ct < Ktiles; ++ct) {
        const int buf = ct & 1;
        if (ct + 1 < Ktiles) { load_chunk(ct + 1, (ct + 1) & 1); CP_WAIT(1); }
        else                 { CP_WAIT(0); }
        __syncthreads();

        const float* Ab = Asm + buf * ASZ + (wr * 32) * GS;
        const float* Wb = Wsm + buf * WSZ + (wc * (NT / 4)) * GS;
        #pragma unroll
        for (int ks = 0; ks < 4; ++ks) {
            const int k0 = ks * 8;
            uint32_t af[2][4];
            #pragma unroll
            for (int mf = 0; mf < 2; ++mf) {
                const float* ar = Ab + (mf * 16) * GS + k0;
                af[mf][0] = __float_as_uint(ar[(g    ) * GS + t    ]);
                af[mf][1] = __float_as_uint(ar[(g + 8) * GS + t    ]);
                af[mf][2] = __float_as_uint(ar[(g    ) * GS + t + 4]);
                af[mf][3] = __float_as_uint(ar[(g + 8) * GS + t + 4]);
            }
            #pragma unroll
            for (int nf = 0; nf < NF; ++nf) {
                const float* wrp = Wb + (nf * 8 + g) * GS + k0;
                uint32_t b0 = __float_as_uint(wrp[t]);
                uint32_t b1 = __float_as_uint(wrp[t + 4]);
                mma_tf32(acc[0][nf], af[0][0], af[0][1], af[0][2], af[0][3], b0, b1);
                mma_tf32(acc[1][nf], af[1][0], af[1][1], af[1][2], af[1][3], b0, b1);
            }
        }
        __syncthreads();
    }

    if (EPI != 3) {
        #pragma unroll
        for (int mf = 0; mf < 2; ++mf) {
            #pragma unroll
            for (int r01 = 0; r01 < 2; ++r01) {
                int grow = row0 + wr * 32 + mf * 16 + g + r01 * 8;
                if (grow >= Mrows) continue;
                #pragma unroll
                for (int nf = 0; nf < NF; ++nf) {
                    int gcol = col0 + wc * (NT / 4) + nf * 8 + 2 * t;
                    float v0 = acc[mf][nf][r01 * 2 + 0] + bias[gcol];
                    float v1 = acc[mf][nf][r01 * 2 + 1] + bias[gcol + 1];
                    if (EPI == 1) { v0 = fmaxf(v0, 0.f); v1 = fmaxf(v1, 0.f); }
                    else if (EPI == 2) {
                        const float* fp = F + (size_t)grow * 512 + gcol;
                        v0 = 0.7f * fp[0] + 0.3f * v0;
                        v1 = 0.7f * fp[1] + 0.3f * v1;
                    }
                    if (EPI == 2 || EPI == 4) { v0 = f2tf_f(v0); v1 = f2tf_f(v1); }
                    *(float2*)(C + (size_t)grow * 512 + gcol) = make_float2(v0, v1);
                    if (EPI == 5)
                        *(float2*)(C2 + (size_t)grow * 512 + gcol) =
                            make_float2(f2tf_f(v0), f2tf_f(v1));
                }
            }
        }
    } else {
        // quality head (NT=128): sigmoid(b2 + sum relu(acc+b1)*w2)
        float* qpart = sm;
        __syncthreads();
        #pragma unroll
        for (int mf = 0; mf < 2; ++mf) {
            #pragma unroll
            for (int r01 = 0; r01 < 2; ++r01) {
                float s = 0.f;
                #pragma unroll
                for (int nf = 0; nf < NF; ++nf) {
                    int c = wc * (NT / 4) + nf * 8 + 2 * t;
                    float h0 = fmaxf(acc[mf][nf][r01 * 2 + 0] + bias[c], 0.f);
                    float h1 = fmaxf(acc[mf][nf][r01 * 2 + 1] + bias[c + 1], 0.f);
                    s += h0 * w2[c] + h1 * w2[c + 1];
                }
                int rl = wr * 32 + mf * 16 + r01 * 8 + g;
                qpart[rl * 17 + wc * 4 + t] = s;
            }
        }
        __syncthreads();
        if (tid < 128) {
            float s = b2[0];
            #pragma unroll
            for (int i = 0; i < 16; ++i) s += qpart[tid * 17 + i];
            C[row0 + tid] = 1.f / (1.f + expf(-s));
        }
    }
}
#define GEMM_SMEM(NT) ((2 * 128 * GS + 2 * (NT) * GS) * 4)

// ==================== tf32 mma flash attention (no-max softmax) ============
#define QS 68
#define VS 72
#define ATT_SMEM ((128*QS + 64*QS + 128*QS + 64*VS) * 4)
__global__ void __launch_bounds__(256, 2) attn_mma(
    const float* __restrict__ Q, const float* __restrict__ Kb,
    const float* __restrict__ Vb, float* __restrict__ ctx)
{
    extern __shared__ float sm[];
    float* Qs = sm;
    float* Ks = Qs + 128 * QS;
    float* Ps = Ks + 64 * QS;
    float* Vs = Ps + 128 * QS;
    const uint32_t sK = smem_u32(Ks);
    const uint32_t sV = smem_u32(Vs);

    const int h = blockIdx.x;
    const int b0 = blockIdx.y * 128;
    const int tid = threadIdx.x;
    const int wid = tid >> 5, lane = tid & 31;
    const int g = lane >> 2, t = lane & 3;
    const int qr = wid * 16;

    #pragma unroll
    for (int it = 0; it < 8; ++it) {
        int vid = tid + it * 256;
        int r = vid >> 4, q = vid & 15;
        float4 v = *(const float4*)(Q + (size_t)(b0 + r) * 512 + h * 64 + q * 4);
        *(float4*)&Qs[r * QS + q * 4] = v;
    }

    float oacc[8][4];
    float rsum[2] = {0.f, 0.f};
    #pragma unroll
    for (int nf = 0; nf < 8; ++nf)
        #pragma unroll
        for (int c = 0; c < 4; ++c) oacc[nf][c] = 0.f;

    for (int m0 = 0; m0 < MEMP; m0 += 64) {
        __syncthreads();
        #pragma unroll
        for (int it = 0; it < 4; ++it) {
            int vid = tid + it * 256;
            int r = vid >> 4, q = vid & 15;
            int gm = m0 + r;
            int sz = (gm < MEM) ? 16 : 0;
            cp_async16(sK + (r * QS + q * 4) * 4, Kb + (size_t)gm * 512 + h * 64 + q * 4, sz);
            cp_async16(sV + (r * VS + q * 4) * 4, Vb + (size_t)gm * 512 + h * 64 + q * 4, sz);
        }
        CP_COMMIT();
        CP_WAIT(0);
        __syncthreads();

        // ---- S = Q K^T ----
        float sacc[8][4];
        #pragma unroll
        for (int nf = 0; nf < 8; ++nf)
            #pragma unroll
            for (int c = 0; c < 4; ++c) sacc[nf][c] = 0.f;
        #pragma unroll
        for (int ks = 0; ks < 8; ++ks) {
            int k0 = ks * 8;
            uint32_t a0 = __float_as_uint(Qs[(qr + g    ) * QS + k0 + t    ]);
            uint32_t a1 = __float_as_uint(Qs[(qr + g + 8) * QS + k0 + t    ]);
            uint32_t a2 = __float_as_uint(Qs[(qr + g    ) * QS + k0 + t + 4]);
            uint32_t a3 = __float_as_uint(Qs[(qr + g + 8) * QS + k0 + t + 4]);
            #pragma unroll
            for (int nf = 0; nf < 8; ++nf) {
                uint32_t b0 = __float_as_uint(Ks[(nf * 8 + g) * QS + k0 + t    ]);
                uint32_t b1 = __float_as_uint(Ks[(nf * 8 + g) * QS + k0 + t + 4]);
                mma_tf32(sacc[nf], a0, a1, a2, a3, b0, b1);
            }
        }

        // ---- softmax numerator (shift-free: scores are tiny) ----
        #pragma unroll
        for (int r01 = 0; r01 < 2; ++r01) {
            float ps = 0.f;
            int prow = qr + g + r01 * 8;
            #pragma unroll
            for (int nf = 0; nf < 8; ++nf) {
                float p0 = 0.f, p1 = 0.f;
                if (m0 + nf * 8 + 2 * t     < MEM) p0 = __expf(sacc[nf][r01 * 2 + 0] * 0.125f);
                if (m0 + nf * 8 + 2 * t + 1 < MEM) p1 = __expf(sacc[nf][r01 * 2 + 1] * 0.125f);
                ps += p0 + p1;
                *(float2*)&Ps[prow * QS + nf * 8 + 2 * t] =
                    make_float2(f2tf_f(p0), f2tf_f(p1));
            }
            ps += __shfl_xor_sync(0xffffffffu, ps, 1);
            ps += __shfl_xor_sync(0xffffffffu, ps, 2);
            rsum[r01] += ps;
        }
        __syncwarp();

        // ---- O += P V ----
        #pragma unroll
        for (int ks = 0; ks < 8; ++ks) {
            int k0 = ks * 8;
            uint32_t a0 = __float_as_uint(Ps[(qr + g    ) * QS + k0 + t    ]);
            uint32_t a1 = __float_as_uint(Ps[(qr + g + 8) * QS + k0 + t    ]);
            uint32_t a2 = __float_as_uint(Ps[(qr + g    ) * QS + k0 + t + 4]);
            uint32_t a3 = __float_as_uint(Ps[(qr + g + 8) * QS + k0 + t + 4]);
            #pragma unroll
            for (int nf = 0; nf < 8; ++nf) {
                uint32_t b0 = __float_as_uint(Vs[(k0 + t    ) * VS + nf * 8 + g]);
                uint32_t b1 = __float_as_uint(Vs[(k0 + t + 4) * VS + nf * 8 + g]);
                mma_tf32(oacc[nf], a0, a1, a2, a3, b0, b1);
            }
        }
    }

    #pragma unroll
    for (int r01 = 0; r01 < 2; ++r01) {
        float inv = 1.f / rsum[r01];
        int grow = b0 + qr + g + r01 * 8;
        #pragma unroll
        for (int nf = 0; nf < 8; ++nf) {
            float2 o = make_float2(f2tf_f(oacc[nf][r01 * 2 + 0] * inv),
                                   f2tf_f(oacc[nf][r01 * 2 + 1] * inv));
            *(float2*)(ctx + (size_t)grow * 512 + h * 64 + nf * 8 + 2 * t) = o;
        }
    }
}

// ==================== LayerNorm: 4 rows per 512-thread block ====================
__global__ void __launch_bounds__(512) ln_kernel(
    const float* __restrict__ x, const float* __restrict__ g,
    const float* __restrict__ b, float* __restrict__ y)
{
    const int grp = threadIdx.x >> 7;          // 0..3 (row within block)
    const int tid = threadIdx.x & 127;
    const int row = blockIdx.x * 4 + grp;
    float4 v = *(const float4*)(x + (size_t)row * 512 + tid * 4);

    __shared__ float red[4][4];
    float s = v.x + v.y + v.z + v.w;
    #pragma unroll
    for (int o = 16; o > 0; o >>= 1) s += __shfl_xor_sync(0xffffffffu, s, o);
    if ((tid & 31) == 0) red[grp][tid >> 5] = s;
    __syncthreads();
    float mean = (red[grp][0] + red[grp][1] + red[grp][2] + red[grp][3]) * (1.f / 512.f);
    __syncthreads();

    float dx = v.x - mean, dy = v.y - mean, dz = v.z - mean, dw = v.w - mean;
    float ss = dx * dx + dy * dy + dz * dz + dw * dw;
    #pragma unroll
    for (int o = 16; o > 0; o >>= 1) ss += __shfl_xor_sync(0xffffffffu, ss, o);
    if ((tid & 31) == 0) red[grp][tid >> 5] = ss;
    __syncthreads();
    float var = (red[grp][0] + red[grp][1] + red[grp][2] + red[grp][3]) * (1.f / 512.f);
    float inv = rsqrtf(var + 1e-5f);

    float4 gg = *(const float4*)(g + tid * 4);
    float4 bb = *(const float4*)(b + tid * 4);
    float4 o;
    o.x = f2tf_f(dx * inv * gg.x + bb.x);
    o.y = f2tf_f(dy * inv * gg.y + bb.y);
    o.z = f2tf_f(dz * inv * gg.z + bb.z);
    o.w = f2tf_f(dw * inv * gg.w + bb.w);
    *(float4*)(y + (size_t)row * 512 + tid * 4) = o;
}

// ==================== mask compaction + memory EMA ====================
__global__ void __launch_bounds__(256) compact_kernel(
    const float* __restrict__ quality, int* __restrict__ midx, int* __restrict__ mcount)
{
    const int tid = threadIdx.x;
    const int base = tid * 32;
    int cnt = 0;
    for (int i = 0; i < 32; ++i) cnt += (quality[base + i] > 0.7f) ? 1 : 0;
    __shared__ int sc[256];
    __shared__ int offs[256];
    sc[tid] = cnt;
    __syncthreads();
    if (tid == 0) {
        int run = 0;
        for (int t = 0; t < 256; ++t) { offs[t] = run; run += sc[t]; }
        *mcount = run;
    }
    __syncthreads();
    int o = offs[tid];
    for (int i = 0; i < 32; ++i)
        if (quality[base + i] > 0.7f) midx[o++] = base + i;
}

__global__ void __launch_bounds__(128) memupd_kernel(
    const float* __restrict__ wm, const float* __restrict__ ns,
    const int* __restrict__ upd, const int* __restrict__ midx,
    const int* __restrict__ mcount, float* __restrict__ outmem)
{
    const int m = blockIdx.x;
    const int d = threadIdx.x * 4;
    float4 v = *(const float4*)(wm + (size_t)m * 512 + d);
    const int cnt = *mcount;
    for (int jj = 0; jj < cnt; ++jj) {
        int i = midx[jj];
        if (upd[i] == m) {
            float4 s = *(const float4*)(ns + (size_t)i * 512 + d);
            v.x = 0.9f * v.x + 0.1f * s.x;
            v.y = 0.9f * v.y + 0.1f * s.y;
            v.z = 0.9f * v.z + 0.1f * s.z;
            v.w = 0.9f * v.w + 0.1f * s.w;
        }
    }
    *(float4*)(outmem + (size_t)m * 512 + d) = v;
}

// ==================== host launcher ====================
extern "C" void kernel_launch(void* const* d_in, const int* in_sizes, int n_in,
                              void* d_out, int out_size)
{
    const float* obs    = (const float*)d_in[0];
    const float* ego    = (const float*)d_in[1];
    const float* wm     = (const float*)d_in[2];
    const float* enc_w1 = (const float*)d_in[3];
    const float* enc_b1 = (const float*)d_in[4];
    const float* enc_g  = (const float*)d_in[5];
    const float* enc_be = (const float*)d_in[6];
    const float* enc_w2 = (const float*)d_in[7];
    const float* enc_b2 = (const float*)d_in[8];
    const float* wq     = (const float*)d_in[9];
    const float* bq     = (const float*)d_in[10];
    const float* wk     = (const float*)d_in[11];
    const float* bk     = (const float*)d_in[12];
    const float* wv     = (const float*)d_in[13];
    const float* bv     = (const float*)d_in[14];
    const float* wo     = (const float*)d_in[15];
    const float* bo     = (const float*)d_in[16];
    const float* tr_w1  = (const float*)d_in[17];
    const float* tr_b1  = (const float*)d_in[18];
    const float* tr_g   = (const float*)d_in[19];
    const float* tr_be  = (const float*)d_in[20];
    const float* tr_w2  = (const float*)d_in[21];
    const float* tr_b2  = (const float*)d_in[22];
    const float* q_w1   = (const float*)d_in[23];
    const float* q_b1   = (const float*)d_in[24];
    const float* q_w2   = (const float*)d_in[25];
    const float* q_b2   = (const float*)d_in[26];
    const int*   uidx   = (const int*)d_in[27];

    float* out        = (float*)d_out;
    float* next_state = out;
    float* quality    = out + (size_t)BATCH * DIM;
    float* outmem     = quality + BATCH;

    float *h, *hn, *enc, *enc_t, *qb, *ctx, *fused, *ns_t, *kb, *vb;
    float *obs_t, *ego_t, *wm_t, *w_t;
    int *midx, *mcount;
    cudaGetSymbolAddress((void**)&h,      g_h);
    cudaGetSymbolAddress((void**)&hn,     g_hn);
    cudaGetSymbolAddress((void**)&enc,    g_enc);
    cudaGetSymbolAddress((void**)&enc_t,  g_enc_t);
    cudaGetSymbolAddress((void**)&qb,     g_q);
    cudaGetSymbolAddress((void**)&ctx,    g_ctx);
    cudaGetSymbolAddress((void**)&fused,  g_fused);
    cudaGetSymbolAddress((void**)&ns_t,   g_ns_t);
    cudaGetSymbolAddress((void**)&kb,     g_k);
    cudaGetSymbolAddress((void**)&vb,     g_v);
    cudaGetSymbolAddress((void**)&obs_t,  g_obs_t);
    cudaGetSymbolAddress((void**)&ego_t,  g_ego_t);
    cudaGetSymbolAddress((void**)&wm_t,   g_wm_t);
    cudaGetSymbolAddress((void**)&w_t,    g_w_t);
    cudaGetSymbolAddress((void**)&midx,   g_midx);
    cudaGetSymbolAddress((void**)&mcount, g_mcount);

    cudaFuncSetAttribute(gemm_mma<256,1>, cudaFuncAttributeMaxDynamicSharedMemorySize, GEMM_SMEM(256));
    cudaFuncSetAttribute(gemm_mma<256,2>, cudaFuncAttributeMaxDynamicSharedMemorySize, GEMM_SMEM(256));
    cudaFuncSetAttribute(gemm_mma<256,4>, cudaFuncAttributeMaxDynamicSharedMemorySize, GEMM_SMEM(256));
    cudaFuncSetAttribute(gemm_mma<256,5>, cudaFuncAttributeMaxDynamicSharedMemorySize, GEMM_SMEM(256));
    cudaFuncSetAttribute(gemm_mma<128,3>, cudaFuncAttributeMaxDynamicSharedMemorySize, GEMM_SMEM(128));
    cudaFuncSetAttribute(attn_mma,        cudaFuncAttributeMaxDynamicSharedMemorySize, ATT_SMEM);

    // ---- prep ----
    PrepArgs pa;
    const float* srcs[12] = {obs, ego, wm, enc_w1, enc_w2, wq, wk, wv, wo, tr_w1, tr_w2, q_w1};
    float* dsts[12] = {obs_t, ego_t, wm_t,
                       w_t + W_ENC1, w_t + W_ENC2, w_t + W_WQ, w_t + W_WK, w_t + W_WV,
                       w_t + W_WO, w_t + W_TR1, w_t + W_TR2, w_t + W_Q1};
    int n4s[12] = {BATCH*DIM/4, BATCH*16/4, MEM*DIM/4,
                   262144/4, 262144/4, 262144/4, 262144/4, 262144/4,
                   262144/4, 270336/4, 262144/4, 65536/4};
    for (int i = 0; i < 12; ++i) { pa.src[i] = srcs[i]; pa.dst[i] = dsts[i]; pa.n4[i] = n4s[i]; }
    prep_kernel<<<dim3(512, 12), 256>>>(pa);

    dim3 gBig(2, 64), gKV(2, 8, 2), gQual(1, 64);

    // encoder
    gemm_mma<256,1><<<gBig, 512, GEMM_SMEM(256)>>>(obs_t, nullptr, w_t + W_ENC1, enc_b1,
        nullptr, nullptr, nullptr, h, nullptr, BATCH, 512, 16);
    ln_kernel<<<BATCH/4, 512>>>(h, enc_g, enc_be, hn);
    gemm_mma<256,5><<<gBig, 512, GEMM_SMEM(256)>>>(hn, nullptr, w_t + W_ENC2, enc_b2,
        nullptr, nullptr, nullptr, enc, enc_t, BATCH, 512, 16);
    // projections (Q; K+V combined via blockIdx.z)
    gemm_mma<256,4><<<gBig, 512, GEMM_SMEM(256)>>>(enc_t, nullptr, w_t + W_WQ, bq,
        nullptr, nullptr, nullptr, qb, nullptr, BATCH, 512, 16);
    gemm_mma<256,4><<<gKV, 512, GEMM_SMEM(256)>>>(wm_t, nullptr, w_t + W_WK, bk,
        w_t + W_WV, bv, nullptr, kb, vb, MEM, 512, 16);
    // attention
    attn_mma<<<dim3(HEADS, BATCH / 128), 256, ATT_SMEM>>>(qb, kb, vb, ctx);
    // out projection + fuse
    gemm_mma<256,2><<<gBig, 512, GEMM_SMEM(256)>>>(ctx, nullptr, w_t + W_WO, bo,
        enc, nullptr, nullptr, fused, nullptr, BATCH, 512, 16);
    // transition
    gemm_mma<256,1><<<gBig, 512, GEMM_SMEM(256)>>>(fused, ego_t, w_t + W_TR1, tr_b1,
        nullptr, nullptr, nullptr, h, nullptr, BATCH, 528, 17);
    ln_kernel<<<BATCH/4, 512>>>(h, tr_g, tr_be, hn);
    gemm_mma<256,5><<<gBig, 512, GEMM_SMEM(256)>>>(hn, nullptr, w_t + W_TR2, tr_b2,
        nullptr, nullptr, nullptr, next_state, ns_t, BATCH, 512, 16);
    // quality head
    gemm_mma<128,3><<<gQual, 512, GEMM_SMEM(128)>>>(ns_t, nullptr, w_t + W_Q1, q_b1,
        nullptr, q_w2, q_b2, quality, nullptr, BATCH, 512, 16);
    // memory bank update
    compact_kernel<<<1, 256>>>(quality, midx, mcount);
    memupd_kernel<<<MEM, 128>>>(wm, next_state, uidx, midx, mcount, outmem);
}

// round 7
// speedup vs baseline: 1.5051x; 1.5051x over previous
#include <cuda_runtime.h>
#include <math.h>
#include <stdint.h>

#define BATCH 8192
#define DIM   512
#define MEM   1000
#define MEMP  1024
#define HEADS 8
#define DH    64

// ==================== helpers ====================
__device__ __forceinline__ uint32_t smem_u32(const void* p) {
    uint32_t a;
    asm("{ .reg .u64 t; cvta.to.shared.u64 t, %1; cvt.u32.u64 %0, t; }" : "=r"(a) : "l"(p));
    return a;
}
__device__ __forceinline__ uint32_t f2tf(float x) {
    uint32_t u; asm("cvt.rna.tf32.f32 %0, %1;" : "=r"(u) : "f"(x)); return u;
}
__device__ __forceinline__ float f2tf_f(float x) { return __uint_as_float(f2tf(x)); }
__device__ __forceinline__ void mma_tf32(float* c, uint32_t a0, uint32_t a1,
                                         uint32_t a2, uint32_t a3,
                                         uint32_t b0, uint32_t b1) {
    asm volatile(
        "mma.sync.aligned.m16n8k8.row.col.f32.tf32.tf32.f32 "
        "{%0,%1,%2,%3}, {%4,%5,%6,%7}, {%8,%9}, {%0,%1,%2,%3};"
        : "+f"(c[0]), "+f"(c[1]), "+f"(c[2]), "+f"(c[3])
        : "r"(a0), "r"(a1), "r"(a2), "r"(a3), "r"(b0), "r"(b1));
}
__device__ __forceinline__ void cp_async16(uint32_t dst, const void* src, int srcsize) {
    asm volatile("cp.async.cg.shared.global [%0], [%1], 16, %2;"
                 :: "r"(dst), "l"(src), "r"(srcsize));
}
#define CP_COMMIT() asm volatile("cp.async.commit_group;" ::: "memory")
#define CP_WAIT(N)  asm volatile("cp.async.wait_group %0;" :: "n"(N) : "memory")

// ==================== scratch ====================
__device__ float g_h[BATCH*DIM];
__device__ float g_hn[BATCH*DIM];
__device__ float g_enc[BATCH*DIM];
__device__ float g_enc_t[BATCH*DIM];
__device__ float g_q[BATCH*DIM];
__device__ float g_ctx[BATCH*DIM];
__device__ float g_fused[BATCH*DIM];
__device__ float g_ns_t[BATCH*DIM];
__device__ float g_k[MEMP*DIM];
__device__ float g_v[MEMP*DIM];
__device__ float g_obs_t[BATCH*DIM];
__device__ float g_ego_t[BATCH*16];
__device__ float g_wm_t[MEM*DIM];
#define W_ENC1 0
#define W_ENC2 262144
#define W_WQ   524288
#define W_WK   786432
#define W_WV   1048576
#define W_WO   1310720
#define W_TR1  1572864
#define W_TR2  1843200
#define W_Q1   2105344
#define W_TOT  2170880
__device__ float g_w_t[W_TOT];
__device__ int   g_midx[BATCH];
__device__ int   g_mcount;

// ==================== prep: fp32 -> tf32-rounded fp32 ====================
struct PrepArgs {
    const float* src[12];
    float*       dst[12];
    int          n4[12];
};
__global__ void __launch_bounds__(256) prep_kernel(PrepArgs p) {
    int seg = blockIdx.y;
    int n4 = p.n4[seg];
    const float4* s = (const float4*)p.src[seg];
    float4* d = (float4*)p.dst[seg];
    for (int i = blockIdx.x * 256 + threadIdx.x; i < n4; i += gridDim.x * 256) {
        float4 v = s[i];
        float4 o;
        o.x = f2tf_f(v.x); o.y = f2tf_f(v.y);
        o.z = f2tf_f(v.z); o.w = f2tf_f(v.w);
        d[i] = o;
    }
}

// ==================== tf32 mma GEMM, 256 threads, 8 warps (R4 shape) =========
// CTA tile 128 x NT, warp tile 64 x NT/4 (2 row-warps x 4 col-warps), BK=32.
// EPI: 1 relu f32, 2 fuse->tf32, 3 quality, 4 tf32 (z-dual), 5 dual f32+tf32
#define GS 36
template<int NT, int EPI>
__global__ void __launch_bounds__(256) gemm_mma(
    const float* __restrict__ A, const float* __restrict__ A2,
    const float* __restrict__ W, const float* __restrict__ bias,
    const float* __restrict__ F, const float* __restrict__ w2,
    const float* __restrict__ b2, float* __restrict__ C, float* __restrict__ C2,
    int Mrows, int Kw, int Ktiles)
{
    constexpr int NF  = NT / 32;
    constexpr int ASZ = 128 * GS;
    constexpr int WSZ = NT * GS;
    extern __shared__ float sm[];
    float* Asm = sm;
    float* Wsm = sm + 2 * ASZ;
    const uint32_t sA = smem_u32(Asm);
    const uint32_t sW = smem_u32(Wsm);

    // combined K/V launch: z=1 -> second weight/bias/output set (EPI==4 only)
    if (EPI == 4 && blockIdx.z) { W = F; C = C2; bias = w2; }

    const int tid = threadIdx.x;
    const int wid = tid >> 5, lane = tid & 31;
    const int g = lane >> 2, t = lane & 3;
    const int wm = wid & 1, wn = wid >> 1;
    const int row0 = blockIdx.y * 128;
    const int col0 = blockIdx.x * NT;

    float acc[4][NF][4];
    #pragma unroll
    for (int mf = 0; mf < 4; ++mf)
        #pragma unroll
        for (int nf = 0; nf < NF; ++nf)
            #pragma unroll
            for (int c = 0; c < 4; ++c) acc[mf][nf][c] = 0.f;

    auto load_chunk = [&](int ct, int buf) {
        const int kbase = ct * 32;
        constexpr int NLOAD = (1024 + NT * 8) / 256;
        #pragma unroll
        for (int it = 0; it < NLOAD; ++it) {
            int vid = tid + it * 256;
            if (vid < 1024) {
                int r = vid >> 3, q = vid & 7;
                int kel = kbase + q * 4;
                int grow = row0 + r;
                const float* src = A;
                int sz = 0;
                if (grow < Mrows) {
                    if (kel < 512) { src = A + (size_t)grow * 512 + kel; sz = 16; }
                    else if (A2 != nullptr && kel < 528) {
                        src = A2 + (size_t)grow * 16 + (kel - 512); sz = 16;
                    }
                }
                cp_async16(sA + (buf * ASZ + r * GS + q * 4) * 4, src, sz);
            } else {
                int vid2 = vid - 1024;
                int r = vid2 >> 3, q = vid2 & 7;
                int kel = kbase + q * 4;
                const float* src = W + (size_t)(col0 + r) * Kw + kel;
                int sz = (kel < Kw) ? 16 : 0;
                cp_async16(sW + (buf * WSZ + r * GS + q * 4) * 4, src, sz);
            }
        }
        CP_COMMIT();
    };

    load_chunk(0, 0);

    for (int ct = 0; ct < Ktiles; ++ct) {
        const int buf = ct & 1;
        if (ct + 1 < Ktiles) { load_chunk(ct + 1, (ct + 1) & 1); CP_WAIT(1); }
        else                 { CP_WAIT(0); }
        __syncthreads();

        const float* Ab = Asm + buf * ASZ + (wm * 64) * GS;
        const float* Wb = Wsm + buf * WSZ + (wn * (NT / 4)) * GS;
        #pragma unroll
        for (int ks = 0; ks < 4; ++ks) {
            const int k0 = ks * 8;
            uint32_t af[4][4];
            #pragma unroll
            for (int mf = 0; mf < 4; ++mf) {
                const float* ar = Ab + (mf * 16) * GS + k0;
                af[mf][0] = __float_as_uint(ar[(g    ) * GS + t    ]);
                af[mf][1] = __float_as_uint(ar[(g + 8) * GS + t    ]);
                af[mf][2] = __float_as_uint(ar[(g    ) * GS + t + 4]);
                af[mf][3] = __float_as_uint(ar[(g + 8) * GS + t + 4]);
            }
            #pragma unroll
            for (int nf = 0; nf < NF; ++nf) {
                const float* wrp = Wb + (nf * 8 + g) * GS + k0;
                uint32_t b0 = __float_as_uint(wrp[t]);
                uint32_t b1 = __float_as_uint(wrp[t + 4]);
                #pragma unroll
                for (int mf = 0; mf < 4; ++mf)
                    mma_tf32(acc[mf][nf], af[mf][0], af[mf][1], af[mf][2], af[mf][3], b0, b1);
            }
        }
        __syncthreads();
    }

    if (EPI != 3) {
        #pragma unroll
        for (int mf = 0; mf < 4; ++mf) {
            #pragma unroll
            for (int r01 = 0; r01 < 2; ++r01) {
                int grow = row0 + wm * 64 + mf * 16 + g + r01 * 8;
                if (grow >= Mrows) continue;
                #pragma unroll
                for (int nf = 0; nf < NF; ++nf) {
                    int gcol = col0 + wn * (NT / 4) + nf * 8 + 2 * t;
                    float v0 = acc[mf][nf][r01 * 2 + 0] + bias[gcol];
                    float v1 = acc[mf][nf][r01 * 2 + 1] + bias[gcol + 1];
                    if (EPI == 1) { v0 = fmaxf(v0, 0.f); v1 = fmaxf(v1, 0.f); }
                    else if (EPI == 2) {
                        const float* fp = F + (size_t)grow * 512 + gcol;
                        v0 = 0.7f * fp[0] + 0.3f * v0;
                        v1 = 0.7f * fp[1] + 0.3f * v1;
                    }
                    if (EPI == 2 || EPI == 4) { v0 = f2tf_f(v0); v1 = f2tf_f(v1); }
                    *(float2*)(C + (size_t)grow * 512 + gcol) = make_float2(v0, v1);
                    if (EPI == 5)
                        *(float2*)(C2 + (size_t)grow * 512 + gcol) =
                            make_float2(f2tf_f(v0), f2tf_f(v1));
                }
            }
        }
    } else {
        // quality head (NT=128, col0=0): sigmoid(b2 + sum relu(acc+b1)*w2)
        float* qpart = sm;
        __syncthreads();
        #pragma unroll
        for (int mf = 0; mf < 4; ++mf) {
            #pragma unroll
            for (int r01 = 0; r01 < 2; ++r01) {
                float s = 0.f;
                #pragma unroll
                for (int nf = 0; nf < NF; ++nf) {
                    int c = wn * (NT / 4) + nf * 8 + 2 * t;
                    float h0 = fmaxf(acc[mf][nf][r01 * 2 + 0] + bias[c], 0.f);
                    float h1 = fmaxf(acc[mf][nf][r01 * 2 + 1] + bias[c + 1], 0.f);
                    s += h0 * w2[c] + h1 * w2[c + 1];
                }
                int rl = wm * 64 + mf * 16 + r01 * 8 + g;
                qpart[rl * 17 + wn * 4 + t] = s;
            }
        }
        __syncthreads();
        if (tid < 128) {
            float s = b2[0];
            #pragma unroll
            for (int i = 0; i < 16; ++i) s += qpart[tid * 17 + i];
            C[row0 + tid] = 1.f / (1.f + expf(-s));
        }
    }
}
#define GEMM_SMEM(NT) ((2 * 128 * GS + 2 * (NT) * GS) * 4)

// ==================== tf32 mma flash attention (no-max softmax, 2 CTA/SM) ====
#define QS 68
#define VS 72
#define ATT_SMEM ((128*QS + 64*QS + 128*QS + 64*VS) * 4)
__global__ void __launch_bounds__(256, 2) attn_mma(
    const float* __restrict__ Q, const float* __restrict__ Kb,
    const float* __restrict__ Vb, float* __restrict__ ctx)
{
    extern __shared__ float sm[];
    float* Qs = sm;
    float* Ks = Qs + 128 * QS;
    float* Ps = Ks + 64 * QS;
    float* Vs = Ps + 128 * QS;
    const uint32_t sK = smem_u32(Ks);
    const uint32_t sV = smem_u32(Vs);

    const int h = blockIdx.x;
    const int b0 = blockIdx.y * 128;
    const int tid = threadIdx.x;
    const int wid = tid >> 5, lane = tid & 31;
    const int g = lane >> 2, t = lane & 3;
    const int qr = wid * 16;

    #pragma unroll
    for (int it = 0; it < 8; ++it) {
        int vid = tid + it * 256;
        int r = vid >> 4, q = vid & 15;
        float4 v = *(const float4*)(Q + (size_t)(b0 + r) * 512 + h * 64 + q * 4);
        *(float4*)&Qs[r * QS + q * 4] = v;
    }

    float oacc[8][4];
    float rsum[2] = {0.f, 0.f};
    #pragma unroll
    for (int nf = 0; nf < 8; ++nf)
        #pragma unroll
        for (int c = 0; c < 4; ++c) oacc[nf][c] = 0.f;

    for (int m0 = 0; m0 < MEMP; m0 += 64) {
        __syncthreads();
        #pragma unroll
        for (int it = 0; it < 4; ++it) {
            int vid = tid + it * 256;
            int r = vid >> 4, q = vid & 15;
            int gm = m0 + r;
            int sz = (gm < MEM) ? 16 : 0;
            cp_async16(sK + (r * QS + q * 4) * 4, Kb + (size_t)gm * 512 + h * 64 + q * 4, sz);
            cp_async16(sV + (r * VS + q * 4) * 4, Vb + (size_t)gm * 512 + h * 64 + q * 4, sz);
        }
        CP_COMMIT();
        CP_WAIT(0);
        __syncthreads();

        // ---- S = Q K^T ----
        float sacc[8][4];
        #pragma unroll
        for (int nf = 0; nf < 8; ++nf)
            #pragma unroll
            for (int c = 0; c < 4; ++c) sacc[nf][c] = 0.f;
        #pragma unroll
        for (int ks = 0; ks < 8; ++ks) {
            int k0 = ks * 8;
            uint32_t a0 = __float_as_uint(Qs[(qr + g    ) * QS + k0 + t    ]);
            uint32_t a1 = __float_as_uint(Qs[(qr + g + 8) * QS + k0 + t    ]);
            uint32_t a2 = __float_as_uint(Qs[(qr + g    ) * QS + k0 + t + 4]);
            uint32_t a3 = __float_as_uint(Qs[(qr + g + 8) * QS + k0 + t + 4]);
            #pragma unroll
            for (int nf = 0; nf < 8; ++nf) {
                uint32_t b0 = __float_as_uint(Ks[(nf * 8 + g) * QS + k0 + t    ]);
                uint32_t b1 = __float_as_uint(Ks[(nf * 8 + g) * QS + k0 + t + 4]);
                mma_tf32(sacc[nf], a0, a1, a2, a3, b0, b1);
            }
        }

        // ---- softmax numerator (shift-free: LN-bounded scores) ----
        #pragma unroll
        for (int r01 = 0; r01 < 2; ++r01) {
            float ps = 0.f;
            int prow = qr + g + r01 * 8;
            #pragma unroll
            for (int nf = 0; nf < 8; ++nf) {
                float p0 = 0.f, p1 = 0.f;
                if (m0 + nf * 8 + 2 * t     < MEM) p0 = __expf(sacc[nf][r01 * 2 + 0] * 0.125f);
                if (m0 + nf * 8 + 2 * t + 1 < MEM) p1 = __expf(sacc[nf][r01 * 2 + 1] * 0.125f);
                ps += p0 + p1;
                *(float2*)&Ps[prow * QS + nf * 8 + 2 * t] =
                    make_float2(f2tf_f(p0), f2tf_f(p1));
            }
            ps += __shfl_xor_sync(0xffffffffu, ps, 1);
            ps += __shfl_xor_sync(0xffffffffu, ps, 2);
            rsum[r01] += ps;
        }
        __syncwarp();

        // ---- O += P V ----
        #pragma unroll
        for (int ks = 0; ks < 8; ++ks) {
            int k0 = ks * 8;
            uint32_t a0 = __float_as_uint(Ps[(qr + g    ) * QS + k0 + t    ]);
            uint32_t a1 = __float_as_uint(Ps[(qr + g + 8) * QS + k0 + t    ]);
            uint32_t a2 = __float_as_uint(Ps[(qr + g    ) * QS + k0 + t + 4]);
            uint32_t a3 = __float_as_uint(Ps[(qr + g + 8) * QS + k0 + t + 4]);
            #pragma unroll
            for (int nf = 0; nf < 8; ++nf) {
                uint32_t b0 = __float_as_uint(Vs[(k0 + t    ) * VS + nf * 8 + g]);
                uint32_t b1 = __float_as_uint(Vs[(k0 + t + 4) * VS + nf * 8 + g]);
                mma_tf32(oacc[nf], a0, a1, a2, a3, b0, b1);
            }
        }
    }

    #pragma unroll
    for (int r01 = 0; r01 < 2; ++r01) {
        float inv = 1.f / rsum[r01];
        int grow = b0 + qr + g + r01 * 8;
        #pragma unroll
        for (int nf = 0; nf < 8; ++nf) {
            float2 o = make_float2(f2tf_f(oacc[nf][r01 * 2 + 0] * inv),
                                   f2tf_f(oacc[nf][r01 * 2 + 1] * inv));
            *(float2*)(ctx + (size_t)grow * 512 + h * 64 + nf * 8 + 2 * t) = o;
        }
    }
}

// ==================== LayerNorm (128 thr per row, tf32 output) ====================
__global__ void __launch_bounds__(128) ln_kernel(
    const float* __restrict__ x, const float* __restrict__ g,
    const float* __restrict__ b, float* __restrict__ y)
{
    const int row = blockIdx.x;
    const int tid = threadIdx.x;
    float4 v = *(const float4*)(x + (size_t)row * 512 + tid * 4);

    __shared__ float red[4];
    float s = v.x + v.y + v.z + v.w;
    #pragma unroll
    for (int o = 16; o > 0; o >>= 1) s += __shfl_xor_sync(0xffffffffu, s, o);
    if ((tid & 31) == 0) red[tid >> 5] = s;
    __syncthreads();
    float mean = (red[0] + red[1] + red[2] + red[3]) * (1.f / 512.f);
    __syncthreads();

    float dx = v.x - mean, dy = v.y - mean, dz = v.z - mean, dw = v.w - mean;
    float ss = dx * dx + dy * dy + dz * dz + dw * dw;
    #pragma unroll
    for (int o = 16; o > 0; o >>= 1) ss += __shfl_xor_sync(0xffffffffu, ss, o);
    if ((tid & 31) == 0) red[tid >> 5] = ss;
    __syncthreads();
    float var = (red[0] + red[1] + red[2] + red[3]) * (1.f / 512.f);
    float inv = rsqrtf(var + 1e-5f);

    float4 gg = *(const float4*)(g + tid * 4);
    float4 bb = *(const float4*)(b + tid * 4);
    float4 o;
    o.x = f2tf_f(dx * inv * gg.x + bb.x);
    o.y = f2tf_f(dy * inv * gg.y + bb.y);
    o.z = f2tf_f(dz * inv * gg.z + bb.z);
    o.w = f2tf_f(dw * inv * gg.w + bb.w);
    *(float4*)(y + (size_t)row * 512 + tid * 4) = o;
}

// ==================== mask compaction + memory EMA ====================
__global__ void __launch_bounds__(256) compact_kernel(
    const float* __restrict__ quality, int* __restrict__ midx, int* __restrict__ mcount)
{
    const int tid = threadIdx.x;
    const int base = tid * 32;
    int cnt = 0;
    for (int i = 0; i < 32; ++i) cnt += (quality[base + i] > 0.7f) ? 1 : 0;
    __shared__ int sc[256];
    __shared__ int offs[256];
    sc[tid] = cnt;
    __syncthreads();
    if (tid == 0) {
        int run = 0;
        for (int t = 0; t < 256; ++t) { offs[t] = run; run += sc[t]; }
        *mcount = run;
    }
    __syncthreads();
    int o = offs[tid];
    for (int i = 0; i < 32; ++i)
        if (quality[base + i] > 0.7f) midx[o++] = base + i;
}

__global__ void __launch_bounds__(128) memupd_kernel(
    const float* __restrict__ wm, const float* __restrict__ ns,
    const int* __restrict__ upd, const int* __restrict__ midx,
    const int* __restrict__ mcount, float* __restrict__ outmem)
{
    const int m = blockIdx.x;
    const int d = threadIdx.x * 4;
    float4 v = *(const float4*)(wm + (size_t)m * 512 + d);
    const int cnt = *mcount;
    for (int jj = 0; jj < cnt; ++jj) {
        int i = midx[jj];
        if (upd[i] == m) {
            float4 s = *(const float4*)(ns + (size_t)i * 512 + d);
            v.x = 0.9f * v.x + 0.1f * s.x;
            v.y = 0.9f * v.y + 0.1f * s.y;
            v.z = 0.9f * v.z + 0.1f * s.z;
            v.w = 0.9f * v.w + 0.1f * s.w;
        }
    }
    *(float4*)(outmem + (size_t)m * 512 + d) = v;
}

// ==================== host launcher ====================
extern "C" void kernel_launch(void* const* d_in, const int* in_sizes, int n_in,
                              void* d_out, int out_size)
{
    const float* obs    = (const float*)d_in[0];
    const float* ego    = (const float*)d_in[1];
    const float* wm     = (const float*)d_in[2];
    const float* enc_w1 = (const float*)d_in[3];
    const float* enc_b1 = (const float*)d_in[4];
    const float* enc_g  = (const float*)d_in[5];
    const float* enc_be = (const float*)d_in[6];
    const float* enc_w2 = (const float*)d_in[7];
    const float* enc_b2 = (const float*)d_in[8];
    const float* wq     = (const float*)d_in[9];
    const float* bq     = (const float*)d_in[10];
    const float* wk     = (const float*)d_in[11];
    const float* bk     = (const float*)d_in[12];
    const float* wv     = (const float*)d_in[13];
    const float* bv     = (const float*)d_in[14];
    const float* wo     = (const float*)d_in[15];
    const float* bo     = (const float*)d_in[16];
    const float* tr_w1  = (const float*)d_in[17];
    const float* tr_b1  = (const float*)d_in[18];
    const float* tr_g   = (const float*)d_in[19];
    const float* tr_be  = (const float*)d_in[20];
    const float* tr_w2  = (const float*)d_in[21];
    const float* tr_b2  = (const float*)d_in[22];
    const float* q_w1   = (const float*)d_in[23];
    const float* q_b1   = (const float*)d_in[24];
    const float* q_w2   = (const float*)d_in[25];
    const float* q_b2   = (const float*)d_in[26];
    const int*   uidx   = (const int*)d_in[27];

    float* out        = (float*)d_out;
    float* next_state = out;
    float* quality    = out + (size_t)BATCH * DIM;
    float* outmem     = quality + BATCH;

    float *h, *hn, *enc, *enc_t, *qb, *ctx, *fused, *ns_t, *kb, *vb;
    float *obs_t, *ego_t, *wm_t, *w_t;
    int *midx, *mcount;
    cudaGetSymbolAddress((void**)&h,      g_h);
    cudaGetSymbolAddress((void**)&hn,     g_hn);
    cudaGetSymbolAddress((void**)&enc,    g_enc);
    cudaGetSymbolAddress((void**)&enc_t,  g_enc_t);
    cudaGetSymbolAddress((void**)&qb,     g_q);
    cudaGetSymbolAddress((void**)&ctx,    g_ctx);
    cudaGetSymbolAddress((void**)&fused,  g_fused);
    cudaGetSymbolAddress((void**)&ns_t,   g_ns_t);
    cudaGetSymbolAddress((void**)&kb,     g_k);
    cudaGetSymbolAddress((void**)&vb,     g_v);
    cudaGetSymbolAddress((void**)&obs_t,  g_obs_t);
    cudaGetSymbolAddress((void**)&ego_t,  g_ego_t);
    cudaGetSymbolAddress((void**)&wm_t,   g_wm_t);
    cudaGetSymbolAddress((void**)&w_t,    g_w_t);
    cudaGetSymbolAddress((void**)&midx,   g_midx);
    cudaGetSymbolAddress((void**)&mcount, g_mcount);

    cudaFuncSetAttribute(gemm_mma<256,1>, cudaFuncAttributeMaxDynamicSharedMemorySize, GEMM_SMEM(256));
    cudaFuncSetAttribute(gemm_mma<256,2>, cudaFuncAttributeMaxDynamicSharedMemorySize, GEMM_SMEM(256));
    cudaFuncSetAttribute(gemm_mma<256,4>, cudaFuncAttributeMaxDynamicSharedMemorySize, GEMM_SMEM(256));
    cudaFuncSetAttribute(gemm_mma<256,5>, cudaFuncAttributeMaxDynamicSharedMemorySize, GEMM_SMEM(256));
    cudaFuncSetAttribute(gemm_mma<128,3>, cudaFuncAttributeMaxDynamicSharedMemorySize, GEMM_SMEM(128));
    cudaFuncSetAttribute(attn_mma,        cudaFuncAttributeMaxDynamicSharedMemorySize, ATT_SMEM);

    // ---- prep ----
    PrepArgs pa;
    const float* srcs[12] = {obs, ego, wm, enc_w1, enc_w2, wq, wk, wv, wo, tr_w1, tr_w2, q_w1};
    float* dsts[12] = {obs_t, ego_t, wm_t,
                       w_t + W_ENC1, w_t + W_ENC2, w_t + W_WQ, w_t + W_WK, w_t + W_WV,
                       w_t + W_WO, w_t + W_TR1, w_t + W_TR2, w_t + W_Q1};
    int n4s[12] = {BATCH*DIM/4, BATCH*16/4, MEM*DIM/4,
                   262144/4, 262144/4, 262144/4, 262144/4, 262144/4,
                   262144/4, 270336/4, 262144/4, 65536/4};
    for (int i = 0; i < 12; ++i) { pa.src[i] = srcs[i]; pa.dst[i] = dsts[i]; pa.n4[i] = n4s[i]; }
    prep_kernel<<<dim3(512, 12), 256>>>(pa);

    dim3 gBig(2, 64), gKV(2, 8, 2), gQual(1, 64);

    // encoder
    gemm_mma<256,1><<<gBig, 256, GEMM_SMEM(256)>>>(obs_t, nullptr, w_t + W_ENC1, enc_b1,
        nullptr, nullptr, nullptr, h, nullptr, BATCH, 512, 16);
    ln_kernel<<<BATCH, 128>>>(h, enc_g, enc_be, hn);
    gemm_mma<256,5><<<gBig, 256, GEMM_SMEM(256)>>>(hn, nullptr, w_t + W_ENC2, enc_b2,
        nullptr, nullptr, nullptr, enc, enc_t, BATCH, 512, 16);
    // projections (Q; K+V combined via blockIdx.z)
    gemm_mma<256,4><<<gBig, 256, GEMM_SMEM(256)>>>(enc_t, nullptr, w_t + W_WQ, bq,
        nullptr, nullptr, nullptr, qb, nullptr, BATCH, 512, 16);
    gemm_mma<256,4><<<gKV, 256, GEMM_SMEM(256)>>>(wm_t, nullptr, w_t + W_WK, bk,
        w_t + W_WV, bv, nullptr, kb, vb, MEM, 512, 16);
    // attention
    attn_mma<<<dim3(HEADS, BATCH / 128), 256, ATT_SMEM>>>(qb, kb, vb, ctx);
    // out projection + fuse
    gemm_mma<256,2><<<gBig, 256, GEMM_SMEM(256)>>>(ctx, nullptr, w_t + W_WO, bo,
        enc, nullptr, nullptr, fused, nullptr, BATCH, 512, 16);
    // transition
    gemm_mma<256,1><<<gBig, 256, GEMM_SMEM(256)>>>(fused, ego_t, w_t + W_TR1, tr_b1,
        nullptr, nullptr, nullptr, h, nullptr, BATCH, 528, 17);
    ln_kernel<<<BATCH, 128>>>(h, tr_g, tr_be, hn);
    gemm_mma<256,5><<<gBig, 256, GEMM_SMEM(256)>>>(hn, nullptr, w_t + W_TR2, tr_b2,
        nullptr, nullptr, nullptr, next_state, ns_t, BATCH, 512, 16);
    // quality head
    gemm_mma<128,3><<<gQual, 256, GEMM_SMEM(128)>>>(ns_t, nullptr, w_t + W_Q1, q_b1,
        nullptr, q_w2, q_b2, quality, nullptr, BATCH, 512, 16);
    // memory bank update
    compact_kernel<<<1, 256>>>(quality, midx, mcount);
    memupd_kernel<<<MEM, 128>>>(wm, next_state, uidx, midx, mcount, outmem);
}

// round 9
// speedup vs baseline: 1.5119x; 1.0045x over previous
#include <cuda_runtime.h>
#include <math.h>
#include <stdint.h>

#define BATCH 8192
#define DIM   512
#define MEM   1000
#define MEMP  1024
#define HEADS 8
#define DH    64

// ==================== helpers ====================
__device__ __forceinline__ uint32_t smem_u32(const void* p) {
    uint32_t a;
    asm("{ .reg .u64 t; cvta.to.shared.u64 t, %1; cvt.u32.u64 %0, t; }" : "=r"(a) : "l"(p));
    return a;
}
__device__ __forceinline__ uint32_t f2tf(float x) {
    uint32_t u; asm("cvt.rna.tf32.f32 %0, %1;" : "=r"(u) : "f"(x)); return u;
}
__device__ __forceinline__ float f2tf_f(float x) { return __uint_as_float(f2tf(x)); }
__device__ __forceinline__ void mma_tf32(float* c, uint32_t a0, uint32_t a1,
                                         uint32_t a2, uint32_t a3,
                                         uint32_t b0, uint32_t b1) {
    asm volatile(
        "mma.sync.aligned.m16n8k8.row.col.f32.tf32.tf32.f32 "
        "{%0,%1,%2,%3}, {%4,%5,%6,%7}, {%8,%9}, {%0,%1,%2,%3};"
        : "+f"(c[0]), "+f"(c[1]), "+f"(c[2]), "+f"(c[3])
        : "r"(a0), "r"(a1), "r"(a2), "r"(a3), "r"(b0), "r"(b1));
}
__device__ __forceinline__ void cp_async16(uint32_t dst, const void* src, int srcsize) {
    asm volatile("cp.async.cg.shared.global [%0], [%1], 16, %2;"
                 :: "r"(dst), "l"(src), "r"(srcsize));
}
#define CP_COMMIT() asm volatile("cp.async.commit_group;" ::: "memory")
#define CP_WAIT(N)  asm volatile("cp.async.wait_group %0;" :: "n"(N) : "memory")

// ==================== scratch ====================
__device__ float g_h[BATCH*DIM];        // fp32 pre-LN
__device__ float g_hn[BATCH*DIM];       // tf32
__device__ float g_enc[BATCH*DIM];      // fp32 (F for fuse)
__device__ float g_enc_t[BATCH*DIM];    // tf32
__device__ float g_q[BATCH*DIM];        // tf32
__device__ float g_ctx[BATCH*DIM];      // tf32
__device__ float g_fused[BATCH*DIM];    // tf32
__device__ float g_ns_t[BATCH*DIM];     // tf32 copy of next_state
__device__ float g_k[MEMP*DIM];         // tf32
__device__ float g_v[MEMP*DIM];         // tf32
__device__ float g_obs_t[BATCH*DIM];    // tf32
__device__ float g_ego_t[BATCH*16];     // tf32
__device__ float g_wm_t[MEM*DIM];       // tf32
#define W_ENC1 0
#define W_ENC2 262144
#define W_WQ   524288
#define W_WK   786432
#define W_WV   1048576
#define W_WO   1310720
#define W_TR1  1572864
#define W_TR2  1843200
#define W_Q1   2105344
#define W_TOT  2170880
__device__ float g_w_t[W_TOT];
__device__ int   g_midx[BATCH];
__device__ int   g_mcount;

// ==================== prep: fp32 -> tf32-rounded fp32 ====================
struct PrepArgs {
    const float* src[12];
    float*       dst[12];
    int          n4[12];
};
__global__ void __launch_bounds__(256) prep_kernel(PrepArgs p) {
    int seg = blockIdx.y;
    int n4 = p.n4[seg];
    const float4* s = (const float4*)p.src[seg];
    float4* d = (float4*)p.dst[seg];
    for (int i = blockIdx.x * 256 + threadIdx.x; i < n4; i += gridDim.x * 256) {
        float4 v = s[i];
        float4 o;
        o.x = f2tf_f(v.x); o.y = f2tf_f(v.y);
        o.z = f2tf_f(v.z); o.w = f2tf_f(v.w);
        d[i] = o;
    }
}

// ==================== tf32 mma GEMM, 256 threads, BK=32, 3-stage pipeline ====
// CTA tile 128 x NT, warp tile 64 x NT/4 (2 row-warps x 4 col-warps).
// EPI: 1 relu f32, 2 fuse->tf32, 3 quality, 4 tf32 (z-dual), 5 dual f32+tf32
#define GS 36
template<int NT, int EPI>
__global__ void __launch_bounds__(256) gemm_mma(
    const float* __restrict__ A, const float* __restrict__ A2,
    const float* __restrict__ W, const float* __restrict__ bias,
    const float* __restrict__ F, const float* __restrict__ w2,
    const float* __restrict__ b2, float* __restrict__ C, float* __restrict__ C2,
    int Mrows, int Kw, int Ktiles)
{
    constexpr int NF  = NT / 32;
    constexpr int ASZ = 128 * GS;
    constexpr int WSZ = NT * GS;
    extern __shared__ float sm[];
    float* Asm = sm;                 // 3 x ASZ
    float* Wsm = sm + 3 * ASZ;       // 3 x WSZ
    const uint32_t sA = smem_u32(Asm);
    const uint32_t sW = smem_u32(Wsm);

    // combined K/V launch: z=1 -> second weight/bias/output set (EPI==4 only)
    if (EPI == 4 && blockIdx.z) { W = F; C = C2; bias = w2; }

    const int tid = threadIdx.x;
    const int wid = tid >> 5, lane = tid & 31;
    const int g = lane >> 2, t = lane & 3;
    const int wm = wid & 1, wn = wid >> 1;
    const int row0 = blockIdx.y * 128;
    const int col0 = blockIdx.x * NT;

    float acc[4][NF][4];
    #pragma unroll
    for (int mf = 0; mf < 4; ++mf)
        #pragma unroll
        for (int nf = 0; nf < NF; ++nf)
            #pragma unroll
            for (int c = 0; c < 4; ++c) acc[mf][nf][c] = 0.f;

    auto load_chunk = [&](int ct, int buf) {
        const int kbase = ct * 32;
        constexpr int NLOAD = (1024 + NT * 8) / 256;
        #pragma unroll
        for (int it = 0; it < NLOAD; ++it) {
            int vid = tid + it * 256;
            if (vid < 1024) {
                int r = vid >> 3, q = vid & 7;
                int kel = kbase + q * 4;
                int grow = row0 + r;
                const float* src = A;
                int sz = 0;
                if (grow < Mrows) {
                    if (kel < 512) { src = A + (size_t)grow * 512 + kel; sz = 16; }
                    else if (A2 != nullptr && kel < 528) {
                        src = A2 + (size_t)grow * 16 + (kel - 512); sz = 16;
                    }
                }
                cp_async16(sA + (buf * ASZ + r * GS + q * 4) * 4, src, sz);
            } else {
                int vid2 = vid - 1024;
                int r = vid2 >> 3, q = vid2 & 7;
                int kel = kbase + q * 4;
                const float* src = W + (size_t)(col0 + r) * Kw + kel;
                int sz = (kel < Kw) ? 16 : 0;
                cp_async16(sW + (buf * WSZ + r * GS + q * 4) * 4, src, sz);
            }
        }
        CP_COMMIT();
    };

    load_chunk(0, 0);
    if (Ktiles > 1) load_chunk(1, 1);

    for (int ct = 0; ct < Ktiles; ++ct) {
        const int buf = ct % 3;
        if (ct + 2 < Ktiles) load_chunk(ct + 2, (ct + 2) % 3);
        // ensure group ct is complete
        if (ct + 2 < Ktiles)      { CP_WAIT(2); }
        else if (ct + 1 < Ktiles) { CP_WAIT(1); }
        else                      { CP_WAIT(0); }
        __syncthreads();

        const float* Ab = Asm + buf * ASZ + (wm * 64) * GS;
        const float* Wb = Wsm + buf * WSZ + (wn * (NT / 4)) * GS;
        #pragma unroll
        for (int ks = 0; ks < 4; ++ks) {
            const int k0 = ks * 8;
            uint32_t af[4][4];
            #pragma unroll
            for (int mf = 0; mf < 4; ++mf) {
                const float* ar = Ab + (mf * 16) * GS + k0;
                af[mf][0] = __float_as_uint(ar[(g    ) * GS + t    ]);
                af[mf][1] = __float_as_uint(ar[(g + 8) * GS + t    ]);
                af[mf][2] = __float_as_uint(ar[(g    ) * GS + t + 4]);
                af[mf][3] = __float_as_uint(ar[(g + 8) * GS + t + 4]);
            }
            #pragma unroll
            for (int nf = 0; nf < NF; ++nf) {
                const float* wrp = Wb + (nf * 8 + g) * GS + k0;
                uint32_t b0 = __float_as_uint(wrp[t]);
                uint32_t b1 = __float_as_uint(wrp[t + 4]);
                #pragma unroll
                for (int mf = 0; mf < 4; ++mf)
                    mma_tf32(acc[mf][nf], af[mf][0], af[mf][1], af[mf][2], af[mf][3], b0, b1);
            }
        }
        __syncthreads();
    }

    if (EPI != 3) {
        #pragma unroll
        for (int mf = 0; mf < 4; ++mf) {
            #pragma unroll
            for (int r01 = 0; r01 < 2; ++r01) {
                int grow = row0 + wm * 64 + mf * 16 + g + r01 * 8;
                if (grow >= Mrows) continue;
                #pragma unroll
                for (int nf = 0; nf < NF; ++nf) {
                    int gcol = col0 + wn * (NT / 4) + nf * 8 + 2 * t;
                    float v0 = acc[mf][nf][r01 * 2 + 0] + bias[gcol];
                    float v1 = acc[mf][nf][r01 * 2 + 1] + bias[gcol + 1];
                    if (EPI == 1) { v0 = fmaxf(v0, 0.f); v1 = fmaxf(v1, 0.f); }
                    else if (EPI == 2) {
                        const float* fp = F + (size_t)grow * 512 + gcol;
                        v0 = 0.7f * fp[0] + 0.3f * v0;
                        v1 = 0.7f * fp[1] + 0.3f * v1;
                    }
                    if (EPI == 2 || EPI == 4) { v0 = f2tf_f(v0); v1 = f2tf_f(v1); }
                    *(float2*)(C + (size_t)grow * 512 + gcol) = make_float2(v0, v1);
                    if (EPI == 5)
                        *(float2*)(C2 + (size_t)grow * 512 + gcol) =
                            make_float2(f2tf_f(v0), f2tf_f(v1));
                }
            }
        }
    } else {
        // quality head (NT=128, col0=0): sigmoid(b2 + sum relu(acc+b1)*w2)
        float* qpart = sm;
        __syncthreads();
        #pragma unroll
        for (int mf = 0; mf < 4; ++mf) {
            #pragma unroll
            for (int r01 = 0; r01 < 2; ++r01) {
                float s = 0.f;
                #pragma unroll
                for (int nf = 0; nf < NF; ++nf) {
                    int c = wn * (NT / 4) + nf * 8 + 2 * t;
                    float h0 = fmaxf(acc[mf][nf][r01 * 2 + 0] + bias[c], 0.f);
                    float h1 = fmaxf(acc[mf][nf][r01 * 2 + 1] + bias[c + 1], 0.f);
                    s += h0 * w2[c] + h1 * w2[c + 1];
                }
                int rl = wm * 64 + mf * 16 + r01 * 8 + g;
                qpart[rl * 17 + wn * 4 + t] = s;
            }
        }
        __syncthreads();
        if (tid < 128) {
            float s = b2[0];
            #pragma unroll
            for (int i = 0; i < 16; ++i) s += qpart[tid * 17 + i];
            C[row0 + tid] = 1.f / (1.f + expf(-s));
        }
    }
}
#define GEMM_SMEM(NT) ((3 * 128 * GS + 3 * (NT) * GS) * 4)

// ==================== tf32 mma flash attention (no-max softmax, 2 CTA/SM) ====
#define QS 68
#define VS 72
#define ATT_SMEM ((128*QS + 64*QS + 128*QS + 64*VS) * 4)
__global__ void __launch_bounds__(256, 2) attn_mma(
    const float* __restrict__ Q, const float* __restrict__ Kb,
    const float* __restrict__ Vb, float* __restrict__ ctx)
{
    extern __shared__ float sm[];
    float* Qs = sm;
    float* Ks = Qs + 128 * QS;
    float* Ps = Ks + 64 * QS;
    float* Vs = Ps + 128 * QS;
    const uint32_t sK = smem_u32(Ks);
    const uint32_t sV = smem_u32(Vs);

    const int h = blockIdx.x;
    const int b0 = blockIdx.y * 128;
    const int tid = threadIdx.x;
    const int wid = tid >> 5, lane = tid & 31;
    const int g = lane >> 2, t = lane & 3;
    const int qr = wid * 16;

    #pragma unroll
    for (int it = 0; it < 8; ++it) {
        int vid = tid + it * 256;
        int r = vid >> 4, q = vid & 15;
        float4 v = *(const float4*)(Q + (size_t)(b0 + r) * 512 + h * 64 + q * 4);
        *(float4*)&Qs[r * QS + q * 4] = v;
    }

    float oacc[8][4];
    float rsum[2] = {0.f, 0.f};
    #pragma unroll
    for (int nf = 0; nf < 8; ++nf)
        #pragma unroll
        for (int c = 0; c < 4; ++c) oacc[nf][c] = 0.f;

    for (int m0 = 0; m0 < MEMP; m0 += 64) {
        __syncthreads();
        #pragma unroll
        for (int it = 0; it < 4; ++it) {
            int vid = tid + it * 256;
            int r = vid >> 4, q = vid & 15;
            int gm = m0 + r;
            int sz = (gm < MEM) ? 16 : 0;
            cp_async16(sK + (r * QS + q * 4) * 4, Kb + (size_t)gm * 512 + h * 64 + q * 4, sz);
            cp_async16(sV + (r * VS + q * 4) * 4, Vb + (size_t)gm * 512 + h * 64 + q * 4, sz);
        }
        CP_COMMIT();
        CP_WAIT(0);
        __syncthreads();

        // ---- S = Q K^T ----
        float sacc[8][4];
        #pragma unroll
        for (int nf = 0; nf < 8; ++nf)
            #pragma unroll
            for (int c = 0; c < 4; ++c) sacc[nf][c] = 0.f;
        #pragma unroll
        for (int ks = 0; ks < 8; ++ks) {
            int k0 = ks * 8;
            uint32_t a0 = __float_as_uint(Qs[(qr + g    ) * QS + k0 + t    ]);
            uint32_t a1 = __float_as_uint(Qs[(qr + g + 8) * QS + k0 + t    ]);
            uint32_t a2 = __float_as_uint(Qs[(qr + g    ) * QS + k0 + t + 4]);
            uint32_t a3 = __float_as_uint(Qs[(qr + g + 8) * QS + k0 + t + 4]);
            #pragma unroll
            for (int nf = 0; nf < 8; ++nf) {
                uint32_t b0 = __float_as_uint(Ks[(nf * 8 + g) * QS + k0 + t    ]);
                uint32_t b1 = __float_as_uint(Ks[(nf * 8 + g) * QS + k0 + t + 4]);
                mma_tf32(sacc[nf], a0, a1, a2, a3, b0, b1);
            }
        }

        // ---- softmax numerator (shift-free: LN-bounded scores) ----
        #pragma unroll
        for (int r01 = 0; r01 < 2; ++r01) {
            float ps = 0.f;
            int prow = qr + g + r01 * 8;
            #pragma unroll
            for (int nf = 0; nf < 8; ++nf) {
                float p0 = 0.f, p1 = 0.f;
                if (m0 + nf * 8 + 2 * t     < MEM) p0 = __expf(sacc[nf][r01 * 2 + 0] * 0.125f);
                if (m0 + nf * 8 + 2 * t + 1 < MEM) p1 = __expf(sacc[nf][r01 * 2 + 1] * 0.125f);
                ps += p0 + p1;
                *(float2*)&Ps[prow * QS + nf * 8 + 2 * t] =
                    make_float2(f2tf_f(p0), f2tf_f(p1));
            }
            ps += __shfl_xor_sync(0xffffffffu, ps, 1);
            ps += __shfl_xor_sync(0xffffffffu, ps, 2);
            rsum[r01] += ps;
        }
        __syncwarp();

        // ---- O += P V ----
        #pragma unroll
        for (int ks = 0; ks < 8; ++ks) {
            int k0 = ks * 8;
            uint32_t a0 = __float_as_uint(Ps[(qr + g    ) * QS + k0 + t    ]);
            uint32_t a1 = __float_as_uint(Ps[(qr + g + 8) * QS + k0 + t    ]);
            uint32_t a2 = __float_as_uint(Ps[(qr + g    ) * QS + k0 + t + 4]);
            uint32_t a3 = __float_as_uint(Ps[(qr + g + 8) * QS + k0 + t + 4]);
            #pragma unroll
            for (int nf = 0; nf < 8; ++nf) {
                uint32_t b0 = __float_as_uint(Vs[(k0 + t    ) * VS + nf * 8 + g]);
                uint32_t b1 = __float_as_uint(Vs[(k0 + t + 4) * VS + nf * 8 + g]);
                mma_tf32(oacc[nf], a0, a1, a2, a3, b0, b1);
            }
        }
    }

    #pragma unroll
    for (int r01 = 0; r01 < 2; ++r01) {
        float inv = 1.f / rsum[r01];
        int grow = b0 + qr + g + r01 * 8;
        #pragma unroll
        for (int nf = 0; nf < 8; ++nf) {
            float2 o = make_float2(f2tf_f(oacc[nf][r01 * 2 + 0] * inv),
                                   f2tf_f(oacc[nf][r01 * 2 + 1] * inv));
            *(float2*)(ctx + (size_t)grow * 512 + h * 64 + nf * 8 + 2 * t) = o;
        }
    }
}

// ==================== LayerNorm: warp-per-row (8 rows / 256-thr block) ========
__global__ void __launch_bounds__(256) ln_kernel(
    const float* __restrict__ x, const float* __restrict__ g,
    const float* __restrict__ b, float* __restrict__ y)
{
    const int warp = threadIdx.x >> 5, lane = threadIdx.x & 31;
    const int row = blockIdx.x * 8 + warp;
    const float* xr = x + (size_t)row * 512;

    float4 v[4];
    #pragma unroll
    for (int i = 0; i < 4; ++i)
        v[i] = *(const float4*)(xr + i * 128 + lane * 4);

    float s = 0.f;
    #pragma unroll
    for (int i = 0; i < 4; ++i) s += v[i].x + v[i].y + v[i].z + v[i].w;
    #pragma unroll
    for (int o = 16; o > 0; o >>= 1) s += __shfl_xor_sync(0xffffffffu, s, o);
    float mean = s * (1.f / 512.f);

    float ss = 0.f;
    #pragma unroll
    for (int i = 0; i < 4; ++i) {
        v[i].x -= mean; v[i].y -= mean; v[i].z -= mean; v[i].w -= mean;
        ss += v[i].x * v[i].x + v[i].y * v[i].y + v[i].z * v[i].z + v[i].w * v[i].w;
    }
    #pragma unroll
    for (int o = 16; o > 0; o >>= 1) ss += __shfl_xor_sync(0xffffffffu, ss, o);
    float inv = rsqrtf(ss * (1.f / 512.f) + 1e-5f);

    #pragma unroll
    for (int i = 0; i < 4; ++i) {
        float4 gg = *(const float4*)(g + i * 128 + lane * 4);
        float4 bb = *(const float4*)(b + i * 128 + lane * 4);
        float4 o;
        o.x = f2tf_f(v[i].x * inv * gg.x + bb.x);
        o.y = f2tf_f(v[i].y * inv * gg.y + bb.y);
        o.z = f2tf_f(v[i].z * inv * gg.z + bb.z);
        o.w = f2tf_f(v[i].w * inv * gg.w + bb.w);
        *(float4*)(y + (size_t)row * 512 + i * 128 + lane * 4) = o;
    }
}

// ==================== mask compaction + memory EMA ====================
__global__ void __launch_bounds__(256) compact_kernel(
    const float* __restrict__ quality, int* __restrict__ midx, int* __restrict__ mcount)
{
    const int tid = threadIdx.x;
    const int base = tid * 32;
    int cnt = 0;
    for (int i = 0; i < 32; ++i) cnt += (quality[base + i] > 0.7f) ? 1 : 0;
    __shared__ int sc[256];
    __shared__ int offs[256];
    sc[tid] = cnt;
    __syncthreads();
    if (tid == 0) {
        int run = 0;
        for (int t = 0; t < 256; ++t) { offs[t] = run; run += sc[t]; }
        *mcount = run;
    }
    __syncthreads();
    int o = offs[tid];
    for (int i = 0; i < 32; ++i)
        if (quality[base + i] > 0.7f) midx[o++] = base + i;
}

__global__ void __launch_bounds__(128) memupd_kernel(
    const float* __restrict__ wm, const float* __restrict__ ns,
    const int* __restrict__ upd, const int* __restrict__ midx,
    const int* __restrict__ mcount, float* __restrict__ outmem)
{
    const int m = blockIdx.x;
    const int d = threadIdx.x * 4;
    float4 v = *(const float4*)(wm + (size_t)m * 512 + d);
    const int cnt = *mcount;
    for (int jj = 0; jj < cnt; ++jj) {
        int i = midx[jj];
        if (upd[i] == m) {
            float4 s = *(const float4*)(ns + (size_t)i * 512 + d);
            v.x = 0.9f * v.x + 0.1f * s.x;
            v.y = 0.9f * v.y + 0.1f * s.y;
            v.z = 0.9f * v.z + 0.1f * s.z;
            v.w = 0.9f * v.w + 0.1f * s.w;
        }
    }
    *(float4*)(outmem + (size_t)m * 512 + d) = v;
}

// ==================== host launcher ====================
extern "C" void kernel_launch(void* const* d_in, const int* in_sizes, int n_in,
                              void* d_out, int out_size)
{
    const float* obs    = (const float*)d_in[0];
    const float* ego    = (const float*)d_in[1];
    const float* wm     = (const float*)d_in[2];
    const float* enc_w1 = (const float*)d_in[3];
    const float* enc_b1 = (const float*)d_in[4];
    const float* enc_g  = (const float*)d_in[5];
    const float* enc_be = (const float*)d_in[6];
    const float* enc_w2 = (const float*)d_in[7];
    const float* enc_b2 = (const float*)d_in[8];
    const float* wq     = (const float*)d_in[9];
    const float* bq     = (const float*)d_in[10];
    const float* wk     = (const float*)d_in[11];
    const float* bk     = (const float*)d_in[12];
    const float* wv     = (const float*)d_in[13];
    const float* bv     = (const float*)d_in[14];
    const float* wo     = (const float*)d_in[15];
    const float* bo     = (const float*)d_in[16];
    const float* tr_w1  = (const float*)d_in[17];
    const float* tr_b1  = (const float*)d_in[18];
    const float* tr_g   = (const float*)d_in[19];
    const float* tr_be  = (const float*)d_in[20];
    const float* tr_w2  = (const float*)d_in[21];
    const float* tr_b2  = (const float*)d_in[22];
    const float* q_w1   = (const float*)d_in[23];
    const float* q_b1   = (const float*)d_in[24];
    const float* q_w2   = (const float*)d_in[25];
    const float* q_b2   = (const float*)d_in[26];
    const int*   uidx   = (const int*)d_in[27];

    float* out        = (float*)d_out;
    float* next_state = out;
    float* quality    = out + (size_t)BATCH * DIM;
    float* outmem     = quality + BATCH;

    float *h, *hn, *enc, *enc_t, *qb, *ctx, *fused, *ns_t, *kb, *vb;
    float *obs_t, *ego_t, *wm_t, *w_t;
    int *midx, *mcount;
    cudaGetSymbolAddress((void**)&h,      g_h);
    cudaGetSymbolAddress((void**)&hn,     g_hn);
    cudaGetSymbolAddress((void**)&enc,    g_enc);
    cudaGetSymbolAddress((void**)&enc_t,  g_enc_t);
    cudaGetSymbolAddress((void**)&qb,     g_q);
    cudaGetSymbolAddress((void**)&ctx,    g_ctx);
    cudaGetSymbolAddress((void**)&fused,  g_fused);
    cudaGetSymbolAddress((void**)&ns_t,   g_ns_t);
    cudaGetSymbolAddress((void**)&kb,     g_k);
    cudaGetSymbolAddress((void**)&vb,     g_v);
    cudaGetSymbolAddress((void**)&obs_t,  g_obs_t);
    cudaGetSymbolAddress((void**)&ego_t,  g_ego_t);
    cudaGetSymbolAddress((void**)&wm_t,   g_wm_t);
    cudaGetSymbolAddress((void**)&w_t,    g_w_t);
    cudaGetSymbolAddress((void**)&midx,   g_midx);
    cudaGetSymbolAddress((void**)&mcount, g_mcount);

    cudaFuncSetAttribute(gemm_mma<256,1>, cudaFuncAttributeMaxDynamicSharedMemorySize, GEMM_SMEM(256));
    cudaFuncSetAttribute(gemm_mma<256,2>, cudaFuncAttributeMaxDynamicSharedMemorySize, GEMM_SMEM(256));
    cudaFuncSetAttribute(gemm_mma<256,4>, cudaFuncAttributeMaxDynamicSharedMemorySize, GEMM_SMEM(256));
    cudaFuncSetAttribute(gemm_mma<256,5>, cudaFuncAttributeMaxDynamicSharedMemorySize, GEMM_SMEM(256));
    cudaFuncSetAttribute(gemm_mma<128,3>, cudaFuncAttributeMaxDynamicSharedMemorySize, GEMM_SMEM(128));
    cudaFuncSetAttribute(attn_mma,        cudaFuncAttributeMaxDynamicSharedMemorySize, ATT_SMEM);

    // ---- prep ----
    PrepArgs pa;
    const float* srcs[12] = {obs, ego, wm, enc_w1, enc_w2, wq, wk, wv, wo, tr_w1, tr_w2, q_w1};
    float* dsts[12] = {obs_t, ego_t, wm_t,
                       w_t + W_ENC1, w_t + W_ENC2, w_t + W_WQ, w_t + W_WK, w_t + W_WV,
                       w_t + W_WO, w_t + W_TR1, w_t + W_TR2, w_t + W_Q1};
    int n4s[12] = {BATCH*DIM/4, BATCH*16/4, MEM*DIM/4,
                   262144/4, 262144/4, 262144/4, 262144/4, 262144/4,
                   262144/4, 270336/4, 262144/4, 65536/4};
    for (int i = 0; i < 12; ++i) { pa.src[i] = srcs[i]; pa.dst[i] = dsts[i]; pa.n4[i] = n4s[i]; }
    prep_kernel<<<dim3(512, 12), 256>>>(pa);

    dim3 gBig(2, 64), gKV(2, 8, 2), gQual(1, 64);

    // encoder
    gemm_mma<256,1><<<gBig, 256, GEMM_SMEM(256)>>>(obs_t, nullptr, w_t + W_ENC1, enc_b1,
        nullptr, nullptr, nullptr, h, nullptr, BATCH, 512, 16);
    ln_kernel<<<BATCH/8, 256>>>(h, enc_g, enc_be, hn);
    gemm_mma<256,5><<<gBig, 256, GEMM_SMEM(256)>>>(hn, nullptr, w_t + W_ENC2, enc_b2,
        nullptr, nullptr, nullptr, enc, enc_t, BATCH, 512, 16);
    // projections (Q; K+V combined via blockIdx.z)
    gemm_mma<256,4><<<gBig, 256, GEMM_SMEM(256)>>>(enc_t, nullptr, w_t + W_WQ, bq,
        nullptr, nullptr, nullptr, qb, nullptr, BATCH, 512, 16);
    gemm_mma<256,4><<<gKV, 256, GEMM_SMEM(256)>>>(wm_t, nullptr, w_t + W_WK, bk,
        w_t + W_WV, bv, nullptr, kb, vb, MEM, 512, 16);
    // attention
    attn_mma<<<dim3(HEADS, BATCH / 128), 256, ATT_SMEM>>>(qb, kb, vb, ctx);
    // out projection + fuse (F = enc fp32, exact R7 numerics)
    gemm_mma<256,2><<<gBig, 256, GEMM_SMEM(256)>>>(ctx, nullptr, w_t + W_WO, bo,
        enc, nullptr, nullptr, fused, nullptr, BATCH, 512, 16);
    // transition (K=528, ego in 17th K-chunk)
    gemm_mma<256,1><<<gBig, 256, GEMM_SMEM(256)>>>(fused, ego_t, w_t + W_TR1, tr_b1,
        nullptr, nullptr, nullptr, h, nullptr, BATCH, 528, 17);
    ln_kernel<<<BATCH/8, 256>>>(h, tr_g, tr_be, hn);
    gemm_mma<256,5><<<gBig, 256, GEMM_SMEM(256)>>>(hn, nullptr, w_t + W_TR2, tr_b2,
        nullptr, nullptr, nullptr, next_state, ns_t, BATCH, 512, 16);
    // quality head (tf32 ns_t input, exact R7 numerics)
    gemm_mma<128,3><<<gQual, 256, GEMM_SMEM(128)>>>(ns_t, nullptr, w_t + W_Q1, q_b1,
        nullptr, q_w2, q_b2, quality, nullptr, BATCH, 512, 16);
    // memory bank update
    compact_kernel<<<1, 256>>>(quality, midx, mcount);
    memupd_kernel<<<MEM, 128>>>(wm, next_state, uidx, midx, mcount, outmem);
}

// round 10
// speedup vs baseline: 1.5235x; 1.0077x over previous
#include <cuda_runtime.h>
#include <math.h>
#include <stdint.h>

#define BATCH 8192
#define DIM   512
#define MEM   1000
#define MEMP  1024
#define HEADS 8
#define DH    64

// ==================== helpers ====================
__device__ __forceinline__ uint32_t smem_u32(const void* p) {
    uint32_t a;
    asm("{ .reg .u64 t; cvta.to.shared.u64 t, %1; cvt.u32.u64 %0, t; }" : "=r"(a) : "l"(p));
    return a;
}
__device__ __forceinline__ uint32_t f2tf(float x) {
    uint32_t u; asm("cvt.rna.tf32.f32 %0, %1;" : "=r"(u) : "f"(x)); return u;
}
__device__ __forceinline__ float f2tf_f(float x) { return __uint_as_float(f2tf(x)); }
__device__ __forceinline__ void mma_tf32(float* c, uint32_t a0, uint32_t a1,
                                         uint32_t a2, uint32_t a3,
                                         uint32_t b0, uint32_t b1) {
    asm volatile(
        "mma.sync.aligned.m16n8k8.row.col.f32.tf32.tf32.f32 "
        "{%0,%1,%2,%3}, {%4,%5,%6,%7}, {%8,%9}, {%0,%1,%2,%3};"
        : "+f"(c[0]), "+f"(c[1]), "+f"(c[2]), "+f"(c[3])
        : "r"(a0), "r"(a1), "r"(a2), "r"(a3), "r"(b0), "r"(b1));
}
__device__ __forceinline__ void cp_async16(uint32_t dst, const void* src, int srcsize) {
    asm volatile("cp.async.cg.shared.global [%0], [%1], 16, %2;"
                 :: "r"(dst), "l"(src), "r"(srcsize));
}
#define CP_COMMIT() asm volatile("cp.async.commit_group;" ::: "memory")
#define CP_WAIT(N)  asm volatile("cp.async.wait_group %0;" :: "n"(N) : "memory")

// ==================== scratch ====================
__device__ float g_h[BATCH*DIM];        // fp32 pre-LN
__device__ float g_hn[BATCH*DIM];       // tf32
__device__ float g_enc[BATCH*DIM];      // fp32 (F for fuse)
__device__ float g_enc_t[BATCH*DIM];    // tf32
__device__ float g_q[BATCH*DIM];        // tf32, pre-scaled by 0.125
__device__ float g_ctx[BATCH*DIM];      // tf32
__device__ float g_fused[BATCH*DIM];    // tf32
__device__ float g_ns_t[BATCH*DIM];     // tf32 copy of next_state
__device__ float g_k[MEMP*DIM];         // tf32
__device__ float g_v[MEMP*DIM];         // tf32
__device__ float g_obs_t[BATCH*DIM];    // tf32
__device__ float g_ego_t[BATCH*16];     // tf32
__device__ float g_wm_t[MEM*DIM];       // tf32
#define W_ENC1 0
#define W_ENC2 262144
#define W_WQ   524288
#define W_WK   786432
#define W_WV   1048576
#define W_WO   1310720
#define W_TR1  1572864
#define W_TR2  1843200
#define W_Q1   2105344
#define W_TOT  2170880
__device__ float g_w_t[W_TOT];
__device__ int   g_midx[BATCH];
__device__ int   g_mcount;

// ==================== prep: fp32 -> tf32-rounded fp32 ====================
struct PrepArgs {
    const float* src[12];
    float*       dst[12];
    int          n4[12];
};
__global__ void __launch_bounds__(256) prep_kernel(PrepArgs p) {
    int seg = blockIdx.y;
    int n4 = p.n4[seg];
    const float4* s = (const float4*)p.src[seg];
    float4* d = (float4*)p.dst[seg];
    for (int i = blockIdx.x * 256 + threadIdx.x; i < n4; i += gridDim.x * 256) {
        float4 v = s[i];
        float4 o;
        o.x = f2tf_f(v.x); o.y = f2tf_f(v.y);
        o.z = f2tf_f(v.z); o.w = f2tf_f(v.w);
        d[i] = o;
    }
}

// ==================== tf32 mma GEMM, 256 thr, NT=128, 2 CTA/SM, 3-stage ======
// CTA tile 128 x 128, warp tile 64 x 32 (2 row-warps x 4 col-warps), BK=32.
// EPI: 1 relu f32, 2 fuse->tf32, 3 quality, 4 tf32 (z-dual), 5 dual f32+tf32,
//      6 tf32 scaled by 0.125 (attention Q)
#define GS 36
#define NT 128
#define NF 4
template<int EPI>
__global__ void __launch_bounds__(256, 2) gemm_mma(
    const float* __restrict__ A, const float* __restrict__ A2,
    const float* __restrict__ W, const float* __restrict__ bias,
    const float* __restrict__ F, const float* __restrict__ w2,
    const float* __restrict__ b2, float* __restrict__ C, float* __restrict__ C2,
    int Mrows, int Kw, int Ktiles)
{
    constexpr int ASZ = 128 * GS;
    constexpr int WSZ = NT * GS;
    extern __shared__ float sm[];
    float* Asm = sm;                 // 3 x ASZ
    float* Wsm = sm + 3 * ASZ;       // 3 x WSZ
    const uint32_t sA = smem_u32(Asm);
    const uint32_t sW = smem_u32(Wsm);

    // combined K/V launch: z=1 -> second weight/bias/output set (EPI==4 only)
    if (EPI == 4 && blockIdx.z) { W = F; C = C2; bias = w2; }

    const int tid = threadIdx.x;
    const int wid = tid >> 5, lane = tid & 31;
    const int g = lane >> 2, t = lane & 3;
    const int wm = wid & 1, wn = wid >> 1;
    const int row0 = blockIdx.y * 128;
    const int col0 = blockIdx.x * NT;

    float acc[4][NF][4];
    #pragma unroll
    for (int mf = 0; mf < 4; ++mf)
        #pragma unroll
        for (int nf = 0; nf < NF; ++nf)
            #pragma unroll
            for (int c = 0; c < 4; ++c) acc[mf][nf][c] = 0.f;

    auto load_chunk = [&](int ct, int buf) {
        const int kbase = ct * 32;
        constexpr int NLOAD = (1024 + NT * 8) / 256;     // 8
        #pragma unroll
        for (int it = 0; it < NLOAD; ++it) {
            int vid = tid + it * 256;
            if (vid < 1024) {
                int r = vid >> 3, q = vid & 7;
                int kel = kbase + q * 4;
                int grow = row0 + r;
                const float* src = A;
                int sz = 0;
                if (grow < Mrows) {
                    if (kel < 512) { src = A + (size_t)grow * 512 + kel; sz = 16; }
                    else if (A2 != nullptr && kel < 528) {
                        src = A2 + (size_t)grow * 16 + (kel - 512); sz = 16;
                    }
                }
                cp_async16(sA + (buf * ASZ + r * GS + q * 4) * 4, src, sz);
            } else {
                int vid2 = vid - 1024;
                int r = vid2 >> 3, q = vid2 & 7;
                int kel = kbase + q * 4;
                const float* src = W + (size_t)(col0 + r) * Kw + kel;
                int sz = (kel < Kw) ? 16 : 0;
                cp_async16(sW + (buf * WSZ + r * GS + q * 4) * 4, src, sz);
            }
        }
        CP_COMMIT();
    };

    load_chunk(0, 0);
    if (Ktiles > 1) load_chunk(1, 1);

    for (int ct = 0; ct < Ktiles; ++ct) {
        const int buf = ct % 3;
        if (ct + 2 < Ktiles) load_chunk(ct + 2, (ct + 2) % 3);
        if (ct + 2 < Ktiles)      { CP_WAIT(2); }
        else if (ct + 1 < Ktiles) { CP_WAIT(1); }
        else                      { CP_WAIT(0); }
        __syncthreads();

        const float* Ab = Asm + buf * ASZ + (wm * 64) * GS;
        const float* Wb = Wsm + buf * WSZ + (wn * (NT / 4)) * GS;
        #pragma unroll
        for (int ks = 0; ks < 4; ++ks) {
            const int k0 = ks * 8;
            uint32_t af[4][4];
            #pragma unroll
            for (int mf = 0; mf < 4; ++mf) {
                const float* ar = Ab + (mf * 16) * GS + k0;
                af[mf][0] = __float_as_uint(ar[(g    ) * GS + t    ]);
                af[mf][1] = __float_as_uint(ar[(g + 8) * GS + t    ]);
                af[mf][2] = __float_as_uint(ar[(g    ) * GS + t + 4]);
                af[mf][3] = __float_as_uint(ar[(g + 8) * GS + t + 4]);
            }
            #pragma unroll
            for (int nf = 0; nf < NF; ++nf) {
                const float* wrp = Wb + (nf * 8 + g) * GS + k0;
                uint32_t b0 = __float_as_uint(wrp[t]);
                uint32_t b1 = __float_as_uint(wrp[t + 4]);
                #pragma unroll
                for (int mf = 0; mf < 4; ++mf)
                    mma_tf32(acc[mf][nf], af[mf][0], af[mf][1], af[mf][2], af[mf][3], b0, b1);
            }
        }
        __syncthreads();
    }

    if (EPI != 3) {
        #pragma unroll
        for (int mf = 0; mf < 4; ++mf) {
            #pragma unroll
            for (int r01 = 0; r01 < 2; ++r01) {
                int grow = row0 + wm * 64 + mf * 16 + g + r01 * 8;
                if (grow >= Mrows) continue;
                #pragma unroll
                for (int nf = 0; nf < NF; ++nf) {
                    int gcol = col0 + wn * (NT / 4) + nf * 8 + 2 * t;
                    float v0 = acc[mf][nf][r01 * 2 + 0] + bias[gcol];
                    float v1 = acc[mf][nf][r01 * 2 + 1] + bias[gcol + 1];
                    if (EPI == 1) { v0 = fmaxf(v0, 0.f); v1 = fmaxf(v1, 0.f); }
                    else if (EPI == 2) {
                        const float* fp = F + (size_t)grow * 512 + gcol;
                        v0 = 0.7f * fp[0] + 0.3f * v0;
                        v1 = 0.7f * fp[1] + 0.3f * v1;
                    } else if (EPI == 6) {
                        v0 *= 0.125f; v1 *= 0.125f;
                    }
                    if (EPI == 2 || EPI == 4 || EPI == 6) { v0 = f2tf_f(v0); v1 = f2tf_f(v1); }
                    *(float2*)(C + (size_t)grow * 512 + gcol) = make_float2(v0, v1);
                    if (EPI == 5)
                        *(float2*)(C2 + (size_t)grow * 512 + gcol) =
                            make_float2(f2tf_f(v0), f2tf_f(v1));
                }
            }
        }
    } else {
        // quality head (NT=128, col0=0): sigmoid(b2 + sum relu(acc+b1)*w2)
        float* qpart = sm;
        __syncthreads();
        #pragma unroll
        for (int mf = 0; mf < 4; ++mf) {
            #pragma unroll
            for (int r01 = 0; r01 < 2; ++r01) {
                float s = 0.f;
                #pragma unroll
                for (int nf = 0; nf < NF; ++nf) {
                    int c = wn * (NT / 4) + nf * 8 + 2 * t;
                    float h0 = fmaxf(acc[mf][nf][r01 * 2 + 0] + bias[c], 0.f);
                    float h1 = fmaxf(acc[mf][nf][r01 * 2 + 1] + bias[c + 1], 0.f);
                    s += h0 * w2[c] + h1 * w2[c + 1];
                }
                int rl = wm * 64 + mf * 16 + r01 * 8 + g;
                qpart[rl * 17 + wn * 4 + t] = s;
            }
        }
        __syncthreads();
        if (tid < 128) {
            float s = b2[0];
            #pragma unroll
            for (int i = 0; i < 16; ++i) s += qpart[tid * 17 + i];
            C[row0 + tid] = 1.f / (1.f + expf(-s));
        }
    }
}
#define GEMM_SMEM ((3 * 128 * GS + 3 * NT * GS) * 4)

// ==================== tf32 mma flash attention (no-max softmax, 2 CTA/SM) ====
// Q pre-scaled by 0.125 at projection time.
#define QS 68
#define VS 72
#define ATT_SMEM ((128*QS + 64*QS + 128*QS + 64*VS) * 4)
__global__ void __launch_bounds__(256, 2) attn_mma(
    const float* __restrict__ Q, const float* __restrict__ Kb,
    const float* __restrict__ Vb, float* __restrict__ ctx)
{
    extern __shared__ float sm[];
    float* Qs = sm;
    float* Ks = Qs + 128 * QS;
    float* Ps = Ks + 64 * QS;
    float* Vs = Ps + 128 * QS;
    const uint32_t sK = smem_u32(Ks);
    const uint32_t sV = smem_u32(Vs);

    const int h = blockIdx.x;
    const int b0 = blockIdx.y * 128;
    const int tid = threadIdx.x;
    const int wid = tid >> 5, lane = tid & 31;
    const int g = lane >> 2, t = lane & 3;
    const int qr = wid * 16;

    auto load_kv = [&](int m0) {
        #pragma unroll
        for (int it = 0; it < 4; ++it) {
            int vid = tid + it * 256;
            int r = vid >> 4, q = vid & 15;
            int gm = m0 + r;
            int sz = (gm < MEM) ? 16 : 0;
            cp_async16(sK + (r * QS + q * 4) * 4, Kb + (size_t)gm * 512 + h * 64 + q * 4, sz);
            cp_async16(sV + (r * VS + q * 4) * 4, Vb + (size_t)gm * 512 + h * 64 + q * 4, sz);
        }
        CP_COMMIT();
    };

    load_kv(0);   // prefetch chunk 0 behind Q staging

    #pragma unroll
    for (int it = 0; it < 8; ++it) {
        int vid = tid + it * 256;
        int r = vid >> 4, q = vid & 15;
        float4 v = *(const float4*)(Q + (size_t)(b0 + r) * 512 + h * 64 + q * 4);
        *(float4*)&Qs[r * QS + q * 4] = v;
    }

    float oacc[8][4];
    float rsum[2] = {0.f, 0.f};
    #pragma unroll
    for (int nf = 0; nf < 8; ++nf)
        #pragma unroll
        for (int c = 0; c < 4; ++c) oacc[nf][c] = 0.f;

    for (int m0 = 0; m0 < MEMP; m0 += 64) {
        CP_WAIT(0);
        __syncthreads();

        // ---- S = Q K^T (Q pre-scaled by 0.125) ----
        float sacc[8][4];
        #pragma unroll
        for (int nf = 0; nf < 8; ++nf)
            #pragma unroll
            for (int c = 0; c < 4; ++c) sacc[nf][c] = 0.f;
        #pragma unroll
        for (int ks = 0; ks < 8; ++ks) {
            int k0 = ks * 8;
            uint32_t a0 = __float_as_uint(Qs[(qr + g    ) * QS + k0 + t    ]);
            uint32_t a1 = __float_as_uint(Qs[(qr + g + 8) * QS + k0 + t    ]);
            uint32_t a2 = __float_as_uint(Qs[(qr + g    ) * QS + k0 + t + 4]);
            uint32_t a3 = __float_as_uint(Qs[(qr + g + 8) * QS + k0 + t + 4]);
            #pragma unroll
            for (int nf = 0; nf < 8; ++nf) {
                uint32_t b0 = __float_as_uint(Ks[(nf * 8 + g) * QS + k0 + t    ]);
                uint32_t b1 = __float_as_uint(Ks[(nf * 8 + g) * QS + k0 + t + 4]);
                mma_tf32(sacc[nf], a0, a1, a2, a3, b0, b1);
            }
        }

        // ---- softmax numerator (shift-free: LN-bounded scores) ----
        #pragma unroll
        for (int r01 = 0; r01 < 2; ++r01) {
            float ps = 0.f;
            int prow = qr + g + r01 * 8;
            #pragma unroll
            for (int nf = 0; nf < 8; ++nf) {
                float p0 = 0.f, p1 = 0.f;
                if (m0 + nf * 8 + 2 * t     < MEM) p0 = __expf(sacc[nf][r01 * 2 + 0]);
                if (m0 + nf * 8 + 2 * t + 1 < MEM) p1 = __expf(sacc[nf][r01 * 2 + 1]);
                ps += p0 + p1;
                *(float2*)&Ps[prow * QS + nf * 8 + 2 * t] =
                    make_float2(f2tf_f(p0), f2tf_f(p1));
            }
            ps += __shfl_xor_sync(0xffffffffu, ps, 1);
            ps += __shfl_xor_sync(0xffffffffu, ps, 2);
            rsum[r01] += ps;
        }
        __syncwarp();

        // ---- O += P V ----
        #pragma unroll
        for (int ks = 0; ks < 8; ++ks) {
            int k0 = ks * 8;
            uint32_t a0 = __float_as_uint(Ps[(qr + g    ) * QS + k0 + t    ]);
            uint32_t a1 = __float_as_uint(Ps[(qr + g + 8) * QS + k0 + t    ]);
            uint32_t a2 = __float_as_uint(Ps[(qr + g    ) * QS + k0 + t + 4]);
            uint32_t a3 = __float_as_uint(Ps[(qr + g + 8) * QS + k0 + t + 4]);
            #pragma unroll
            for (int nf = 0; nf < 8; ++nf) {
                uint32_t b0 = __float_as_uint(Vs[(k0 + t    ) * VS + nf * 8 + g]);
                uint32_t b1 = __float_as_uint(Vs[(k0 + t + 4) * VS + nf * 8 + g]);
                mma_tf32(oacc[nf], a0, a1, a2, a3, b0, b1);
            }
        }
        __syncthreads();                 // all Ks/Vs reads done
        if (m0 + 64 < MEMP) load_kv(m0 + 64);
    }

    #pragma unroll
    for (int r01 = 0; r01 < 2; ++r01) {
        float inv = 1.f / rsum[r01];
        int grow = b0 + qr + g + r01 * 8;
        #pragma unroll
        for (int nf = 0; nf < 8; ++nf) {
            float2 o = make_float2(f2tf_f(oacc[nf][r01 * 2 + 0] * inv),
                                   f2tf_f(oacc[nf][r01 * 2 + 1] * inv));
            *(float2*)(ctx + (size_t)grow * 512 + h * 64 + nf * 8 + 2 * t) = o;
        }
    }
}

// ==================== LayerNorm: warp-per-row (8 rows / 256-thr block) ========
__global__ void __launch_bounds__(256) ln_kernel(
    const float* __restrict__ x, const float* __restrict__ g,
    const float* __restrict__ b, float* __restrict__ y)
{
    const int warp = threadIdx.x >> 5, lane = threadIdx.x & 31;
    const int row = blockIdx.x * 8 + warp;
    const float* xr = x + (size_t)row * 512;

    float4 v[4];
    #pragma unroll
    for (int i = 0; i < 4; ++i)
        v[i] = *(const float4*)(xr + i * 128 + lane * 4);

    float s = 0.f;
    #pragma unroll
    for (int i = 0; i < 4; ++i) s += v[i].x + v[i].y + v[i].z + v[i].w;
    #pragma unroll
    for (int o = 16; o > 0; o >>= 1) s += __shfl_xor_sync(0xffffffffu, s, o);
    float mean = s * (1.f / 512.f);

    float ss = 0.f;
    #pragma unroll
    for (int i = 0; i < 4; ++i) {
        v[i].x -= mean; v[i].y -= mean; v[i].z -= mean; v[i].w -= mean;
        ss += v[i].x * v[i].x + v[i].y * v[i].y + v[i].z * v[i].z + v[i].w * v[i].w;
    }
    #pragma unroll
    for (int o = 16; o > 0; o >>= 1) ss += __shfl_xor_sync(0xffffffffu, ss, o);
    float inv = rsqrtf(ss * (1.f / 512.f) + 1e-5f);

    #pragma unroll
    for (int i = 0; i < 4; ++i) {
        float4 gg = *(const float4*)(g + i * 128 + lane * 4);
        float4 bb = *(const float4*)(b + i * 128 + lane * 4);
        float4 o;
        o.x = f2tf_f(v[i].x * inv * gg.x + bb.x);
        o.y = f2tf_f(v[i].y * inv * gg.y + bb.y);
        o.z = f2tf_f(v[i].z * inv * gg.z + bb.z);
        o.w = f2tf_f(v[i].w * inv * gg.w + bb.w);
        *(float4*)(y + (size_t)row * 512 + i * 128 + lane * 4) = o;
    }
}

// ==================== mask compaction + memory EMA ====================
__global__ void __launch_bounds__(256) compact_kernel(
    const float* __restrict__ quality, int* __restrict__ midx, int* __restrict__ mcount)
{
    const int tid = threadIdx.x;
    const int base = tid * 32;
    int cnt = 0;
    for (int i = 0; i < 32; ++i) cnt += (quality[base + i] > 0.7f) ? 1 : 0;
    __shared__ int sc[256];
    __shared__ int offs[256];
    sc[tid] = cnt;
    __syncthreads();
    if (tid == 0) {
        int run = 0;
        for (int t = 0; t < 256; ++t) { offs[t] = run; run += sc[t]; }
        *mcount = run;
    }
    __syncthreads();
    int o = offs[tid];
    for (int i = 0; i < 32; ++i)
        if (quality[base + i] > 0.7f) midx[o++] = base + i;
}

__global__ void __launch_bounds__(128) memupd_kernel(
    const float* __restrict__ wm, const float* __restrict__ ns,
    const int* __restrict__ upd, const int* __restrict__ midx,
    const int* __restrict__ mcount, float* __restrict__ outmem)
{
    const int m = blockIdx.x;
    const int d = threadIdx.x * 4;
    float4 v = *(const float4*)(wm + (size_t)m * 512 + d);
    const int cnt = *mcount;
    for (int jj = 0; jj < cnt; ++jj) {
        int i = midx[jj];
        if (upd[i] == m) {
            float4 s = *(const float4*)(ns + (size_t)i * 512 + d);
            v.x = 0.9f * v.x + 0.1f * s.x;
            v.y = 0.9f * v.y + 0.1f * s.y;
            v.z = 0.9f * v.z + 0.1f * s.z;
            v.w = 0.9f * v.w + 0.1f * s.w;
        }
    }
    *(float4*)(outmem + (size_t)m * 512 + d) = v;
}

// ==================== host launcher ====================
extern "C" void kernel_launch(void* const* d_in, const int* in_sizes, int n_in,
                              void* d_out, int out_size)
{
    const float* obs    = (const float*)d_in[0];
    const float* ego    = (const float*)d_in[1];
    const float* wm     = (const float*)d_in[2];
    const float* enc_w1 = (const float*)d_in[3];
    const float* enc_b1 = (const float*)d_in[4];
    const float* enc_g  = (const float*)d_in[5];
    const float* enc_be = (const float*)d_in[6];
    const float* enc_w2 = (const float*)d_in[7];
    const float* enc_b2 = (const float*)d_in[8];
    const float* wq     = (const float*)d_in[9];
    const float* bq     = (const float*)d_in[10];
    const float* wk     = (const float*)d_in[11];
    const float* bk     = (const float*)d_in[12];
    const float* wv     = (const float*)d_in[13];
    const float* bv     = (const float*)d_in[14];
    const float* wo     = (const float*)d_in[15];
    const float* bo     = (const float*)d_in[16];
    const float* tr_w1  = (const float*)d_in[17];
    const float* tr_b1  = (const float*)d_in[18];
    const float* tr_g   = (const float*)d_in[19];
    const float* tr_be  = (const float*)d_in[20];
    const float* tr_w2  = (const float*)d_in[21];
    const float* tr_b2  = (const float*)d_in[22];
    const float* q_w1   = (const float*)d_in[23];
    const float* q_b1   = (const float*)d_in[24];
    const float* q_w2   = (const float*)d_in[25];
    const float* q_b2   = (const float*)d_in[26];
    const int*   uidx   = (const int*)d_in[27];

    float* out        = (float*)d_out;
    float* next_state = out;
    float* quality    = out + (size_t)BATCH * DIM;
    float* outmem     = quality + BATCH;

    float *h, *hn, *enc, *enc_t, *qb, *ctx, *fused, *ns_t, *kb, *vb;
    float *obs_t, *ego_t, *wm_t, *w_t;
    int *midx, *mcount;
    cudaGetSymbolAddress((void**)&h,      g_h);
    cudaGetSymbolAddress((void**)&hn,     g_hn);
    cudaGetSymbolAddress((void**)&enc,    g_enc);
    cudaGetSymbolAddress((void**)&enc_t,  g_enc_t);
    cudaGetSymbolAddress((void**)&qb,     g_q);
    cudaGetSymbolAddress((void**)&ctx,    g_ctx);
    cudaGetSymbolAddress((void**)&fused,  g_fused);
    cudaGetSymbolAddress((void**)&ns_t,   g_ns_t);
    cudaGetSymbolAddress((void**)&kb,     g_k);
    cudaGetSymbolAddress((void**)&vb,     g_v);
    cudaGetSymbolAddress((void**)&obs_t,  g_obs_t);
    cudaGetSymbolAddress((void**)&ego_t,  g_ego_t);
    cudaGetSymbolAddress((void**)&wm_t,   g_wm_t);
    cudaGetSymbolAddress((void**)&w_t,    g_w_t);
    cudaGetSymbolAddress((void**)&midx,   g_midx);
    cudaGetSymbolAddress((void**)&mcount, g_mcount);

    cudaFuncSetAttribute(gemm_mma<1>, cudaFuncAttributeMaxDynamicSharedMemorySize, GEMM_SMEM);
    cudaFuncSetAttribute(gemm_mma<2>, cudaFuncAttributeMaxDynamicSharedMemorySize, GEMM_SMEM);
    cudaFuncSetAttribute(gemm_mma<3>, cudaFuncAttributeMaxDynamicSharedMemorySize, GEMM_SMEM);
    cudaFuncSetAttribute(gemm_mma<4>, cudaFuncAttributeMaxDynamicSharedMemorySize, GEMM_SMEM);
    cudaFuncSetAttribute(gemm_mma<5>, cudaFuncAttributeMaxDynamicSharedMemorySize, GEMM_SMEM);
    cudaFuncSetAttribute(gemm_mma<6>, cudaFuncAttributeMaxDynamicSharedMemorySize, GEMM_SMEM);
    cudaFuncSetAttribute(attn_mma,    cudaFuncAttributeMaxDynamicSharedMemorySize, ATT_SMEM);

    // ---- prep ----
    PrepArgs pa;
    const float* srcs[12] = {obs, ego, wm, enc_w1, enc_w2, wq, wk, wv, wo, tr_w1, tr_w2, q_w1};
    float* dsts[12] = {obs_t, ego_t, wm_t,
                       w_t + W_ENC1, w_t + W_ENC2, w_t + W_WQ, w_t + W_WK, w_t + W_WV,
                       w_t + W_WO, w_t + W_TR1, w_t + W_TR2, w_t + W_Q1};
    int n4s[12] = {BATCH*DIM/4, BATCH*16/4, MEM*DIM/4,
                   262144/4, 262144/4, 262144/4, 262144/4, 262144/4,
                   262144/4, 270336/4, 262144/4, 65536/4};
    for (int i = 0; i < 12; ++i) { pa.src[i] = srcs[i]; pa.dst[i] = dsts[i]; pa.n4[i] = n4s[i]; }
    prep_kernel<<<dim3(512, 12), 256>>>(pa);

    dim3 gBig(4, 64), gKV(4, 8, 2), gQual(1, 64);

    // encoder
    gemm_mma<1><<<gBig, 256, GEMM_SMEM>>>(obs_t, nullptr, w_t + W_ENC1, enc_b1,
        nullptr, nullptr, nullptr, h, nullptr, BATCH, 512, 16);
    ln_kernel<<<BATCH/8, 256>>>(h, enc_g, enc_be, hn);
    gemm_mma<5><<<gBig, 256, GEMM_SMEM>>>(hn, nullptr, w_t + W_ENC2, enc_b2,
        nullptr, nullptr, nullptr, enc, enc_t, BATCH, 512, 16);
    // projections (Q pre-scaled 0.125; K+V combined via blockIdx.z)
    gemm_mma<6><<<gBig, 256, GEMM_SMEM>>>(enc_t, nullptr, w_t + W_WQ, bq,
        nullptr, nullptr, nullptr, qb, nullptr, BATCH, 512, 16);
    gemm_mma<4><<<gKV, 256, GEMM_SMEM>>>(wm_t, nullptr, w_t + W_WK, bk,
        w_t + W_WV, bv, nullptr, kb, vb, MEM, 512, 16);
    // attention
    attn_mma<<<dim3(HEADS, BATCH / 128), 256, ATT_SMEM>>>(qb, kb, vb, ctx);
    // out projection + fuse (F = enc fp32)
    gemm_mma<2><<<gBig, 256, GEMM_SMEM>>>(ctx, nullptr, w_t + W_WO, bo,
        enc, nullptr, nullptr, fused, nullptr, BATCH, 512, 16);
    // transition (K=528, ego in 17th K-chunk)
    gemm_mma<1><<<gBig, 256, GEMM_SMEM>>>(fused, ego_t, w_t + W_TR1, tr_b1,
        nullptr, nullptr, nullptr, h, nullptr, BATCH, 528, 17);
    ln_kernel<<<BATCH/8, 256>>>(h, tr_g, tr_be, hn);
    gemm_mma<5><<<gBig, 256, GEMM_SMEM>>>(hn, nullptr, w_t + W_TR2, tr_b2,
        nullptr, nullptr, nullptr, next_state, ns_t, BATCH, 512, 16);
    // quality head (tf32 ns_t input)
    gemm_mma<3><<<gQual, 256, GEMM_SMEM>>>(ns_t, nullptr, w_t + W_Q1, q_b1,
        nullptr, q_w2, q_b2, quality, nullptr, BATCH, 512, 16);
    // memory bank update
    compact_kernel<<<1, 256>>>(quality, midx, mcount);
    memupd_kernel<<<MEM, 128>>>(wm, next_state, uidx, midx, mcount, outmem);
}

// round 11
// speedup vs baseline: 2.1952x; 1.4409x over previous
#include <cuda_runtime.h>
#include <cuda_fp16.h>
#include <math.h>
#include <stdint.h>

#define BATCH 8192
#define DIM   512
#define MEM   1000
#define MEMP  1024
#define HEADS 8
#define DH    64

// ==================== helpers ====================
__device__ __forceinline__ uint32_t smem_u32(const void* p) {
    uint32_t a;
    asm("{ .reg .u64 t; cvta.to.shared.u64 t, %1; cvt.u32.u64 %0, t; }" : "=r"(a) : "l"(p));
    return a;
}
__device__ __forceinline__ void mma_f16(float* c, uint32_t a0, uint32_t a1,
                                        uint32_t a2, uint32_t a3,
                                        uint32_t b0, uint32_t b1) {
    asm volatile(
        "mma.sync.aligned.m16n8k16.row.col.f32.f16.f16.f32 "
        "{%0,%1,%2,%3}, {%4,%5,%6,%7}, {%8,%9}, {%0,%1,%2,%3};"
        : "+f"(c[0]), "+f"(c[1]), "+f"(c[2]), "+f"(c[3])
        : "r"(a0), "r"(a1), "r"(a2), "r"(a3), "r"(b0), "r"(b1));
}
__device__ __forceinline__ void cp_async16(uint32_t dst, const void* src, int srcsize) {
    asm volatile("cp.async.cg.shared.global [%0], [%1], 16, %2;"
                 :: "r"(dst), "l"(src), "r"(srcsize));
}
#define CP_COMMIT() asm volatile("cp.async.commit_group;" ::: "memory")
#define CP_WAIT(N)  asm volatile("cp.async.wait_group %0;" :: "n"(N) : "memory")

// ==================== scratch ====================
__device__ float  g_h[BATCH*DIM];         // fp32 pre-LN
__device__ float  g_enc[BATCH*DIM];       // fp32 (F for fuse)
__device__ __half g_hn_h[BATCH*DIM];
__device__ __half g_enc_h[BATCH*DIM];
__device__ __half g_q_h[BATCH*DIM];       // pre-scaled by 0.125
__device__ __half g_ctx_h[BATCH*DIM];
__device__ __half g_fused_h[BATCH*DIM];
__device__ __half g_ns_h[BATCH*DIM];
__device__ __half g_k_h[MEMP*DIM];        // zero-init pads
__device__ __half g_vt_h[DIM*MEMP];       // V^T: [d][m]
__device__ __half g_obs_h[BATCH*DIM];
__device__ __half g_ego_h[BATCH*16];
__device__ __half g_wm_h[MEMP*DIM];       // zero-init pad rows 1000..1023
#define W_ENC1 0
#define W_ENC2 262144
#define W_WQ   524288
#define W_WK   786432
#define W_WV   1048576
#define W_WO   1310720
#define W_TR1  1572864
#define W_TR2  1843200
#define W_Q1   2105344
#define W_TOT  2170880
__device__ __half g_w_h[W_TOT];
__device__ int    g_midx[BATCH];
__device__ int    g_mcount;

// ==================== prep: fp32 -> fp16 ====================
struct PrepArgs {
    const float* src[12];
    __half*      dst[12];
    int          n4[12];
};
__global__ void __launch_bounds__(256) prep_kernel(PrepArgs p) {
    int seg = blockIdx.y;
    int n4 = p.n4[seg];
    const float4* s = (const float4*)p.src[seg];
    for (int i = blockIdx.x * 256 + threadIdx.x; i < n4; i += gridDim.x * 256) {
        float4 v = s[i];
        __half2 lo = __floats2half2_rn(v.x, v.y);
        __half2 hi = __floats2half2_rn(v.z, v.w);
        uint2 pk;
        pk.x = *(uint32_t*)&lo; pk.y = *(uint32_t*)&hi;
        *(uint2*)(p.dst[seg] + (size_t)i * 4) = pk;
    }
}

// ==================== fp16 mma GEMM, 256 thr, NT cols, BK=32, 3-stage ========
// CTA tile 128 x NT, warp tile 64 x NT/4 (2 row-warps x 4 col-warps).
// EPI: 1 relu->f32, 2 fuse->f16, 3 quality, 4 f16, 5 dual f32+f16,
//      6 f16 scaled 0.125, 7 f16 row-bias (V^T)
#define GSH 40                  // smem stride in halves (80B = 20 banks, CF)
template<int NT, int EPI>
__global__ void __launch_bounds__(256) gemm_mma(
    const __half* __restrict__ A, const __half* __restrict__ A2,
    const __half* __restrict__ W, const float* __restrict__ bias,
    const float* __restrict__ F, const float* __restrict__ w2,
    const float* __restrict__ b2, void* __restrict__ Cv, void* __restrict__ C2v,
    int Mrows, int Kw, int Ktiles, int ldc)
{
    constexpr int NF  = NT / 32;
    constexpr int ASZ = 128 * GSH;          // halves
    constexpr int WSZ = NT * GSH;
    extern __shared__ __half smh[];
    __half* Ah = smh;                       // 3 x ASZ
    __half* Wh = smh + 3 * ASZ;             // 3 x WSZ
    const uint32_t sA = smem_u32(Ah);
    const uint32_t sW = smem_u32(Wh);

    const int tid = threadIdx.x;
    const int wid = tid >> 5, lane = tid & 31;
    const int g = lane >> 2, t = lane & 3;
    const int wm = wid & 1, wn = wid >> 1;
    const int row0 = blockIdx.y * 128;
    const int col0 = blockIdx.x * NT;

    float acc[4][NF][4];
    #pragma unroll
    for (int mf = 0; mf < 4; ++mf)
        #pragma unroll
        for (int nf = 0; nf < NF; ++nf)
            #pragma unroll
            for (int c = 0; c < 4; ++c) acc[mf][nf][c] = 0.f;

    auto load_chunk = [&](int ct, int buf) {
        const int kbase = ct * 32;
        constexpr int NLOAD = (512 + NT * 4) / 256;
        #pragma unroll
        for (int it = 0; it < NLOAD; ++it) {
            int vid = tid + it * 256;
            if (vid < 512) {
                int r = vid >> 2, q = vid & 3;
                int kel = kbase + q * 8;
                int grow = row0 + r;
                const __half* src = A;
                int sz = 0;
                if (grow < Mrows) {
                    if (kel < 512) { src = A + (size_t)grow * 512 + kel; sz = 16; }
                    else if (A2 != nullptr && kel < 528) {
                        src = A2 + (size_t)grow * 16 + (kel - 512); sz = 16;
                    }
                }
                cp_async16(sA + (buf * ASZ + r * GSH + q * 8) * 2, src, sz);
            } else {
                int vid2 = vid - 512;
                int r = vid2 >> 2, q = vid2 & 3;
                int kel = kbase + q * 8;
                const __half* src = W + (size_t)(col0 + r) * Kw + kel;
                int sz = (kel < Kw) ? 16 : 0;
                cp_async16(sW + (buf * WSZ + r * GSH + q * 8) * 2, src, sz);
            }
        }
        CP_COMMIT();
    };

    load_chunk(0, 0);
    if (Ktiles > 1) load_chunk(1, 1);

    for (int ct = 0; ct < Ktiles; ++ct) {
        const int buf = ct % 3;
        if (ct + 2 < Ktiles) load_chunk(ct + 2, (ct + 2) % 3);
        if (ct + 2 < Ktiles)      { CP_WAIT(2); }
        else if (ct + 1 < Ktiles) { CP_WAIT(1); }
        else                      { CP_WAIT(0); }
        __syncthreads();

        const __half* Ab = Ah + buf * ASZ + (wm * 64) * GSH;
        const __half* Wb = Wh + buf * WSZ + (wn * (NT / 4)) * GSH;
        #pragma unroll
        for (int ks = 0; ks < 2; ++ks) {
            const int k0 = ks * 16;
            uint32_t af[4][4];
            #pragma unroll
            for (int mf = 0; mf < 4; ++mf) {
                const __half* ar = Ab + (mf * 16) * GSH + k0;
                af[mf][0] = *(const uint32_t*)(ar + (g    ) * GSH + 2 * t    );
                af[mf][1] = *(const uint32_t*)(ar + (g + 8) * GSH + 2 * t    );
                af[mf][2] = *(const uint32_t*)(ar + (g    ) * GSH + 2 * t + 8);
                af[mf][3] = *(const uint32_t*)(ar + (g + 8) * GSH + 2 * t + 8);
            }
            #pragma unroll
            for (int nf = 0; nf < NF; ++nf) {
                const __half* wrp = Wb + (nf * 8 + g) * GSH + k0;
                uint32_t b0 = *(const uint32_t*)(wrp + 2 * t);
                uint32_t b1 = *(const uint32_t*)(wrp + 2 * t + 8);
                #pragma unroll
                for (int mf = 0; mf < 4; ++mf)
                    mma_f16(acc[mf][nf], af[mf][0], af[mf][1], af[mf][2], af[mf][3], b0, b1);
            }
        }
        __syncthreads();
    }

    if (EPI != 3) {
        #pragma unroll
        for (int mf = 0; mf < 4; ++mf) {
            #pragma unroll
            for (int r01 = 0; r01 < 2; ++r01) {
                int grow = row0 + wm * 64 + mf * 16 + g + r01 * 8;
                if (grow >= Mrows) continue;
                #pragma unroll
                for (int nf = 0; nf < NF; ++nf) {
                    int gcol = col0 + wn * (NT / 4) + nf * 8 + 2 * t;
                    float b0 = (EPI == 7) ? bias[grow] : bias[gcol];
                    float b1 = (EPI == 7) ? bias[grow] : bias[gcol + 1];
                    float v0 = acc[mf][nf][r01 * 2 + 0] + b0;
                    float v1 = acc[mf][nf][r01 * 2 + 1] + b1;
                    if (EPI == 1) { v0 = fmaxf(v0, 0.f); v1 = fmaxf(v1, 0.f); }
                    else if (EPI == 2) {
                        const float* fp = F + (size_t)grow * 512 + gcol;
                        v0 = 0.7f * fp[0] + 0.3f * v0;
                        v1 = 0.7f * fp[1] + 0.3f * v1;
                    } else if (EPI == 6) { v0 *= 0.125f; v1 *= 0.125f; }
                    size_t off = (size_t)grow * ldc + gcol;
                    if (EPI == 1) {
                        *(float2*)((float*)Cv + off) = make_float2(v0, v1);
                    } else if (EPI == 5) {
                        *(float2*)((float*)Cv + off) = make_float2(v0, v1);
                        __half2 hv = __floats2half2_rn(v0, v1);
                        *(__half2*)((__half*)C2v + off) = hv;
                    } else {
                        __half2 hv = __floats2half2_rn(v0, v1);
                        *(__half2*)((__half*)Cv + off) = hv;
                    }
                }
            }
        }
    } else {
        // quality head (NT=128, col0=0): sigmoid(b2 + sum relu(acc+b1)*w2)
        float* qpart = (float*)smh;
        __syncthreads();
        #pragma unroll
        for (int mf = 0; mf < 4; ++mf) {
            #pragma unroll
            for (int r01 = 0; r01 < 2; ++r01) {
                float s = 0.f;
                #pragma unroll
                for (int nf = 0; nf < NF; ++nf) {
                    int c = wn * (NT / 4) + nf * 8 + 2 * t;
                    float h0 = fmaxf(acc[mf][nf][r01 * 2 + 0] + bias[c], 0.f);
                    float h1 = fmaxf(acc[mf][nf][r01 * 2 + 1] + bias[c + 1], 0.f);
                    s += h0 * w2[c] + h1 * w2[c + 1];
                }
                int rl = wm * 64 + mf * 16 + r01 * 8 + g;
                qpart[rl * 17 + wn * 4 + t] = s;
            }
        }
        __syncthreads();
        if (tid < 128) {
            float s = b2[0];
            #pragma unroll
            for (int i = 0; i < 16; ++i) s += qpart[tid * 17 + i];
            ((float*)Cv)[row0 + tid] = 1.f / (1.f + expf(-s));
        }
    }
}
#define GEMM_SMEM(NT) ((3 * 128 * GSH + 3 * (NT) * GSH) * 2)

// ==================== fp16 mma flash attention (no-max softmax, 2 CTA/SM) ====
// Q pre-scaled by 0.125. Vt is V^T [d][m].
#define AS 72      // smem stride in halves
#define ATT_SMEM ((128*AS + 64*AS + 128*AS + 64*AS) * 2)
__global__ void __launch_bounds__(256, 2) attn_mma(
    const __half* __restrict__ Q, const __half* __restrict__ Kb,
    const __half* __restrict__ Vt, __half* __restrict__ ctx)
{
    extern __shared__ __half smh[];
    __half* Qs = smh;                 // 128 x AS
    __half* Ks = Qs + 128 * AS;       // 64 x AS
    __half* Ps = Ks + 64 * AS;        // 128 x AS
    __half* Vs = Ps + 128 * AS;       // 64 x AS  (rows = d, cols = m)
    const uint32_t sK = smem_u32(Ks);
    const uint32_t sV = smem_u32(Vs);

    const int h = blockIdx.x;
    const int b0 = blockIdx.y * 128;
    const int tid = threadIdx.x;
    const int wid = tid >> 5, lane = tid & 31;
    const int g = lane >> 2, t = lane & 3;
    const int qr = wid * 16;

    auto load_kv = [&](int m0) {
        #pragma unroll
        for (int it = 0; it < 4; ++it) {
            int vid = tid + it * 256;
            if (vid < 512) {
                int r = vid >> 3, q = vid & 7;      // K: row=mem, 64 halves
                int gm = m0 + r;
                int sz = (gm < MEM) ? 16 : 0;
                cp_async16(sK + (r * AS + q * 8) * 2,
                           Kb + (size_t)gm * 512 + h * 64 + q * 8, sz);
            } else {
                int vid2 = vid - 512;
                int r = vid2 >> 3, q = vid2 & 7;    // V: row=d, 64 m-halves
                cp_async16(sV + (r * AS + q * 8) * 2,
                           Vt + (size_t)(h * 64 + r) * MEMP + m0 + q * 8, 16);
            }
        }
        CP_COMMIT();
    };

    load_kv(0);

    #pragma unroll
    for (int it = 0; it < 4; ++it) {
        int vid = tid + it * 256;                   // 128 rows x 8 segs of 8 halves
        int r = vid >> 3, q = vid & 7;
        uint4 v = *(const uint4*)(Q + (size_t)(b0 + r) * 512 + h * 64 + q * 8);
        *(uint4*)(Qs + r * AS + q * 8) = v;
    }

    float oacc[8][4];
    float rsum[2] = {0.f, 0.f};
    #pragma unroll
    for (int nf = 0; nf < 8; ++nf)
        #pragma unroll
        for (int c = 0; c < 4; ++c) oacc[nf][c] = 0.f;

    for (int m0 = 0; m0 < MEMP; m0 += 64) {
        CP_WAIT(0);
        __syncthreads();

        // ---- S = Q K^T (d = 64 -> 4 k16 steps) ----
        float sacc[8][4];
        #pragma unroll
        for (int nf = 0; nf < 8; ++nf)
            #pragma unroll
            for (int c = 0; c < 4; ++c) sacc[nf][c] = 0.f;
        #pragma unroll
        for (int ks = 0; ks < 4; ++ks) {
            int k0 = ks * 16;
            uint32_t a0 = *(const uint32_t*)(Qs + (qr + g    ) * AS + k0 + 2 * t    );
            uint32_t a1 = *(const uint32_t*)(Qs + (qr + g + 8) * AS + k0 + 2 * t    );
            uint32_t a2 = *(const uint32_t*)(Qs + (qr + g    ) * AS + k0 + 2 * t + 8);
            uint32_t a3 = *(const uint32_t*)(Qs + (qr + g + 8) * AS + k0 + 2 * t + 8);
            #pragma unroll
            for (int nf = 0; nf < 8; ++nf) {
                uint32_t b0 = *(const uint32_t*)(Ks + (nf * 8 + g) * AS + k0 + 2 * t    );
                uint32_t b1 = *(const uint32_t*)(Ks + (nf * 8 + g) * AS + k0 + 2 * t + 8);
                mma_f16(sacc[nf], a0, a1, a2, a3, b0, b1);
            }
        }

        // ---- softmax numerator (shift-free: LN-bounded scores) ----
        #pragma unroll
        for (int r01 = 0; r01 < 2; ++r01) {
            float ps = 0.f;
            int prow = qr + g + r01 * 8;
            #pragma unroll
            for (int nf = 0; nf < 8; ++nf) {
                float p0 = 0.f, p1 = 0.f;
                if (m0 + nf * 8 + 2 * t     < MEM) p0 = __expf(sacc[nf][r01 * 2 + 0]);
                if (m0 + nf * 8 + 2 * t + 1 < MEM) p1 = __expf(sacc[nf][r01 * 2 + 1]);
                ps += p0 + p1;
                *(__half2*)(Ps + prow * AS + nf * 8 + 2 * t) = __floats2half2_rn(p0, p1);
            }
            ps += __shfl_xor_sync(0xffffffffu, ps, 1);
            ps += __shfl_xor_sync(0xffffffffu, ps, 2);
            rsum[r01] += ps;
        }
        __syncwarp();

        // ---- O += P V  (k = mem 64 -> 4 k16 steps; B from Vs[d][m]) ----
        #pragma unroll
        for (int ks = 0; ks < 4; ++ks) {
            int k0 = ks * 16;
            uint32_t a0 = *(const uint32_t*)(Ps + (qr + g    ) * AS + k0 + 2 * t    );
            uint32_t a1 = *(const uint32_t*)(Ps + (qr + g + 8) * AS + k0 + 2 * t    );
            uint32_t a2 = *(const uint32_t*)(Ps + (qr + g    ) * AS + k0 + 2 * t + 8);
            uint32_t a3 = *(const uint32_t*)(Ps + (qr + g + 8) * AS + k0 + 2 * t + 8);
            #pragma unroll
            for (int nf = 0; nf < 8; ++nf) {
                uint32_t b0 = *(const uint32_t*)(Vs + (nf * 8 + g) * AS + k0 + 2 * t    );
                uint32_t b1 = *(const uint32_t*)(Vs + (nf * 8 + g) * AS + k0 + 2 * t + 8);
                mma_f16(oacc[nf], a0, a1, a2, a3, b0, b1);
            }
        }
        __syncthreads();
        if (m0 + 64 < MEMP) load_kv(m0 + 64);
    }

    #pragma unroll
    for (int r01 = 0; r01 < 2; ++r01) {
        float inv = 1.f / rsum[r01];
        int grow = b0 + qr + g + r01 * 8;
        #pragma unroll
        for (int nf = 0; nf < 8; ++nf) {
            __half2 o = __floats2half2_rn(oacc[nf][r01 * 2 + 0] * inv,
                                          oacc[nf][r01 * 2 + 1] * inv);
            *(__half2*)(ctx + (size_t)grow * 512 + h * 64 + nf * 8 + 2 * t) = o;
        }
    }
}

// ==================== LayerNorm: warp-per-row, fp32 in, fp16 out =============
__global__ void __launch_bounds__(256) ln_kernel(
    const float* __restrict__ x, const float* __restrict__ g,
    const float* __restrict__ b, __half* __restrict__ y)
{
    const int warp = threadIdx.x >> 5, lane = threadIdx.x & 31;
    const int row = blockIdx.x * 8 + warp;
    const float* xr = x + (size_t)row * 512;

    float4 v[4];
    #pragma unroll
    for (int i = 0; i < 4; ++i)
        v[i] = *(const float4*)(xr + i * 128 + lane * 4);

    float s = 0.f;
    #pragma unroll
    for (int i = 0; i < 4; ++i) s += v[i].x + v[i].y + v[i].z + v[i].w;
    #pragma unroll
    for (int o = 16; o > 0; o >>= 1) s += __shfl_xor_sync(0xffffffffu, s, o);
    float mean = s * (1.f / 512.f);

    float ss = 0.f;
    #pragma unroll
    for (int i = 0; i < 4; ++i) {
        v[i].x -= mean; v[i].y -= mean; v[i].z -= mean; v[i].w -= mean;
        ss += v[i].x * v[i].x + v[i].y * v[i].y + v[i].z * v[i].z + v[i].w * v[i].w;
    }
    #pragma unroll
    for (int o = 16; o > 0; o >>= 1) ss += __shfl_xor_sync(0xffffffffu, ss, o);
    float inv = rsqrtf(ss * (1.f / 512.f) + 1e-5f);

    #pragma unroll
    for (int i = 0; i < 4; ++i) {
        float4 gg = *(const float4*)(g + i * 128 + lane * 4);
        float4 bb = *(const float4*)(b + i * 128 + lane * 4);
        __half2 lo = __floats2half2_rn(v[i].x * inv * gg.x + bb.x,
                                       v[i].y * inv * gg.y + bb.y);
        __half2 hi = __floats2half2_rn(v[i].z * inv * gg.z + bb.z,
                                       v[i].w * inv * gg.w + bb.w);
        uint2 pk; pk.x = *(uint32_t*)&lo; pk.y = *(uint32_t*)&hi;
        *(uint2*)(y + (size_t)row * 512 + i * 128 + lane * 4) = pk;
    }
}

// ==================== mask compaction + memory EMA ====================
__global__ void __launch_bounds__(256) compact_kernel(
    const float* __restrict__ quality, int* __restrict__ midx, int* __restrict__ mcount)
{
    const int tid = threadIdx.x;
    const int base = tid * 32;
    int cnt = 0;
    for (int i = 0; i < 32; ++i) cnt += (quality[base + i] > 0.7f) ? 1 : 0;
    __shared__ int sc[256];
    __shared__ int offs[256];
    sc[tid] = cnt;
    __syncthreads();
    if (tid == 0) {
        int run = 0;
        for (int t = 0; t < 256; ++t) { offs[t] = run; run += sc[t]; }
        *mcount = run;
    }
    __syncthreads();
    int o = offs[tid];
    for (int i = 0; i < 32; ++i)
        if (quality[base + i] > 0.7f) midx[o++] = base + i;
}

__global__ void __launch_bounds__(128) memupd_kernel(
    const float* __restrict__ wm, const float* __restrict__ ns,
    const int* __restrict__ upd, const int* __restrict__ midx,
    const int* __restrict__ mcount, float* __restrict__ outmem)
{
    const int m = blockIdx.x;
    const int d = threadIdx.x * 4;
    float4 v = *(const float4*)(wm + (size_t)m * 512 + d);
    const int cnt = *mcount;
    for (int jj = 0; jj < cnt; ++jj) {
        int i = midx[jj];
        if (upd[i] == m) {
            float4 s = *(const float4*)(ns + (size_t)i * 512 + d);
            v.x = 0.9f * v.x + 0.1f * s.x;
            v.y = 0.9f * v.y + 0.1f * s.y;
            v.z = 0.9f * v.z + 0.1f * s.z;
            v.w = 0.9f * v.w + 0.1f * s.w;
        }
    }
    *(float4*)(outmem + (size_t)m * 512 + d) = v;
}

// ==================== host launcher ====================
extern "C" void kernel_launch(void* const* d_in, const int* in_sizes, int n_in,
                              void* d_out, int out_size)
{
    const float* obs    = (const float*)d_in[0];
    const float* ego    = (const float*)d_in[1];
    const float* wm     = (const float*)d_in[2];
    const float* enc_w1 = (const float*)d_in[3];
    const float* enc_b1 = (const float*)d_in[4];
    const float* enc_g  = (const float*)d_in[5];
    const float* enc_be = (const float*)d_in[6];
    const float* enc_w2 = (const float*)d_in[7];
    const float* enc_b2 = (const float*)d_in[8];
    const float* wq     = (const float*)d_in[9];
    const float* bq     = (const float*)d_in[10];
    const float* wk     = (const float*)d_in[11];
    const float* bk     = (const float*)d_in[12];
    const float* wv     = (const float*)d_in[13];
    const float* bv     = (const float*)d_in[14];
    const float* wo     = (const float*)d_in[15];
    const float* bo     = (const float*)d_in[16];
    const float* tr_w1  = (const float*)d_in[17];
    const float* tr_b1  = (const float*)d_in[18];
    const float* tr_g   = (const float*)d_in[19];
    const float* tr_be  = (const float*)d_in[20];
    const float* tr_w2  = (const float*)d_in[21];
    const float* tr_b2  = (const float*)d_in[22];
    const float* q_w1   = (const float*)d_in[23];
    const float* q_b1   = (const float*)d_in[24];
    const float* q_w2   = (const float*)d_in[25];
    const float* q_b2   = (const float*)d_in[26];
    const int*   uidx   = (const int*)d_in[27];

    float* out        = (float*)d_out;
    float* next_state = out;
    float* quality    = out + (size_t)BATCH * DIM;
    float* outmem     = quality + BATCH;

    float *h, *enc;
    __half *hn_h, *enc_h, *q_h, *ctx_h, *fused_h, *ns_h, *k_h, *vt_h;
    __half *obs_h, *ego_h, *wm_h, *w_h;
    int *midx, *mcount;
    cudaGetSymbolAddress((void**)&h,      g_h);
    cudaGetSymbolAddress((void**)&enc,    g_enc);
    cudaGetSymbolAddress((void**)&hn_h,   g_hn_h);
    cudaGetSymbolAddress((void**)&enc_h,  g_enc_h);
    cudaGetSymbolAddress((void**)&q_h,    g_q_h);
    cudaGetSymbolAddress((void**)&ctx_h,  g_ctx_h);
    cudaGetSymbolAddress((void**)&fused_h,g_fused_h);
    cudaGetSymbolAddress((void**)&ns_h,   g_ns_h);
    cudaGetSymbolAddress((void**)&k_h,    g_k_h);
    cudaGetSymbolAddress((void**)&vt_h,   g_vt_h);
    cudaGetSymbolAddress((void**)&obs_h,  g_obs_h);
    cudaGetSymbolAddress((void**)&ego_h,  g_ego_h);
    cudaGetSymbolAddress((void**)&wm_h,   g_wm_h);
    cudaGetSymbolAddress((void**)&w_h,    g_w_h);
    cudaGetSymbolAddress((void**)&midx,   g_midx);
    cudaGetSymbolAddress((void**)&mcount, g_mcount);

    cudaFuncSetAttribute(gemm_mma<256,1>, cudaFuncAttributeMaxDynamicSharedMemorySize, GEMM_SMEM(256));
    cudaFuncSetAttribute(gemm_mma<256,2>, cudaFuncAttributeMaxDynamicSharedMemorySize, GEMM_SMEM(256));
    cudaFuncSetAttribute(gemm_mma<128,3>, cudaFuncAttributeMaxDynamicSharedMemorySize, GEMM_SMEM(128));
    cudaFuncSetAttribute(gemm_mma<256,4>, cudaFuncAttributeMaxDynamicSharedMemorySize, GEMM_SMEM(256));
    cudaFuncSetAttribute(gemm_mma<256,5>, cudaFuncAttributeMaxDynamicSharedMemorySize, GEMM_SMEM(256));
    cudaFuncSetAttribute(gemm_mma<256,6>, cudaFuncAttributeMaxDynamicSharedMemorySize, GEMM_SMEM(256));
    cudaFuncSetAttribute(gemm_mma<256,7>, cudaFuncAttributeMaxDynamicSharedMemorySize, GEMM_SMEM(256));
    cudaFuncSetAttribute(attn_mma,        cudaFuncAttributeMaxDynamicSharedMemorySize, ATT_SMEM);

    // ---- prep: fp32 -> fp16 ----
    PrepArgs pa;
    const float* srcs[12] = {obs, ego, wm, enc_w1, enc_w2, wq, wk, wv, wo, tr_w1, tr_w2, q_w1};
    __half* dsts[12] = {obs_h, ego_h, wm_h,
                        w_h + W_ENC1, w_h + W_ENC2, w_h + W_WQ, w_h + W_WK, w_h + W_WV,
                        w_h + W_WO, w_h + W_TR1, w_h + W_TR2, w_h + W_Q1};
    int n4s[12] = {BATCH*DIM/4, BATCH*16/4, MEM*DIM/4,
                   262144/4, 262144/4, 262144/4, 262144/4, 262144/4,
                   262144/4, 270336/4, 262144/4, 65536/4};
    for (int i = 0; i < 12; ++i) { pa.src[i] = srcs[i]; pa.dst[i] = dsts[i]; pa.n4[i] = n4s[i]; }
    prep_kernel<<<dim3(512, 12), 256>>>(pa);

    dim3 gBig(2, 64), gK(2, 8), gVt(4, 4), gQual(1, 64);

    // encoder
    gemm_mma<256,1><<<gBig, 256, GEMM_SMEM(256)>>>(obs_h, nullptr, w_h + W_ENC1, enc_b1,
        nullptr, nullptr, nullptr, h, nullptr, BATCH, 512, 16, 512);
    ln_kernel<<<BATCH/8, 256>>>(h, enc_g, enc_be, hn_h);
    gemm_mma<256,5><<<gBig, 256, GEMM_SMEM(256)>>>(hn_h, nullptr, w_h + W_ENC2, enc_b2,
        nullptr, nullptr, nullptr, enc, enc_h, BATCH, 512, 16, 512);
    // projections: Q (pre-scaled), K natural, V transposed (Vt = Wv * Wm^T)
    gemm_mma<256,6><<<gBig, 256, GEMM_SMEM(256)>>>(enc_h, nullptr, w_h + W_WQ, bq,
        nullptr, nullptr, nullptr, q_h, nullptr, BATCH, 512, 16, 512);
    gemm_mma<256,4><<<gK, 256, GEMM_SMEM(256)>>>(wm_h, nullptr, w_h + W_WK, bk,
        nullptr, nullptr, nullptr, k_h, nullptr, MEM, 512, 16, 512);
    gemm_mma<256,7><<<gVt, 256, GEMM_SMEM(256)>>>(w_h + W_WV, nullptr, wm_h, bv,
        nullptr, nullptr, nullptr, vt_h, nullptr, 512, 512, 16, MEMP);
    // attention
    attn_mma<<<dim3(HEADS, BATCH / 128), 256, ATT_SMEM>>>(q_h, k_h, vt_h, ctx_h);
    // out projection + fuse (F = enc fp32)
    gemm_mma<256,2><<<gBig, 256, GEMM_SMEM(256)>>>(ctx_h, nullptr, w_h + W_WO, bo,
        enc, nullptr, nullptr, fused_h, nullptr, BATCH, 512, 16, 512);
    // transition (K=528, ego in 17th K-chunk)
    gemm_mma<256,1><<<gBig, 256, GEMM_SMEM(256)>>>(fused_h, ego_h, w_h + W_TR1, tr_b1,
        nullptr, nullptr, nullptr, h, nullptr, BATCH, 528, 17, 512);
    ln_kernel<<<BATCH/8, 256>>>(h, tr_g, tr_be, hn_h);
    gemm_mma<256,5><<<gBig, 256, GEMM_SMEM(256)>>>(hn_h, nullptr, w_h + W_TR2, tr_b2,
        nullptr, nullptr, nullptr, next_state, ns_h, BATCH, 512, 16, 512);
    // quality head
    gemm_mma<128,3><<<gQual, 256, GEMM_SMEM(128)>>>(ns_h, nullptr, w_h + W_Q1, q_b1,
        nullptr, q_w2, q_b2, quality, nullptr, BATCH, 512, 16, 512);
    // memory bank update
    compact_kernel<<<1, 256>>>(quality, midx, mcount);
    memupd_kernel<<<MEM, 128>>>(wm, next_state, uidx, midx, mcount, outmem);
}

// round 12
// speedup vs baseline: 2.2999x; 1.0477x over previous
#include <cuda_runtime.h>
#include <cuda_fp16.h>
#include <math.h>
#include <stdint.h>

#define BATCH 8192
#define DIM   512
#define MEM   1000
#define MEMP  1024
#define HEADS 8
#define DH    64

// ==================== helpers ====================
__device__ __forceinline__ uint32_t smem_u32(const void* p) {
    uint32_t a;
    asm("{ .reg .u64 t; cvta.to.shared.u64 t, %1; cvt.u32.u64 %0, t; }" : "=r"(a) : "l"(p));
    return a;
}
__device__ __forceinline__ void mma_f16(float* c, uint32_t a0, uint32_t a1,
                                        uint32_t a2, uint32_t a3,
                                        uint32_t b0, uint32_t b1) {
    asm volatile(
        "mma.sync.aligned.m16n8k16.row.col.f32.f16.f16.f32 "
        "{%0,%1,%2,%3}, {%4,%5,%6,%7}, {%8,%9}, {%0,%1,%2,%3};"
        : "+f"(c[0]), "+f"(c[1]), "+f"(c[2]), "+f"(c[3])
        : "r"(a0), "r"(a1), "r"(a2), "r"(a3), "r"(b0), "r"(b1));
}
__device__ __forceinline__ void cp_async16(uint32_t dst, const void* src, int srcsize) {
    asm volatile("cp.async.cg.shared.global [%0], [%1], 16, %2;"
                 :: "r"(dst), "l"(src), "r"(srcsize));
}
#define CP_COMMIT() asm volatile("cp.async.commit_group;" ::: "memory")
#define CP_WAIT(N)  asm volatile("cp.async.wait_group %0;" :: "n"(N) : "memory")

// ==================== scratch ====================
__device__ float  g_h[BATCH*DIM];         // fp32 pre-LN
__device__ float  g_enc[BATCH*DIM];       // fp32 (F for fuse)
__device__ __half g_hn_h[BATCH*DIM];
__device__ __half g_enc_h[BATCH*DIM];
__device__ __half g_q_h[BATCH*DIM];       // pre-scaled by 0.125
__device__ __half g_ctx_h[BATCH*DIM];
__device__ __half g_fused_h[BATCH*DIM];
__device__ __half g_ns_h[BATCH*DIM];
__device__ __half g_k_h[MEMP*DIM];        // zero-init pads
__device__ __half g_vt_h[DIM*MEMP];       // V^T: [d][m]
__device__ __half g_obs_h[BATCH*DIM];
__device__ __half g_ego_h[BATCH*16];
__device__ __half g_wm_h[MEMP*DIM];       // zero-init pad rows 1000..1023
#define W_ENC1 0
#define W_ENC2 262144
#define W_WQ   524288
#define W_WK   786432
#define W_WV   1048576
#define W_WO   1310720
#define W_TR1  1572864
#define W_TR2  1843200
#define W_Q1   2105344
#define W_TOT  2170880
__device__ __half g_w_h[W_TOT];
__device__ int    g_midx[BATCH];
__device__ int    g_mcount;

// ==================== prep: fp32 -> fp16 ====================
struct PrepArgs {
    const float* src[12];
    __half*      dst[12];
    int          n4[12];
};
__global__ void __launch_bounds__(256) prep_kernel(PrepArgs p) {
    int seg = blockIdx.y;
    int n4 = p.n4[seg];
    const float4* s = (const float4*)p.src[seg];
    for (int i = blockIdx.x * 256 + threadIdx.x; i < n4; i += gridDim.x * 256) {
        float4 v = s[i];
        __half2 lo = __floats2half2_rn(v.x, v.y);
        __half2 hi = __floats2half2_rn(v.z, v.w);
        uint2 pk;
        pk.x = *(uint32_t*)&lo; pk.y = *(uint32_t*)&hi;
        *(uint2*)(p.dst[seg] + (size_t)i * 4) = pk;
    }
}

// ==================== fp16 mma GEMM, 256 thr, NT=128, 2 CTA/SM, 3-stage ======
// CTA tile 128 x 128, warp tile 64 x 32 (2 row-warps x 4 col-warps), BK=32.
// EPI: 1 relu->f32, 2 fuse->f16, 3 quality, 4 f16, 5 dual f32+f16,
//      6 f16 scaled 0.125, 7 f16 row-bias (V^T)
#define GSH 40                  // smem stride in halves (80B, conflict-free)
#define NT  128
#define NF  4
template<int EPI>
__global__ void __launch_bounds__(256, 2) gemm_mma(
    const __half* __restrict__ A, const __half* __restrict__ A2,
    const __half* __restrict__ W, const float* __restrict__ bias,
    const float* __restrict__ F, const float* __restrict__ w2,
    const float* __restrict__ b2, void* __restrict__ Cv, void* __restrict__ C2v,
    int Mrows, int Kw, int Ktiles, int ldc)
{
    constexpr int ASZ = 128 * GSH;          // halves
    constexpr int WSZ = NT * GSH;
    extern __shared__ __half smh[];
    __half* Ah = smh;                       // 3 x ASZ
    __half* Wh = smh + 3 * ASZ;             // 3 x WSZ
    const uint32_t sA = smem_u32(Ah);
    const uint32_t sW = smem_u32(Wh);

    const int tid = threadIdx.x;
    const int wid = tid >> 5, lane = tid & 31;
    const int g = lane >> 2, t = lane & 3;
    const int wm = wid & 1, wn = wid >> 1;
    const int row0 = blockIdx.y * 128;
    const int col0 = blockIdx.x * NT;

    float acc[4][NF][4];
    #pragma unroll
    for (int mf = 0; mf < 4; ++mf)
        #pragma unroll
        for (int nf = 0; nf < NF; ++nf)
            #pragma unroll
            for (int c = 0; c < 4; ++c) acc[mf][nf][c] = 0.f;

    auto load_chunk = [&](int ct, int buf) {
        const int kbase = ct * 32;
        constexpr int NLOAD = (512 + NT * 4) / 256;     // 4
        #pragma unroll
        for (int it = 0; it < NLOAD; ++it) {
            int vid = tid + it * 256;
            if (vid < 512) {
                int r = vid >> 2, q = vid & 3;
                int kel = kbase + q * 8;
                int grow = row0 + r;
                const __half* src = A;
                int sz = 0;
                if (grow < Mrows) {
                    if (kel < 512) { src = A + (size_t)grow * 512 + kel; sz = 16; }
                    else if (A2 != nullptr && kel < 528) {
                        src = A2 + (size_t)grow * 16 + (kel - 512); sz = 16;
                    }
                }
                cp_async16(sA + (buf * ASZ + r * GSH + q * 8) * 2, src, sz);
            } else {
                int vid2 = vid - 512;
                int r = vid2 >> 2, q = vid2 & 3;
                int kel = kbase + q * 8;
                const __half* src = W + (size_t)(col0 + r) * Kw + kel;
                int sz = (kel < Kw) ? 16 : 0;
                cp_async16(sW + (buf * WSZ + r * GSH + q * 8) * 2, src, sz);
            }
        }
        CP_COMMIT();
    };

    load_chunk(0, 0);
    if (Ktiles > 1) load_chunk(1, 1);

    for (int ct = 0; ct < Ktiles; ++ct) {
        const int buf = ct % 3;
        if (ct + 2 < Ktiles) load_chunk(ct + 2, (ct + 2) % 3);
        if (ct + 2 < Ktiles)      { CP_WAIT(2); }
        else if (ct + 1 < Ktiles) { CP_WAIT(1); }
        else                      { CP_WAIT(0); }
        __syncthreads();

        const __half* Ab = Ah + buf * ASZ + (wm * 64) * GSH;
        const __half* Wb = Wh + buf * WSZ + (wn * (NT / 4)) * GSH;
        #pragma unroll
        for (int ks = 0; ks < 2; ++ks) {
            const int k0 = ks * 16;
            uint32_t af[4][4];
            #pragma unroll
            for (int mf = 0; mf < 4; ++mf) {
                const __half* ar = Ab + (mf * 16) * GSH + k0;
                af[mf][0] = *(const uint32_t*)(ar + (g    ) * GSH + 2 * t    );
                af[mf][1] = *(const uint32_t*)(ar + (g + 8) * GSH + 2 * t    );
                af[mf][2] = *(const uint32_t*)(ar + (g    ) * GSH + 2 * t + 8);
                af[mf][3] = *(const uint32_t*)(ar + (g + 8) * GSH + 2 * t + 8);
            }
            #pragma unroll
            for (int nf = 0; nf < NF; ++nf) {
                const __half* wrp = Wb + (nf * 8 + g) * GSH + k0;
                uint32_t b0 = *(const uint32_t*)(wrp + 2 * t);
                uint32_t b1 = *(const uint32_t*)(wrp + 2 * t + 8);
                #pragma unroll
                for (int mf = 0; mf < 4; ++mf)
                    mma_f16(acc[mf][nf], af[mf][0], af[mf][1], af[mf][2], af[mf][3], b0, b1);
            }
        }
        __syncthreads();
    }

    if (EPI != 3) {
        #pragma unroll
        for (int mf = 0; mf < 4; ++mf) {
            #pragma unroll
            for (int r01 = 0; r01 < 2; ++r01) {
                int grow = row0 + wm * 64 + mf * 16 + g + r01 * 8;
                if (grow >= Mrows) continue;
                #pragma unroll
                for (int nf = 0; nf < NF; ++nf) {
                    int gcol = col0 + wn * (NT / 4) + nf * 8 + 2 * t;
                    float b0 = (EPI == 7) ? bias[grow] : bias[gcol];
                    float b1 = (EPI == 7) ? bias[grow] : bias[gcol + 1];
                    float v0 = acc[mf][nf][r01 * 2 + 0] + b0;
                    float v1 = acc[mf][nf][r01 * 2 + 1] + b1;
                    if (EPI == 1) { v0 = fmaxf(v0, 0.f); v1 = fmaxf(v1, 0.f); }
                    else if (EPI == 2) {
                        const float* fp = F + (size_t)grow * 512 + gcol;
                        v0 = 0.7f * fp[0] + 0.3f * v0;
                        v1 = 0.7f * fp[1] + 0.3f * v1;
                    } else if (EPI == 6) { v0 *= 0.125f; v1 *= 0.125f; }
                    size_t off = (size_t)grow * ldc + gcol;
                    if (EPI == 1) {
                        *(float2*)((float*)Cv + off) = make_float2(v0, v1);
                    } else if (EPI == 5) {
                        *(float2*)((float*)Cv + off) = make_float2(v0, v1);
                        __half2 hv = __floats2half2_rn(v0, v1);
                        *(__half2*)((__half*)C2v + off) = hv;
                    } else {
                        __half2 hv = __floats2half2_rn(v0, v1);
                        *(__half2*)((__half*)Cv + off) = hv;
                    }
                }
            }
        }
    } else {
        // quality head (NT=128, col0=0): sigmoid(b2 + sum relu(acc+b1)*w2)
        float* qpart = (float*)smh;
        __syncthreads();
        #pragma unroll
        for (int mf = 0; mf < 4; ++mf) {
            #pragma unroll
            for (int r01 = 0; r01 < 2; ++r01) {
                float s = 0.f;
                #pragma unroll
                for (int nf = 0; nf < NF; ++nf) {
                    int c = wn * (NT / 4) + nf * 8 + 2 * t;
                    float h0 = fmaxf(acc[mf][nf][r01 * 2 + 0] + bias[c], 0.f);
                    float h1 = fmaxf(acc[mf][nf][r01 * 2 + 1] + bias[c + 1], 0.f);
                    s += h0 * w2[c] + h1 * w2[c + 1];
                }
                int rl = wm * 64 + mf * 16 + r01 * 8 + g;
                qpart[rl * 17 + wn * 4 + t] = s;
            }
        }
        __syncthreads();
        if (tid < 128) {
            float s = b2[0];
            #pragma unroll
            for (int i = 0; i < 16; ++i) s += qpart[tid * 17 + i];
            ((float*)Cv)[row0 + tid] = 1.f / (1.f + expf(-s));
        }
    }
}
#define GEMM_SMEM ((3 * 128 * GSH + 3 * NT * GSH) * 2)

// ==================== fp16 mma flash attention (no-max softmax, 2 CTA/SM) ====
// Q pre-scaled by 0.125. Vt is V^T [d][m].
#define AS 72      // smem stride in halves
#define ATT_SMEM ((128*AS + 64*AS + 128*AS + 64*AS) * 2)
__global__ void __launch_bounds__(256, 2) attn_mma(
    const __half* __restrict__ Q, const __half* __restrict__ Kb,
    const __half* __restrict__ Vt, __half* __restrict__ ctx)
{
    extern __shared__ __half smh[];
    __half* Qs = smh;                 // 128 x AS
    __half* Ks = Qs + 128 * AS;       // 64 x AS
    __half* Ps = Ks + 64 * AS;        // 128 x AS
    __half* Vs = Ps + 128 * AS;       // 64 x AS  (rows = d, cols = m)
    const uint32_t sK = smem_u32(Ks);
    const uint32_t sV = smem_u32(Vs);

    const int h = blockIdx.x;
    const int b0 = blockIdx.y * 128;
    const int tid = threadIdx.x;
    const int wid = tid >> 5, lane = tid & 31;
    const int g = lane >> 2, t = lane & 3;
    const int qr = wid * 16;

    auto load_kv = [&](int m0) {
        #pragma unroll
        for (int it = 0; it < 4; ++it) {
            int vid = tid + it * 256;
            if (vid < 512) {
                int r = vid >> 3, q = vid & 7;      // K: row=mem, 64 halves
                int gm = m0 + r;
                int sz = (gm < MEM) ? 16 : 0;
                cp_async16(sK + (r * AS + q * 8) * 2,
                           Kb + (size_t)gm * 512 + h * 64 + q * 8, sz);
            } else {
                int vid2 = vid - 512;
                int r = vid2 >> 3, q = vid2 & 7;    // V: row=d, 64 m-halves
                cp_async16(sV + (r * AS + q * 8) * 2,
                           Vt + (size_t)(h * 64 + r) * MEMP + m0 + q * 8, 16);
            }
        }
        CP_COMMIT();
    };

    load_kv(0);

    #pragma unroll
    for (int it = 0; it < 4; ++it) {
        int vid = tid + it * 256;                   // 128 rows x 8 segs of 8 halves
        int r = vid >> 3, q = vid & 7;
        uint4 v = *(const uint4*)(Q + (size_t)(b0 + r) * 512 + h * 64 + q * 8);
        *(uint4*)(Qs + r * AS + q * 8) = v;
    }

    float oacc[8][4];
    float rsum[2] = {0.f, 0.f};
    #pragma unroll
    for (int nf = 0; nf < 8; ++nf)
        #pragma unroll
        for (int c = 0; c < 4; ++c) oacc[nf][c] = 0.f;

    for (int m0 = 0; m0 < MEMP; m0 += 64) {
        CP_WAIT(0);
        __syncthreads();

        // ---- S = Q K^T (d = 64 -> 4 k16 steps) ----
        float sacc[8][4];
        #pragma unroll
        for (int nf = 0; nf < 8; ++nf)
            #pragma unroll
            for (int c = 0; c < 4; ++c) sacc[nf][c] = 0.f;
        #pragma unroll
        for (int ks = 0; ks < 4; ++ks) {
            int k0 = ks * 16;
            uint32_t a0 = *(const uint32_t*)(Qs + (qr + g    ) * AS + k0 + 2 * t    );
            uint32_t a1 = *(const uint32_t*)(Qs + (qr + g + 8) * AS + k0 + 2 * t    );
            uint32_t a2 = *(const uint32_t*)(Qs + (qr + g    ) * AS + k0 + 2 * t + 8);
            uint32_t a3 = *(const uint32_t*)(Qs + (qr + g + 8) * AS + k0 + 2 * t + 8);
            #pragma unroll
            for (int nf = 0; nf < 8; ++nf) {
                uint32_t b0 = *(const uint32_t*)(Ks + (nf * 8 + g) * AS + k0 + 2 * t    );
                uint32_t b1 = *(const uint32_t*)(Ks + (nf * 8 + g) * AS + k0 + 2 * t + 8);
                mma_f16(sacc[nf], a0, a1, a2, a3, b0, b1);
            }
        }

        // ---- softmax numerator (shift-free: LN-bounded scores) ----
        #pragma unroll
        for (int r01 = 0; r01 < 2; ++r01) {
            float ps = 0.f;
            int prow = qr + g + r01 * 8;
            #pragma unroll
            for (int nf = 0; nf < 8; ++nf) {
                float p0 = 0.f, p1 = 0.f;
                if (m0 + nf * 8 + 2 * t     < MEM) p0 = __expf(sacc[nf][r01 * 2 + 0]);
                if (m0 + nf * 8 + 2 * t + 1 < MEM) p1 = __expf(sacc[nf][r01 * 2 + 1]);
                ps += p0 + p1;
                *(__half2*)(Ps + prow * AS + nf * 8 + 2 * t) = __floats2half2_rn(p0, p1);
            }
            ps += __shfl_xor_sync(0xffffffffu, ps, 1);
            ps += __shfl_xor_sync(0xffffffffu, ps, 2);
            rsum[r01] += ps;
        }
        __syncwarp();

        // ---- O += P V  (k = mem 64 -> 4 k16 steps; B from Vs[d][m]) ----
        #pragma unroll
        for (int ks = 0; ks < 4; ++ks) {
            int k0 = ks * 16;
            uint32_t a0 = *(const uint32_t*)(Ps + (qr + g    ) * AS + k0 + 2 * t    );
            uint32_t a1 = *(const uint32_t*)(Ps + (qr + g + 8) * AS + k0 + 2 * t    );
            uint32_t a2 = *(const uint32_t*)(Ps + (qr + g    ) * AS + k0 + 2 * t + 8);
            uint32_t a3 = *(const uint32_t*)(Ps + (qr + g + 8) * AS + k0 + 2 * t + 8);
            #pragma unroll
            for (int nf = 0; nf < 8; ++nf) {
                uint32_t b0 = *(const uint32_t*)(Vs + (nf * 8 + g) * AS + k0 + 2 * t    );
                uint32_t b1 = *(const uint32_t*)(Vs + (nf * 8 + g) * AS + k0 + 2 * t + 8);
                mma_f16(oacc[nf], a0, a1, a2, a3, b0, b1);
            }
        }
        __syncthreads();
        if (m0 + 64 < MEMP) load_kv(m0 + 64);
    }

    #pragma unroll
    for (int r01 = 0; r01 < 2; ++r01) {
        float inv = 1.f / rsum[r01];
        int grow = b0 + qr + g + r01 * 8;
        #pragma unroll
        for (int nf = 0; nf < 8; ++nf) {
            __half2 o = __floats2half2_rn(oacc[nf][r01 * 2 + 0] * inv,
                                          oacc[nf][r01 * 2 + 1] * inv);
            *(__half2*)(ctx + (size_t)grow * 512 + h * 64 + nf * 8 + 2 * t) = o;
        }
    }
}

// ==================== LayerNorm: warp-per-row, fp32 in, fp16 out =============
__global__ void __launch_bounds__(256) ln_kernel(
    const float* __restrict__ x, const float* __restrict__ g,
    const float* __restrict__ b, __half* __restrict__ y)
{
    const int warp = threadIdx.x >> 5, lane = threadIdx.x & 31;
    const int row = blockIdx.x * 8 + warp;
    const float* xr = x + (size_t)row * 512;

    float4 v[4];
    #pragma unroll
    for (int i = 0; i < 4; ++i)
        v[i] = *(const float4*)(xr + i * 128 + lane * 4);

    float s = 0.f;
    #pragma unroll
    for (int i = 0; i < 4; ++i) s += v[i].x + v[i].y + v[i].z + v[i].w;
    #pragma unroll
    for (int o = 16; o > 0; o >>= 1) s += __shfl_xor_sync(0xffffffffu, s, o);
    float mean = s * (1.f / 512.f);

    float ss = 0.f;
    #pragma unroll
    for (int i = 0; i < 4; ++i) {
        v[i].x -= mean; v[i].y -= mean; v[i].z -= mean; v[i].w -= mean;
        ss += v[i].x * v[i].x + v[i].y * v[i].y + v[i].z * v[i].z + v[i].w * v[i].w;
    }
    #pragma unroll
    for (int o = 16; o > 0; o >>= 1) ss += __shfl_xor_sync(0xffffffffu, ss, o);
    float inv = rsqrtf(ss * (1.f / 512.f) + 1e-5f);

    #pragma unroll
    for (int i = 0; i < 4; ++i) {
        float4 gg = *(const float4*)(g + i * 128 + lane * 4);
        float4 bb = *(const float4*)(b + i * 128 + lane * 4);
        __half2 lo = __floats2half2_rn(v[i].x * inv * gg.x + bb.x,
                                       v[i].y * inv * gg.y + bb.y);
        __half2 hi = __floats2half2_rn(v[i].z * inv * gg.z + bb.z,
                                       v[i].w * inv * gg.w + bb.w);
        uint2 pk; pk.x = *(uint32_t*)&lo; pk.y = *(uint32_t*)&hi;
        *(uint2*)(y + (size_t)row * 512 + i * 128 + lane * 4) = pk;
    }
}

// ==================== mask compaction + memory EMA ====================
__global__ void __launch_bounds__(256) compact_kernel(
    const float* __restrict__ quality, int* __restrict__ midx, int* __restrict__ mcount)
{
    const int tid = threadIdx.x;
    const int base = tid * 32;
    int cnt = 0;
    for (int i = 0; i < 32; ++i) cnt += (quality[base + i] > 0.7f) ? 1 : 0;
    __shared__ int sc[256];
    __shared__ int offs[256];
    sc[tid] = cnt;
    __syncthreads();
    if (tid == 0) {
        int run = 0;
        for (int t = 0; t < 256; ++t) { offs[t] = run; run += sc[t]; }
        *mcount = run;
    }
    __syncthreads();
    int o = offs[tid];
    for (int i = 0; i < 32; ++i)
        if (quality[base + i] > 0.7f) midx[o++] = base + i;
}

__global__ void __launch_bounds__(128) memupd_kernel(
    const float* __restrict__ wm, const float* __restrict__ ns,
    const int* __restrict__ upd, const int* __restrict__ midx,
    const int* __restrict__ mcount, float* __restrict__ outmem)
{
    const int m = blockIdx.x;
    const int d = threadIdx.x * 4;
    float4 v = *(const float4*)(wm + (size_t)m * 512 + d);
    const int cnt = *mcount;
    for (int jj = 0; jj < cnt; ++jj) {
        int i = midx[jj];
        if (upd[i] == m) {
            float4 s = *(const float4*)(ns + (size_t)i * 512 + d);
            v.x = 0.9f * v.x + 0.1f * s.x;
            v.y = 0.9f * v.y + 0.1f * s.y;
            v.z = 0.9f * v.z + 0.1f * s.z;
            v.w = 0.9f * v.w + 0.1f * s.w;
        }
    }
    *(float4*)(outmem + (size_t)m * 512 + d) = v;
}

// ==================== host launcher ====================
extern "C" void kernel_launch(void* const* d_in, const int* in_sizes, int n_in,
                              void* d_out, int out_size)
{
    const float* obs    = (const float*)d_in[0];
    const float* ego    = (const float*)d_in[1];
    const float* wm     = (const float*)d_in[2];
    const float* enc_w1 = (const float*)d_in[3];
    const float* enc_b1 = (const float*)d_in[4];
    const float* enc_g  = (const float*)d_in[5];
    const float* enc_be = (const float*)d_in[6];
    const float* enc_w2 = (const float*)d_in[7];
    const float* enc_b2 = (const float*)d_in[8];
    const float* wq     = (const float*)d_in[9];
    const float* bq     = (const float*)d_in[10];
    const float* wk     = (const float*)d_in[11];
    const float* bk     = (const float*)d_in[12];
    const float* wv     = (const float*)d_in[13];
    const float* bv     = (const float*)d_in[14];
    const float* wo     = (const float*)d_in[15];
    const float* bo     = (const float*)d_in[16];
    const float* tr_w1  = (const float*)d_in[17];
    const float* tr_b1  = (const float*)d_in[18];
    const float* tr_g   = (const float*)d_in[19];
    const float* tr_be  = (const float*)d_in[20];
    const float* tr_w2  = (const float*)d_in[21];
    const float* tr_b2  = (const float*)d_in[22];
    const float* q_w1   = (const float*)d_in[23];
    const float* q_b1   = (const float*)d_in[24];
    const float* q_w2   = (const float*)d_in[25];
    const float* q_b2   = (const float*)d_in[26];
    const int*   uidx   = (const int*)d_in[27];

    float* out        = (float*)d_out;
    float* next_state = out;
    float* quality    = out + (size_t)BATCH * DIM;
    float* outmem     = quality + BATCH;

    float *h, *enc;
    __half *hn_h, *enc_h, *q_h, *ctx_h, *fused_h, *ns_h, *k_h, *vt_h;
    __half *obs_h, *ego_h, *wm_h, *w_h;
    int *midx, *mcount;
    cudaGetSymbolAddress((void**)&h,      g_h);
    cudaGetSymbolAddress((void**)&enc,    g_enc);
    cudaGetSymbolAddress((void**)&hn_h,   g_hn_h);
    cudaGetSymbolAddress((void**)&enc_h,  g_enc_h);
    cudaGetSymbolAddress((void**)&q_h,    g_q_h);
    cudaGetSymbolAddress((void**)&ctx_h,  g_ctx_h);
    cudaGetSymbolAddress((void**)&fused_h,g_fused_h);
    cudaGetSymbolAddress((void**)&ns_h,   g_ns_h);
    cudaGetSymbolAddress((void**)&k_h,    g_k_h);
    cudaGetSymbolAddress((void**)&vt_h,   g_vt_h);
    cudaGetSymbolAddress((void**)&obs_h,  g_obs_h);
    cudaGetSymbolAddress((void**)&ego_h,  g_ego_h);
    cudaGetSymbolAddress((void**)&wm_h,   g_wm_h);
    cudaGetSymbolAddress((void**)&w_h,    g_w_h);
    cudaGetSymbolAddress((void**)&midx,   g_midx);
    cudaGetSymbolAddress((void**)&mcount, g_mcount);

    cudaFuncSetAttribute(gemm_mma<1>, cudaFuncAttributeMaxDynamicSharedMemorySize, GEMM_SMEM);
    cudaFuncSetAttribute(gemm_mma<2>, cudaFuncAttributeMaxDynamicSharedMemorySize, GEMM_SMEM);
    cudaFuncSetAttribute(gemm_mma<3>, cudaFuncAttributeMaxDynamicSharedMemorySize, GEMM_SMEM);
    cudaFuncSetAttribute(gemm_mma<4>, cudaFuncAttributeMaxDynamicSharedMemorySize, GEMM_SMEM);
    cudaFuncSetAttribute(gemm_mma<5>, cudaFuncAttributeMaxDynamicSharedMemorySize, GEMM_SMEM);
    cudaFuncSetAttribute(gemm_mma<6>, cudaFuncAttributeMaxDynamicSharedMemorySize, GEMM_SMEM);
    cudaFuncSetAttribute(gemm_mma<7>, cudaFuncAttributeMaxDynamicSharedMemorySize, GEMM_SMEM);
    cudaFuncSetAttribute(attn_mma,    cudaFuncAttributeMaxDynamicSharedMemorySize, ATT_SMEM);

    // ---- prep: fp32 -> fp16 ----
    PrepArgs pa;
    const float* srcs[12] = {obs, ego, wm, enc_w1, enc_w2, wq, wk, wv, wo, tr_w1, tr_w2, q_w1};
    __half* dsts[12] = {obs_h, ego_h, wm_h,
                        w_h + W_ENC1, w_h + W_ENC2, w_h + W_WQ, w_h + W_WK, w_h + W_WV,
                        w_h + W_WO, w_h + W_TR1, w_h + W_TR2, w_h + W_Q1};
    int n4s[12] = {BATCH*DIM/4, BATCH*16/4, MEM*DIM/4,
                   262144/4, 262144/4, 262144/4, 262144/4, 262144/4,
                   262144/4, 270336/4, 262144/4, 65536/4};
    for (int i = 0; i < 12; ++i) { pa.src[i] = srcs[i]; pa.dst[i] = dsts[i]; pa.n4[i] = n4s[i]; }
    prep_kernel<<<dim3(512, 12), 256>>>(pa);

    dim3 gBig(4, 64), gK(4, 8), gVt(8, 4), gQual(1, 64);

    // encoder
    gemm_mma<1><<<gBig, 256, GEMM_SMEM>>>(obs_h, nullptr, w_h + W_ENC1, enc_b1,
        nullptr, nullptr, nullptr, h, nullptr, BATCH, 512, 16, 512);
    ln_kernel<<<BATCH/8, 256>>>(h, enc_g, enc_be, hn_h);
    gemm_mma<5><<<gBig, 256, GEMM_SMEM>>>(hn_h, nullptr, w_h + W_ENC2, enc_b2,
        nullptr, nullptr, nullptr, enc, enc_h, BATCH, 512, 16, 512);
    // projections: Q (pre-scaled), K natural, V transposed (Vt = Wv * Wm^T)
    gemm_mma<6><<<gBig, 256, GEMM_SMEM>>>(enc_h, nullptr, w_h + W_WQ, bq,
        nullptr, nullptr, nullptr, q_h, nullptr, BATCH, 512, 16, 512);
    gemm_mma<4><<<gK, 256, GEMM_SMEM>>>(wm_h, nullptr, w_h + W_WK, bk,
        nullptr, nullptr, nullptr, k_h, nullptr, MEM, 512, 16, 512);
    gemm_mma<7><<<gVt, 256, GEMM_SMEM>>>(w_h + W_WV, nullptr, wm_h, bv,
        nullptr, nullptr, nullptr, vt_h, nullptr, 512, 512, 16, MEMP);
    // attention
    attn_mma<<<dim3(HEADS, BATCH / 128), 256, ATT_SMEM>>>(q_h, k_h, vt_h, ctx_h);
    // out projection + fuse (F = enc fp32)
    gemm_mma<2><<<gBig, 256, GEMM_SMEM>>>(ctx_h, nullptr, w_h + W_WO, bo,
        enc, nullptr, nullptr, fused_h, nullptr, BATCH, 512, 16, 512);
    // transition (K=528, ego in 17th K-chunk)
    gemm_mma<1><<<gBig, 256, GEMM_SMEM>>>(fused_h, ego_h, w_h + W_TR1, tr_b1,
        nullptr, nullptr, nullptr, h, nullptr, BATCH, 528, 17, 512);
    ln_kernel<<<BATCH/8, 256>>>(h, tr_g, tr_be, hn_h);
    gemm_mma<5><<<gBig, 256, GEMM_SMEM>>>(hn_h, nullptr, w_h + W_TR2, tr_b2,
        nullptr, nullptr, nullptr, next_state, ns_h, BATCH, 512, 16, 512);
    // quality head
    gemm_mma<3><<<gQual, 256, GEMM_SMEM>>>(ns_h, nullptr, w_h + W_Q1, q_b1,
        nullptr, q_w2, q_b2, quality, nullptr, BATCH, 512, 16, 512);
    // memory bank update
    compact_kernel<<<1, 256>>>(quality, midx, mcount);
    memupd_kernel<<<MEM, 128>>>(wm, next_state, uidx, midx, mcount, outmem);
}

// round 13
// speedup vs baseline: 2.5814x; 1.1224x over previous
#include <cuda_runtime.h>
#include <cuda_fp16.h>
#include <math.h>
#include <stdint.h>

#define BATCH 8192
#define DIM   512
#define MEM   1000
#define MEMP  1024
#define HEADS 8
#define DH    64

// ==================== helpers ====================
__device__ __forceinline__ uint32_t smem_u32(const void* p) {
    uint32_t a;
    asm("{ .reg .u64 t; cvta.to.shared.u64 t, %1; cvt.u32.u64 %0, t; }" : "=r"(a) : "l"(p));
    return a;
}
__device__ __forceinline__ void mma_f16(float* c, uint32_t a0, uint32_t a1,
                                        uint32_t a2, uint32_t a3,
                                        uint32_t b0, uint32_t b1) {
    asm volatile(
        "mma.sync.aligned.m16n8k16.row.col.f32.f16.f16.f32 "
        "{%0,%1,%2,%3}, {%4,%5,%6,%7}, {%8,%9}, {%0,%1,%2,%3};"
        : "+f"(c[0]), "+f"(c[1]), "+f"(c[2]), "+f"(c[3])
        : "r"(a0), "r"(a1), "r"(a2), "r"(a3), "r"(b0), "r"(b1));
}
__device__ __forceinline__ void cp_async16(uint32_t dst, const void* src, int srcsize) {
    asm volatile("cp.async.cg.shared.global [%0], [%1], 16, %2;"
                 :: "r"(dst), "l"(src), "r"(srcsize));
}
#define CP_COMMIT() asm volatile("cp.async.commit_group;" ::: "memory")
#define CP_WAIT(N)  asm volatile("cp.async.wait_group %0;" :: "n"(N) : "memory")

// ==================== scratch ====================
__device__ float  g_h[BATCH*DIM];         // fp32 pre-LN
__device__ float  g_enc[BATCH*DIM];       // fp32 (F for fuse)
__device__ __half g_hn_h[BATCH*DIM];
__device__ __half g_enc_h[BATCH*DIM];
__device__ __half g_q_h[BATCH*DIM];       // pre-scaled by 0.125
__device__ __half g_ctx_h[BATCH*DIM];
__device__ __half g_fused_h[BATCH*DIM];
__device__ __half g_ns_h[BATCH*DIM];
__device__ __half g_k_h[MEMP*DIM];        // zero-init pads
__device__ __half g_vt_h[DIM*MEMP];       // V^T: [d][m]
__device__ __half g_obs_h[BATCH*DIM];
__device__ __half g_ego_h[BATCH*16];
__device__ __half g_wm_h[MEMP*DIM];       // zero-init pad rows 1000..1023
#define W_ENC1 0
#define W_ENC2 262144
#define W_WQ   524288
#define W_WK   786432
#define W_WV   1048576
#define W_WO   1310720
#define W_TR1  1572864
#define W_TR2  1843200
#define W_Q1   2105344
#define W_TOT  2170880
__device__ __half g_w_h[W_TOT];
__device__ int    g_midx[BATCH];
__device__ int    g_mcount;

// ==================== prep: fp32 -> fp16 ====================
struct PrepArgs {
    const float* src[12];
    __half*      dst[12];
    int          n4[12];
};
__global__ void __launch_bounds__(256) prep_kernel(PrepArgs p) {
    int seg = blockIdx.y;
    int n4 = p.n4[seg];
    const float4* s = (const float4*)p.src[seg];
    for (int i = blockIdx.x * 256 + threadIdx.x; i < n4; i += gridDim.x * 256) {
        float4 v = s[i];
        __half2 lo = __floats2half2_rn(v.x, v.y);
        __half2 hi = __floats2half2_rn(v.z, v.w);
        uint2 pk;
        pk.x = *(uint32_t*)&lo; pk.y = *(uint32_t*)&hi;
        *(uint2*)(p.dst[seg] + (size_t)i * 4) = pk;
    }
}

// ==================== fp16 mma GEMM, 256 thr, NT=128, BK=64, 2 CTA/SM ========
// CTA tile 128 x 128, warp tile 64 x 32 (2 row-warps x 4 col-warps), 3-stage.
// EPI: 1 relu->f32, 2 fuse->f16, 3 quality, 4 f16, 5 dual f32+f16,
//      6 f16 scaled 0.125, 7 f16 row-bias (V^T)
#define GSH 72                  // smem stride in halves (BK=64 + 8 pad; 4g+t banks)
#define NT  128
#define NF  4
template<int EPI>
__global__ void __launch_bounds__(256, 2) gemm_mma(
    const __half* __restrict__ A, const __half* __restrict__ A2,
    const __half* __restrict__ W, const float* __restrict__ bias,
    const float* __restrict__ F, const float* __restrict__ w2,
    const float* __restrict__ b2, void* __restrict__ Cv, void* __restrict__ C2v,
    int Mrows, int Kw, int Ktiles, int ldc)
{
    constexpr int ASZ = 128 * GSH;          // halves
    constexpr int WSZ = NT * GSH;
    extern __shared__ __half smh[];
    __half* Ah = smh;                       // 3 x ASZ
    __half* Wh = smh + 3 * ASZ;             // 3 x WSZ
    const uint32_t sA = smem_u32(Ah);
    const uint32_t sW = smem_u32(Wh);

    const int tid = threadIdx.x;
    const int wid = tid >> 5, lane = tid & 31;
    const int g = lane >> 2, t = lane & 3;
    const int wm = wid & 1, wn = wid >> 1;
    const int row0 = blockIdx.y * 128;
    const int col0 = blockIdx.x * NT;

    float acc[4][NF][4];
    #pragma unroll
    for (int mf = 0; mf < 4; ++mf)
        #pragma unroll
        for (int nf = 0; nf < NF; ++nf)
            #pragma unroll
            for (int c = 0; c < 4; ++c) acc[mf][nf][c] = 0.f;

    auto load_chunk = [&](int ct, int buf) {
        const int kbase = ct * 64;
        // A: 128 rows x 8 segs; W: 128 rows x 8 segs -> 2048 copies, 8/thread
        #pragma unroll
        for (int it = 0; it < 8; ++it) {
            int vid = tid + it * 256;
            if (vid < 1024) {
                int r = vid >> 3, q = vid & 7;
                int kel = kbase + q * 8;
                int grow = row0 + r;
                const __half* src = A;
                int sz = 0;
                if (grow < Mrows) {
                    if (kel < 512) { src = A + (size_t)grow * 512 + kel; sz = 16; }
                    else if (A2 != nullptr && kel < 528) {
                        src = A2 + (size_t)grow * 16 + (kel - 512); sz = 16;
                    }
                }
                cp_async16(sA + (buf * ASZ + r * GSH + q * 8) * 2, src, sz);
            } else {
                int vid2 = vid - 1024;
                int r = vid2 >> 3, q = vid2 & 7;
                int kel = kbase + q * 8;
                const __half* src = W + (size_t)(col0 + r) * Kw + kel;
                int sz = (kel < Kw) ? 16 : 0;
                cp_async16(sW + (buf * WSZ + r * GSH + q * 8) * 2, src, sz);
            }
        }
        CP_COMMIT();
    };

    load_chunk(0, 0);
    if (Ktiles > 1) load_chunk(1, 1);

    for (int ct = 0; ct < Ktiles; ++ct) {
        const int buf = ct % 3;
        if (ct + 2 < Ktiles) load_chunk(ct + 2, (ct + 2) % 3);
        if (ct + 2 < Ktiles)      { CP_WAIT(2); }
        else if (ct + 1 < Ktiles) { CP_WAIT(1); }
        else                      { CP_WAIT(0); }
        __syncthreads();

        const __half* Ab = Ah + buf * ASZ + (wm * 64) * GSH;
        const __half* Wb = Wh + buf * WSZ + (wn * (NT / 4)) * GSH;
        #pragma unroll
        for (int ks = 0; ks < 4; ++ks) {
            const int k0 = ks * 16;
            uint32_t af[4][4];
            #pragma unroll
            for (int mf = 0; mf < 4; ++mf) {
                const __half* ar = Ab + (mf * 16) * GSH + k0;
                af[mf][0] = *(const uint32_t*)(ar + (g    ) * GSH + 2 * t    );
                af[mf][1] = *(const uint32_t*)(ar + (g + 8) * GSH + 2 * t    );
                af[mf][2] = *(const uint32_t*)(ar + (g    ) * GSH + 2 * t + 8);
                af[mf][3] = *(const uint32_t*)(ar + (g + 8) * GSH + 2 * t + 8);
            }
            #pragma unroll
            for (int nf = 0; nf < NF; ++nf) {
                const __half* wrp = Wb + (nf * 8 + g) * GSH + k0;
                uint32_t b0 = *(const uint32_t*)(wrp + 2 * t);
                uint32_t b1 = *(const uint32_t*)(wrp + 2 * t + 8);
                #pragma unroll
                for (int mf = 0; mf < 4; ++mf)
                    mma_f16(acc[mf][nf], af[mf][0], af[mf][1], af[mf][2], af[mf][3], b0, b1);
            }
        }
        __syncthreads();
    }

    if (EPI != 3) {
        #pragma unroll
        for (int mf = 0; mf < 4; ++mf) {
            #pragma unroll
            for (int r01 = 0; r01 < 2; ++r01) {
                int grow = row0 + wm * 64 + mf * 16 + g + r01 * 8;
                if (grow >= Mrows) continue;
                #pragma unroll
                for (int nf = 0; nf < NF; ++nf) {
                    int gcol = col0 + wn * (NT / 4) + nf * 8 + 2 * t;
                    float b0 = (EPI == 7) ? bias[grow] : bias[gcol];
                    float b1 = (EPI == 7) ? bias[grow] : bias[gcol + 1];
                    float v0 = acc[mf][nf][r01 * 2 + 0] + b0;
                    float v1 = acc[mf][nf][r01 * 2 + 1] + b1;
                    if (EPI == 1) { v0 = fmaxf(v0, 0.f); v1 = fmaxf(v1, 0.f); }
                    else if (EPI == 2) {
                        const float* fp = F + (size_t)grow * 512 + gcol;
                        v0 = 0.7f * fp[0] + 0.3f * v0;
                        v1 = 0.7f * fp[1] + 0.3f * v1;
                    } else if (EPI == 6) { v0 *= 0.125f; v1 *= 0.125f; }
                    size_t off = (size_t)grow * ldc + gcol;
                    if (EPI == 1) {
                        *(float2*)((float*)Cv + off) = make_float2(v0, v1);
                    } else if (EPI == 5) {
                        *(float2*)((float*)Cv + off) = make_float2(v0, v1);
                        __half2 hv = __floats2half2_rn(v0, v1);
                        *(__half2*)((__half*)C2v + off) = hv;
                    } else {
                        __half2 hv = __floats2half2_rn(v0, v1);
                        *(__half2*)((__half*)Cv + off) = hv;
                    }
                }
            }
        }
    } else {
        // quality head (NT=128, col0=0): sigmoid(b2 + sum relu(acc+b1)*w2)
        float* qpart = (float*)smh;
        __syncthreads();
        #pragma unroll
        for (int mf = 0; mf < 4; ++mf) {
            #pragma unroll
            for (int r01 = 0; r01 < 2; ++r01) {
                float s = 0.f;
                #pragma unroll
                for (int nf = 0; nf < NF; ++nf) {
                    int c = wn * (NT / 4) + nf * 8 + 2 * t;
                    float h0 = fmaxf(acc[mf][nf][r01 * 2 + 0] + bias[c], 0.f);
                    float h1 = fmaxf(acc[mf][nf][r01 * 2 + 1] + bias[c + 1], 0.f);
                    s += h0 * w2[c] + h1 * w2[c + 1];
                }
                int rl = wm * 64 + mf * 16 + r01 * 8 + g;
                qpart[rl * 17 + wn * 4 + t] = s;
            }
        }
        __syncthreads();
        if (tid < 128) {
            float s = b2[0];
            #pragma unroll
            for (int i = 0; i < 16; ++i) s += qpart[tid * 17 + i];
            ((float*)Cv)[row0 + tid] = 1.f / (1.f + expf(-s));
        }
    }
}
#define GEMM_SMEM ((3 * 128 * GSH + 3 * NT * GSH) * 2)

// ==================== fp16 mma flash attention (no-max softmax, 2 CTA/SM) ====
// Q pre-scaled by 0.125. Vt is V^T [d][m].
#define AS 72
#define ATT_SMEM ((128*AS + 64*AS + 128*AS + 64*AS) * 2)
__global__ void __launch_bounds__(256, 2) attn_mma(
    const __half* __restrict__ Q, const __half* __restrict__ Kb,
    const __half* __restrict__ Vt, __half* __restrict__ ctx)
{
    extern __shared__ __half smh[];
    __half* Qs = smh;
    __half* Ks = Qs + 128 * AS;
    __half* Ps = Ks + 64 * AS;
    __half* Vs = Ps + 128 * AS;
    const uint32_t sK = smem_u32(Ks);
    const uint32_t sV = smem_u32(Vs);

    const int h = blockIdx.x;
    const int b0 = blockIdx.y * 128;
    const int tid = threadIdx.x;
    const int wid = tid >> 5, lane = tid & 31;
    const int g = lane >> 2, t = lane & 3;
    const int qr = wid * 16;

    auto load_kv = [&](int m0) {
        #pragma unroll
        for (int it = 0; it < 4; ++it) {
            int vid = tid + it * 256;
            if (vid < 512) {
                int r = vid >> 3, q = vid & 7;
                int gm = m0 + r;
                int sz = (gm < MEM) ? 16 : 0;
                cp_async16(sK + (r * AS + q * 8) * 2,
                           Kb + (size_t)gm * 512 + h * 64 + q * 8, sz);
            } else {
                int vid2 = vid - 512;
                int r = vid2 >> 3, q = vid2 & 7;
                cp_async16(sV + (r * AS + q * 8) * 2,
                           Vt + (size_t)(h * 64 + r) * MEMP + m0 + q * 8, 16);
            }
        }
        CP_COMMIT();
    };

    load_kv(0);

    #pragma unroll
    for (int it = 0; it < 4; ++it) {
        int vid = tid + it * 256;
        int r = vid >> 3, q = vid & 7;
        uint4 v = *(const uint4*)(Q + (size_t)(b0 + r) * 512 + h * 64 + q * 8);
        *(uint4*)(Qs + r * AS + q * 8) = v;
    }

    float oacc[8][4];
    float rsum[2] = {0.f, 0.f};
    #pragma unroll
    for (int nf = 0; nf < 8; ++nf)
        #pragma unroll
        for (int c = 0; c < 4; ++c) oacc[nf][c] = 0.f;

    for (int m0 = 0; m0 < MEMP; m0 += 64) {
        CP_WAIT(0);
        __syncthreads();

        float sacc[8][4];
        #pragma unroll
        for (int nf = 0; nf < 8; ++nf)
            #pragma unroll
            for (int c = 0; c < 4; ++c) sacc[nf][c] = 0.f;
        #pragma unroll
        for (int ks = 0; ks < 4; ++ks) {
            int k0 = ks * 16;
            uint32_t a0 = *(const uint32_t*)(Qs + (qr + g    ) * AS + k0 + 2 * t    );
            uint32_t a1 = *(const uint32_t*)(Qs + (qr + g + 8) * AS + k0 + 2 * t    );
            uint32_t a2 = *(const uint32_t*)(Qs + (qr + g    ) * AS + k0 + 2 * t + 8);
            uint32_t a3 = *(const uint32_t*)(Qs + (qr + g + 8) * AS + k0 + 2 * t + 8);
            #pragma unroll
            for (int nf = 0; nf < 8; ++nf) {
                uint32_t b0 = *(const uint32_t*)(Ks + (nf * 8 + g) * AS + k0 + 2 * t    );
                uint32_t b1 = *(const uint32_t*)(Ks + (nf * 8 + g) * AS + k0 + 2 * t + 8);
                mma_f16(sacc[nf], a0, a1, a2, a3, b0, b1);
            }
        }

        #pragma unroll
        for (int r01 = 0; r01 < 2; ++r01) {
            float ps = 0.f;
            int prow = qr + g + r01 * 8;
            #pragma unroll
            for (int nf = 0; nf < 8; ++nf) {
                float p0 = 0.f, p1 = 0.f;
                if (m0 + nf * 8 + 2 * t     < MEM) p0 = __expf(sacc[nf][r01 * 2 + 0]);
                if (m0 + nf * 8 + 2 * t + 1 < MEM) p1 = __expf(sacc[nf][r01 * 2 + 1]);
                ps += p0 + p1;
                *(__half2*)(Ps + prow * AS + nf * 8 + 2 * t) = __floats2half2_rn(p0, p1);
            }
            ps += __shfl_xor_sync(0xffffffffu, ps, 1);
            ps += __shfl_xor_sync(0xffffffffu, ps, 2);
            rsum[r01] += ps;
        }
        __syncwarp();

        #pragma unroll
        for (int ks = 0; ks < 4; ++ks) {
            int k0 = ks * 16;
            uint32_t a0 = *(const uint32_t*)(Ps + (qr + g    ) * AS + k0 + 2 * t    );
            uint32_t a1 = *(const uint32_t*)(Ps + (qr + g + 8) * AS + k0 + 2 * t    );
            uint32_t a2 = *(const uint32_t*)(Ps + (qr + g    ) * AS + k0 + 2 * t + 8);
            uint32_t a3 = *(const uint32_t*)(Ps + (qr + g + 8) * AS + k0 + 2 * t + 8);
            #pragma unroll
            for (int nf = 0; nf < 8; ++nf) {
                uint32_t b0 = *(const uint32_t*)(Vs + (nf * 8 + g) * AS + k0 + 2 * t    );
                uint32_t b1 = *(const uint32_t*)(Vs + (nf * 8 + g) * AS + k0 + 2 * t + 8);
                mma_f16(oacc[nf], a0, a1, a2, a3, b0, b1);
            }
        }
        __syncthreads();
        if (m0 + 64 < MEMP) load_kv(m0 + 64);
    }

    #pragma unroll
    for (int r01 = 0; r01 < 2; ++r01) {
        float inv = 1.f / rsum[r01];
        int grow = b0 + qr + g + r01 * 8;
        #pragma unroll
        for (int nf = 0; nf < 8; ++nf) {
            __half2 o = __floats2half2_rn(oacc[nf][r01 * 2 + 0] * inv,
                                          oacc[nf][r01 * 2 + 1] * inv);
            *(__half2*)(ctx + (size_t)grow * 512 + h * 64 + nf * 8 + 2 * t) = o;
        }
    }
}

// ==================== LayerNorm: warp-per-row, fp32 in, fp16 out =============
__global__ void __launch_bounds__(256) ln_kernel(
    const float* __restrict__ x, const float* __restrict__ g,
    const float* __restrict__ b, __half* __restrict__ y)
{
    const int warp = threadIdx.x >> 5, lane = threadIdx.x & 31;
    const int row = blockIdx.x * 8 + warp;
    const float* xr = x + (size_t)row * 512;

    float4 v[4];
    #pragma unroll
    for (int i = 0; i < 4; ++i)
        v[i] = *(const float4*)(xr + i * 128 + lane * 4);

    float s = 0.f;
    #pragma unroll
    for (int i = 0; i < 4; ++i) s += v[i].x + v[i].y + v[i].z + v[i].w;
    #pragma unroll
    for (int o = 16; o > 0; o >>= 1) s += __shfl_xor_sync(0xffffffffu, s, o);
    float mean = s * (1.f / 512.f);

    float ss = 0.f;
    #pragma unroll
    for (int i = 0; i < 4; ++i) {
        v[i].x -= mean; v[i].y -= mean; v[i].z -= mean; v[i].w -= mean;
        ss += v[i].x * v[i].x + v[i].y * v[i].y + v[i].z * v[i].z + v[i].w * v[i].w;
    }
    #pragma unroll
    for (int o = 16; o > 0; o >>= 1) ss += __shfl_xor_sync(0xffffffffu, ss, o);
    float inv = rsqrtf(ss * (1.f / 512.f) + 1e-5f);

    #pragma unroll
    for (int i = 0; i < 4; ++i) {
        float4 gg = *(const float4*)(g + i * 128 + lane * 4);
        float4 bb = *(const float4*)(b + i * 128 + lane * 4);
        __half2 lo = __floats2half2_rn(v[i].x * inv * gg.x + bb.x,
                                       v[i].y * inv * gg.y + bb.y);
        __half2 hi = __floats2half2_rn(v[i].z * inv * gg.z + bb.z,
                                       v[i].w * inv * gg.w + bb.w);
        uint2 pk; pk.x = *(uint32_t*)&lo; pk.y = *(uint32_t*)&hi;
        *(uint2*)(y + (size_t)row * 512 + i * 128 + lane * 4) = pk;
    }
}

// ==================== mask compaction + memory EMA ====================
__global__ void __launch_bounds__(256) compact_kernel(
    const float* __restrict__ quality, int* __restrict__ midx, int* __restrict__ mcount)
{
    const int tid = threadIdx.x;
    const int base = tid * 32;
    int cnt = 0;
    for (int i = 0; i < 32; ++i) cnt += (quality[base + i] > 0.7f) ? 1 : 0;
    __shared__ int sc[256];
    __shared__ int offs[256];
    sc[tid] = cnt;
    __syncthreads();
    if (tid == 0) {
        int run = 0;
        for (int t = 0; t < 256; ++t) { offs[t] = run; run += sc[t]; }
        *mcount = run;
    }
    __syncthreads();
    int o = offs[tid];
    for (int i = 0; i < 32; ++i)
        if (quality[base + i] > 0.7f) midx[o++] = base + i;
}

__global__ void __launch_bounds__(128) memupd_kernel(
    const float* __restrict__ wm, const float* __restrict__ ns,
    const int* __restrict__ upd, const int* __restrict__ midx,
    const int* __restrict__ mcount, float* __restrict__ outmem)
{
    const int m = blockIdx.x;
    const int d = threadIdx.x * 4;
    float4 v = *(const float4*)(wm + (size_t)m * 512 + d);
    const int cnt = *mcount;
    for (int jj = 0; jj < cnt; ++jj) {
        int i = midx[jj];
        if (upd[i] == m) {
            float4 s = *(const float4*)(ns + (size_t)i * 512 + d);
            v.x = 0.9f * v.x + 0.1f * s.x;
            v.y = 0.9f * v.y + 0.1f * s.y;
            v.z = 0.9f * v.z + 0.1f * s.z;
            v.w = 0.9f * v.w + 0.1f * s.w;
        }
    }
    *(float4*)(outmem + (size_t)m * 512 + d) = v;
}

// ==================== host launcher ====================
extern "C" void kernel_launch(void* const* d_in, const int* in_sizes, int n_in,
                              void* d_out, int out_size)
{
    const float* obs    = (const float*)d_in[0];
    const float* ego    = (const float*)d_in[1];
    const float* wm     = (const float*)d_in[2];
    const float* enc_w1 = (const float*)d_in[3];
    const float* enc_b1 = (const float*)d_in[4];
    const float* enc_g  = (const float*)d_in[5];
    const float* enc_be = (const float*)d_in[6];
    const float* enc_w2 = (const float*)d_in[7];
    const float* enc_b2 = (const float*)d_in[8];
    const float* wq     = (const float*)d_in[9];
    const float* bq     = (const float*)d_in[10];
    const float* wk     = (const float*)d_in[11];
    const float* bk     = (const float*)d_in[12];
    const float* wv     = (const float*)d_in[13];
    const float* bv     = (const float*)d_in[14];
    const float* wo     = (const float*)d_in[15];
    const float* bo     = (const float*)d_in[16];
    const float* tr_w1  = (const float*)d_in[17];
    const float* tr_b1  = (const float*)d_in[18];
    const float* tr_g   = (const float*)d_in[19];
    const float* tr_be  = (const float*)d_in[20];
    const float* tr_w2  = (const float*)d_in[21];
    const float* tr_b2  = (const float*)d_in[22];
    const float* q_w1   = (const float*)d_in[23];
    const float* q_b1   = (const float*)d_in[24];
    const float* q_w2   = (const float*)d_in[25];
    const float* q_b2   = (const float*)d_in[26];
    const int*   uidx   = (const int*)d_in[27];

    float* out        = (float*)d_out;
    float* next_state = out;
    float* quality    = out + (size_t)BATCH * DIM;
    float* outmem     = quality + BATCH;

    float *h, *enc;
    __half *hn_h, *enc_h, *q_h, *ctx_h, *fused_h, *ns_h, *k_h, *vt_h;
    __half *obs_h, *ego_h, *wm_h, *w_h;
    int *midx, *mcount;
    cudaGetSymbolAddress((void**)&h,      g_h);
    cudaGetSymbolAddress((void**)&enc,    g_enc);
    cudaGetSymbolAddress((void**)&hn_h,   g_hn_h);
    cudaGetSymbolAddress((void**)&enc_h,  g_enc_h);
    cudaGetSymbolAddress((void**)&q_h,    g_q_h);
    cudaGetSymbolAddress((void**)&ctx_h,  g_ctx_h);
    cudaGetSymbolAddress((void**)&fused_h,g_fused_h);
    cudaGetSymbolAddress((void**)&ns_h,   g_ns_h);
    cudaGetSymbolAddress((void**)&k_h,    g_k_h);
    cudaGetSymbolAddress((void**)&vt_h,   g_vt_h);
    cudaGetSymbolAddress((void**)&obs_h,  g_obs_h);
    cudaGetSymbolAddress((void**)&ego_h,  g_ego_h);
    cudaGetSymbolAddress((void**)&wm_h,   g_wm_h);
    cudaGetSymbolAddress((void**)&w_h,    g_w_h);
    cudaGetSymbolAddress((void**)&midx,   g_midx);
    cudaGetSymbolAddress((void**)&mcount, g_mcount);

    cudaFuncSetAttribute(gemm_mma<1>, cudaFuncAttributeMaxDynamicSharedMemorySize, GEMM_SMEM);
    cudaFuncSetAttribute(gemm_mma<2>, cudaFuncAttributeMaxDynamicSharedMemorySize, GEMM_SMEM);
    cudaFuncSetAttribute(gemm_mma<3>, cudaFuncAttributeMaxDynamicSharedMemorySize, GEMM_SMEM);
    cudaFuncSetAttribute(gemm_mma<4>, cudaFuncAttributeMaxDynamicSharedMemorySize, GEMM_SMEM);
    cudaFuncSetAttribute(gemm_mma<5>, cudaFuncAttributeMaxDynamicSharedMemorySize, GEMM_SMEM);
    cudaFuncSetAttribute(gemm_mma<6>, cudaFuncAttributeMaxDynamicSharedMemorySize, GEMM_SMEM);
    cudaFuncSetAttribute(gemm_mma<7>, cudaFuncAttributeMaxDynamicSharedMemorySize, GEMM_SMEM);
    cudaFuncSetAttribute(attn_mma,    cudaFuncAttributeMaxDynamicSharedMemorySize, ATT_SMEM);

    // persistent side-stream + events (handles reused; recorded fresh each call)
    static cudaStream_t s1 = nullptr;
    static cudaEvent_t  eP = nullptr, eKV = nullptr;
    if (s1 == nullptr) {
        cudaStreamCreateWithFlags(&s1, cudaStreamNonBlocking);
        cudaEventCreateWithFlags(&eP,  cudaEventDisableTiming);
        cudaEventCreateWithFlags(&eKV, cudaEventDisableTiming);
    }

    // ---- prep: fp32 -> fp16 ----
    PrepArgs pa;
    const float* srcs[12] = {obs, ego, wm, enc_w1, enc_w2, wq, wk, wv, wo, tr_w1, tr_w2, q_w1};
    __half* dsts[12] = {obs_h, ego_h, wm_h,
                        w_h + W_ENC1, w_h + W_ENC2, w_h + W_WQ, w_h + W_WK, w_h + W_WV,
                        w_h + W_WO, w_h + W_TR1, w_h + W_TR2, w_h + W_Q1};
    int n4s[12] = {BATCH*DIM/4, BATCH*16/4, MEM*DIM/4,
                   262144/4, 262144/4, 262144/4, 262144/4, 262144/4,
                   262144/4, 270336/4, 262144/4, 65536/4};
    for (int i = 0; i < 12; ++i) { pa.src[i] = srcs[i]; pa.dst[i] = dsts[i]; pa.n4[i] = n4s[i]; }
    prep_kernel<<<dim3(512, 12), 256>>>(pa);

    dim3 gBig(4, 64), gK(4, 8), gVt(8, 4), gQual(1, 64);

    // ---- fork: K + Vt projections on side stream (depend only on prep) ----
    cudaEventRecord(eP, 0);
    cudaStreamWaitEvent(s1, eP, 0);
    gemm_mma<4><<<gK, 256, GEMM_SMEM, s1>>>(wm_h, nullptr, w_h + W_WK, bk,
        nullptr, nullptr, nullptr, k_h, nullptr, MEM, 512, 8, 512);
    gemm_mma<7><<<gVt, 256, GEMM_SMEM, s1>>>(w_h + W_WV, nullptr, wm_h, bv,
        nullptr, nullptr, nullptr, vt_h, nullptr, 512, 512, 8, MEMP);
    cudaEventRecord(eKV, s1);

    // ---- main chain on stream 0 ----
    gemm_mma<1><<<gBig, 256, GEMM_SMEM>>>(obs_h, nullptr, w_h + W_ENC1, enc_b1,
        nullptr, nullptr, nullptr, h, nullptr, BATCH, 512, 8, 512);
    ln_kernel<<<BATCH/8, 256>>>(h, enc_g, enc_be, hn_h);
    gemm_mma<5><<<gBig, 256, GEMM_SMEM>>>(hn_h, nullptr, w_h + W_ENC2, enc_b2,
        nullptr, nullptr, nullptr, enc, enc_h, BATCH, 512, 8, 512);
    gemm_mma<6><<<gBig, 256, GEMM_SMEM>>>(enc_h, nullptr, w_h + W_WQ, bq,
        nullptr, nullptr, nullptr, q_h, nullptr, BATCH, 512, 8, 512);
    // join K/V before attention
    cudaStreamWaitEvent(0, eKV, 0);
    attn_mma<<<dim3(HEADS, BATCH / 128), 256, ATT_SMEM>>>(q_h, k_h, vt_h, ctx_h);
    // out projection + fuse (F = enc fp32)
    gemm_mma<2><<<gBig, 256, GEMM_SMEM>>>(ctx_h, nullptr, w_h + W_WO, bo,
        enc, nullptr, nullptr, fused_h, nullptr, BATCH, 512, 8, 512);
    // transition (K=528, ego in 9th K-chunk)
    gemm_mma<1><<<gBig, 256, GEMM_SMEM>>>(fused_h, ego_h, w_h + W_TR1, tr_b1,
        nullptr, nullptr, nullptr, h, nullptr, BATCH, 528, 9, 512);
    ln_kernel<<<BATCH/8, 256>>>(h, tr_g, tr_be, hn_h);
    gemm_mma<5><<<gBig, 256, GEMM_SMEM>>>(hn_h, nullptr, w_h + W_TR2, tr_b2,
        nullptr, nullptr, nullptr, next_state, ns_h, BATCH, 512, 8, 512);
    // quality head
    gemm_mma<3><<<gQual, 256, GEMM_SMEM>>>(ns_h, nullptr, w_h + W_Q1, q_b1,
        nullptr, q_w2, q_b2, quality, nullptr, BATCH, 512, 8, 512);
    // memory bank update
    compact_kernel<<<1, 256>>>(quality, midx, mcount);
    memupd_kernel<<<MEM, 128>>>(wm, next_state, uidx, midx, mcount, outmem);
}

// round 14
// speedup vs baseline: 2.6192x; 1.0147x over previous
#include <cuda_runtime.h>
#include <cuda_fp16.h>
#include <math.h>
#include <stdint.h>

#define BATCH 8192
#define DIM   512
#define MEM   1000
#define MEMP  1024
#define HEADS 8
#define DH    64

// ==================== helpers ====================
__device__ __forceinline__ uint32_t smem_u32(const void* p) {
    uint32_t a;
    asm("{ .reg .u64 t; cvta.to.shared.u64 t, %1; cvt.u32.u64 %0, t; }" : "=r"(a) : "l"(p));
    return a;
}
__device__ __forceinline__ void mma_f16(float* c, uint32_t a0, uint32_t a1,
                                        uint32_t a2, uint32_t a3,
                                        uint32_t b0, uint32_t b1) {
    asm volatile(
        "mma.sync.aligned.m16n8k16.row.col.f32.f16.f16.f32 "
        "{%0,%1,%2,%3}, {%4,%5,%6,%7}, {%8,%9}, {%0,%1,%2,%3};"
        : "+f"(c[0]), "+f"(c[1]), "+f"(c[2]), "+f"(c[3])
        : "r"(a0), "r"(a1), "r"(a2), "r"(a3), "r"(b0), "r"(b1));
}
__device__ __forceinline__ void cp_async16(uint32_t dst, const void* src, int srcsize) {
    asm volatile("cp.async.cg.shared.global [%0], [%1], 16, %2;"
                 :: "r"(dst), "l"(src), "r"(srcsize));
}
#define CP_COMMIT() asm volatile("cp.async.commit_group;" ::: "memory")
#define CP_WAIT(N)  asm volatile("cp.async.wait_group %0;" :: "n"(N) : "memory")

// ==================== scratch ====================
__device__ float  g_h[BATCH*DIM];         // fp32 pre-LN
__device__ float  g_enc[BATCH*DIM];       // fp32 (F for fuse)
__device__ __half g_hn_h[BATCH*DIM];
__device__ __half g_enc_h[BATCH*DIM];
__device__ __half g_q_h[BATCH*DIM];       // pre-scaled by 0.125
__device__ __half g_ctx_h[BATCH*DIM];
__device__ __half g_fused_h[BATCH*DIM];
__device__ __half g_ns_h[BATCH*DIM];
__device__ __half g_k_h[MEMP*DIM];        // zero-init pads
__device__ __half g_vt_h[DIM*MEMP];       // V^T: [d][m]
__device__ __half g_obs_h[BATCH*DIM];
__device__ __half g_ego_h[BATCH*16];
__device__ __half g_wm_h[MEMP*DIM];       // zero-init pad rows 1000..1023
#define W_ENC1 0
#define W_ENC2 262144
#define W_WQ   524288
#define W_WK   786432
#define W_WV   1048576
#define W_WO   1310720
#define W_TR1  1572864
#define W_TR2  1843200
#define W_Q1   2105344
#define W_TOT  2170880
__device__ __half g_w_h[W_TOT];
__device__ int    g_midx[BATCH];
__device__ int    g_mcount;

// ==================== prep: fp32 -> fp16 ====================
struct PrepArgs {
    const float* src[12];
    __half*      dst[12];
    int          n4[12];
};
__global__ void __launch_bounds__(256) prep_kernel(PrepArgs p) {
    int seg = blockIdx.y;
    int n4 = p.n4[seg];
    const float4* s = (const float4*)p.src[seg];
    for (int i = blockIdx.x * 256 + threadIdx.x; i < n4; i += gridDim.x * 256) {
        float4 v = s[i];
        __half2 lo = __floats2half2_rn(v.x, v.y);
        __half2 hi = __floats2half2_rn(v.z, v.w);
        uint2 pk;
        pk.x = *(uint32_t*)&lo; pk.y = *(uint32_t*)&hi;
        *(uint2*)(p.dst[seg] + (size_t)i * 4) = pk;
    }
}

// ==================== fp16 mma GEMM, 256 thr, NT=128, BK=64, 2 CTA/SM ========
// CTA tile 128 x 128, warp tile 64 x 32 (2 row-warps x 4 col-warps), 3-stage.
// EPI: 1 relu->f32, 2 fuse->f16, 3 quality, 4 f16, 5 dual f32+f16,
//      6 f16 scaled 0.125, 7 f16 row-bias (V^T)
#define GSH 72                  // smem stride in halves (BK=64 + 8 pad)
#define NT  128
#define NF  4
template<int EPI>
__global__ void __launch_bounds__(256, 2) gemm_mma(
    const __half* __restrict__ A, const __half* __restrict__ A2,
    const __half* __restrict__ W, const float* __restrict__ bias,
    const float* __restrict__ F, const float* __restrict__ w2,
    const float* __restrict__ b2, void* __restrict__ Cv, void* __restrict__ C2v,
    int Mrows, int Kw, int Ktiles, int ldc)
{
    constexpr int ASZ = 128 * GSH;          // halves
    constexpr int WSZ = NT * GSH;
    extern __shared__ __half smh[];
    __half* Ah = smh;                       // 3 x ASZ
    __half* Wh = smh + 3 * ASZ;             // 3 x WSZ
    const uint32_t sA = smem_u32(Ah);
    const uint32_t sW = smem_u32(Wh);

    const int tid = threadIdx.x;
    const int wid = tid >> 5, lane = tid & 31;
    const int g = lane >> 2, t = lane & 3;
    const int wm = wid & 1, wn = wid >> 1;
    const int row0 = blockIdx.y * 128;
    const int col0 = blockIdx.x * NT;

    float acc[4][NF][4];
    #pragma unroll
    for (int mf = 0; mf < 4; ++mf)
        #pragma unroll
        for (int nf = 0; nf < NF; ++nf)
            #pragma unroll
            for (int c = 0; c < 4; ++c) acc[mf][nf][c] = 0.f;

    auto load_chunk = [&](int ct, int buf) {
        const int kbase = ct * 64;
        #pragma unroll
        for (int it = 0; it < 8; ++it) {
            int vid = tid + it * 256;
            if (vid < 1024) {
                int r = vid >> 3, q = vid & 7;
                int kel = kbase + q * 8;
                int grow = row0 + r;
                const __half* src = A;
                int sz = 0;
                if (grow < Mrows) {
                    if (kel < 512) { src = A + (size_t)grow * 512 + kel; sz = 16; }
                    else if (A2 != nullptr && kel < 528) {
                        src = A2 + (size_t)grow * 16 + (kel - 512); sz = 16;
                    }
                }
                cp_async16(sA + (buf * ASZ + r * GSH + q * 8) * 2, src, sz);
            } else {
                int vid2 = vid - 1024;
                int r = vid2 >> 3, q = vid2 & 7;
                int kel = kbase + q * 8;
                const __half* src = W + (size_t)(col0 + r) * Kw + kel;
                int sz = (kel < Kw) ? 16 : 0;
                cp_async16(sW + (buf * WSZ + r * GSH + q * 8) * 2, src, sz);
            }
        }
        CP_COMMIT();
    };

    load_chunk(0, 0);
    if (Ktiles > 1) load_chunk(1, 1);

    for (int ct = 0; ct < Ktiles; ++ct) {
        const int buf = ct % 3;
        if (ct + 2 < Ktiles) load_chunk(ct + 2, (ct + 2) % 3);
        if (ct + 2 < Ktiles)      { CP_WAIT(2); }
        else if (ct + 1 < Ktiles) { CP_WAIT(1); }
        else                      { CP_WAIT(0); }
        __syncthreads();

        const __half* Ab = Ah + buf * ASZ + (wm * 64) * GSH;
        const __half* Wb = Wh + buf * WSZ + (wn * (NT / 4)) * GSH;
        #pragma unroll
        for (int ks = 0; ks < 4; ++ks) {
            const int k0 = ks * 16;
            uint32_t af[4][4];
            #pragma unroll
            for (int mf = 0; mf < 4; ++mf) {
                const __half* ar = Ab + (mf * 16) * GSH + k0;
                af[mf][0] = *(const uint32_t*)(ar + (g    ) * GSH + 2 * t    );
                af[mf][1] = *(const uint32_t*)(ar + (g + 8) * GSH + 2 * t    );
                af[mf][2] = *(const uint32_t*)(ar + (g    ) * GSH + 2 * t + 8);
                af[mf][3] = *(const uint32_t*)(ar + (g + 8) * GSH + 2 * t + 8);
            }
            #pragma unroll
            for (int nf = 0; nf < NF; ++nf) {
                const __half* wrp = Wb + (nf * 8 + g) * GSH + k0;
                uint32_t b0 = *(const uint32_t*)(wrp + 2 * t);
                uint32_t b1 = *(const uint32_t*)(wrp + 2 * t + 8);
                #pragma unroll
                for (int mf = 0; mf < 4; ++mf)
                    mma_f16(acc[mf][nf], af[mf][0], af[mf][1], af[mf][2], af[mf][3], b0, b1);
            }
        }
        __syncthreads();
    }

    if (EPI != 3) {
        #pragma unroll
        for (int mf = 0; mf < 4; ++mf) {
            #pragma unroll
            for (int r01 = 0; r01 < 2; ++r01) {
                int grow = row0 + wm * 64 + mf * 16 + g + r01 * 8;
                if (grow >= Mrows) continue;
                #pragma unroll
                for (int nf = 0; nf < NF; ++nf) {
                    int gcol = col0 + wn * (NT / 4) + nf * 8 + 2 * t;
                    float b0 = (EPI == 7) ? bias[grow] : bias[gcol];
                    float b1 = (EPI == 7) ? bias[grow] : bias[gcol + 1];
                    float v0 = acc[mf][nf][r01 * 2 + 0] + b0;
                    float v1 = acc[mf][nf][r01 * 2 + 1] + b1;
                    if (EPI == 1) { v0 = fmaxf(v0, 0.f); v1 = fmaxf(v1, 0.f); }
                    else if (EPI == 2) {
                        const float* fp = F + (size_t)grow * 512 + gcol;
                        v0 = 0.7f * fp[0] + 0.3f * v0;
                        v1 = 0.7f * fp[1] + 0.3f * v1;
                    } else if (EPI == 6) { v0 *= 0.125f; v1 *= 0.125f; }
                    size_t off = (size_t)grow * ldc + gcol;
                    if (EPI == 1) {
                        *(float2*)((float*)Cv + off) = make_float2(v0, v1);
                    } else if (EPI == 5) {
                        *(float2*)((float*)Cv + off) = make_float2(v0, v1);
                        __half2 hv = __floats2half2_rn(v0, v1);
                        *(__half2*)((__half*)C2v + off) = hv;
                    } else {
                        __half2 hv = __floats2half2_rn(v0, v1);
                        *(__half2*)((__half*)Cv + off) = hv;
                    }
                }
            }
        }
    } else {
        // quality head (NT=128, col0=0): sigmoid(b2 + sum relu(acc+b1)*w2)
        float* qpart = (float*)smh;
        __syncthreads();
        #pragma unroll
        for (int mf = 0; mf < 4; ++mf) {
            #pragma unroll
            for (int r01 = 0; r01 < 2; ++r01) {
                float s = 0.f;
                #pragma unroll
                for (int nf = 0; nf < NF; ++nf) {
                    int c = wn * (NT / 4) + nf * 8 + 2 * t;
                    float h0 = fmaxf(acc[mf][nf][r01 * 2 + 0] + bias[c], 0.f);
                    float h1 = fmaxf(acc[mf][nf][r01 * 2 + 1] + bias[c + 1], 0.f);
                    s += h0 * w2[c] + h1 * w2[c + 1];
                }
                int rl = wm * 64 + mf * 16 + r01 * 8 + g;
                qpart[rl * 17 + wn * 4 + t] = s;
            }
        }
        __syncthreads();
        if (tid < 128) {
            float s = b2[0];
            #pragma unroll
            for (int i = 0; i < 16; ++i) s += qpart[tid * 17 + i];
            ((float*)Cv)[row0 + tid] = 1.f / (1.f + expf(-s));
        }
    }
}
#define GEMM_SMEM ((3 * 128 * GSH + 3 * NT * GSH) * 2)

// ==================== fp16 mma flash attention (double-buffered K/V) =========
// Q pre-scaled by 0.125. Vt is V^T [d][m]. 2 CTA/SM.
#define AS 72
#define KVSZ (64 * AS)
#define ATT_SMEM ((128*AS + 2*KVSZ + 128*AS + 2*KVSZ) * 2)
__global__ void __launch_bounds__(256, 2) attn_mma(
    const __half* __restrict__ Q, const __half* __restrict__ Kb,
    const __half* __restrict__ Vt, __half* __restrict__ ctx)
{
    extern __shared__ __half smh[];
    __half* Qs = smh;                      // 128 x AS
    __half* Ks = Qs + 128 * AS;            // 2 x 64 x AS
    __half* Ps = Ks + 2 * KVSZ;            // 128 x AS
    __half* Vs = Ps + 128 * AS;            // 2 x 64 x AS (rows = d, cols = m)
    const uint32_t sK = smem_u32(Ks);
    const uint32_t sV = smem_u32(Vs);

    const int h = blockIdx.x;
    const int b0 = blockIdx.y * 128;
    const int tid = threadIdx.x;
    const int wid = tid >> 5, lane = tid & 31;
    const int g = lane >> 2, t = lane & 3;
    const int qr = wid * 16;

    auto load_kv = [&](int m0, int buf) {
        #pragma unroll
        for (int it = 0; it < 4; ++it) {
            int vid = tid + it * 256;
            if (vid < 512) {
                int r = vid >> 3, q = vid & 7;
                int gm = m0 + r;
                int sz = (gm < MEM) ? 16 : 0;
                cp_async16(sK + (buf * KVSZ + r * AS + q * 8) * 2,
                           Kb + (size_t)gm * 512 + h * 64 + q * 8, sz);
            } else {
                int vid2 = vid - 512;
                int r = vid2 >> 3, q = vid2 & 7;
                cp_async16(sV + (buf * KVSZ + r * AS + q * 8) * 2,
                           Vt + (size_t)(h * 64 + r) * MEMP + m0 + q * 8, 16);
            }
        }
        CP_COMMIT();
    };

    load_kv(0, 0);

    #pragma unroll
    for (int it = 0; it < 4; ++it) {
        int vid = tid + it * 256;
        int r = vid >> 3, q = vid & 7;
        uint4 v = *(const uint4*)(Q + (size_t)(b0 + r) * 512 + h * 64 + q * 8);
        *(uint4*)(Qs + r * AS + q * 8) = v;
    }

    float oacc[8][4];
    float rsum[2] = {0.f, 0.f};
    #pragma unroll
    for (int nf = 0; nf < 8; ++nf)
        #pragma unroll
        for (int c = 0; c < 4; ++c) oacc[nf][c] = 0.f;

    for (int ci = 0; ci < MEMP / 64; ++ci) {
        const int m0 = ci * 64;
        const int buf = ci & 1;
        // prefetch next chunk into the other buffer (its prior users are done:
        // the end-of-iteration __syncthreads below covers chunk ci-1)
        if (ci + 1 < MEMP / 64) { load_kv(m0 + 64, buf ^ 1); CP_WAIT(1); }
        else                    { CP_WAIT(0); }
        __syncthreads();

        const __half* Kc = Ks + buf * KVSZ;
        const __half* Vc = Vs + buf * KVSZ;

        // ---- S = Q K^T (d = 64 -> 4 k16 steps) ----
        float sacc[8][4];
        #pragma unroll
        for (int nf = 0; nf < 8; ++nf)
            #pragma unroll
            for (int c = 0; c < 4; ++c) sacc[nf][c] = 0.f;
        #pragma unroll
        for (int ks = 0; ks < 4; ++ks) {
            int k0 = ks * 16;
            uint32_t a0 = *(const uint32_t*)(Qs + (qr + g    ) * AS + k0 + 2 * t    );
            uint32_t a1 = *(const uint32_t*)(Qs + (qr + g + 8) * AS + k0 + 2 * t    );
            uint32_t a2 = *(const uint32_t*)(Qs + (qr + g    ) * AS + k0 + 2 * t + 8);
            uint32_t a3 = *(const uint32_t*)(Qs + (qr + g + 8) * AS + k0 + 2 * t + 8);
            #pragma unroll
            for (int nf = 0; nf < 8; ++nf) {
                uint32_t b0 = *(const uint32_t*)(Kc + (nf * 8 + g) * AS + k0 + 2 * t    );
                uint32_t b1 = *(const uint32_t*)(Kc + (nf * 8 + g) * AS + k0 + 2 * t + 8);
                mma_f16(sacc[nf], a0, a1, a2, a3, b0, b1);
            }
        }

        // ---- softmax numerator (shift-free: LN-bounded scores) ----
        #pragma unroll
        for (int r01 = 0; r01 < 2; ++r01) {
            float ps = 0.f;
            int prow = qr + g + r01 * 8;
            #pragma unroll
            for (int nf = 0; nf < 8; ++nf) {
                float p0 = 0.f, p1 = 0.f;
                if (m0 + nf * 8 + 2 * t     < MEM) p0 = __expf(sacc[nf][r01 * 2 + 0]);
                if (m0 + nf * 8 + 2 * t + 1 < MEM) p1 = __expf(sacc[nf][r01 * 2 + 1]);
                ps += p0 + p1;
                *(__half2*)(Ps + prow * AS + nf * 8 + 2 * t) = __floats2half2_rn(p0, p1);
            }
            ps += __shfl_xor_sync(0xffffffffu, ps, 1);
            ps += __shfl_xor_sync(0xffffffffu, ps, 2);
            rsum[r01] += ps;
        }
        __syncwarp();

        // ---- O += P V  (k = mem 64 -> 4 k16 steps; B from Vc[d][m]) ----
        #pragma unroll
        for (int ks = 0; ks < 4; ++ks) {
            int k0 = ks * 16;
            uint32_t a0 = *(const uint32_t*)(Ps + (qr + g    ) * AS + k0 + 2 * t    );
            uint32_t a1 = *(const uint32_t*)(Ps + (qr + g + 8) * AS + k0 + 2 * t    );
            uint32_t a2 = *(const uint32_t*)(Ps + (qr + g    ) * AS + k0 + 2 * t + 8);
            uint32_t a3 = *(const uint32_t*)(Ps + (qr + g + 8) * AS + k0 + 2 * t + 8);
            #pragma unroll
            for (int nf = 0; nf < 8; ++nf) {
                uint32_t b0 = *(const uint32_t*)(Vc + (nf * 8 + g) * AS + k0 + 2 * t    );
                uint32_t b1 = *(const uint32_t*)(Vc + (nf * 8 + g) * AS + k0 + 2 * t + 8);
                mma_f16(oacc[nf], a0, a1, a2, a3, b0, b1);
            }
        }
        __syncthreads();    // all reads of buf done before it is overwritten
    }

    #pragma unroll
    for (int r01 = 0; r01 < 2; ++r01) {
        float inv = 1.f / rsum[r01];
        int grow = b0 + qr + g + r01 * 8;
        #pragma unroll
        for (int nf = 0; nf < 8; ++nf) {
            __half2 o = __floats2half2_rn(oacc[nf][r01 * 2 + 0] * inv,
                                          oacc[nf][r01 * 2 + 1] * inv);
            *(__half2*)(ctx + (size_t)grow * 512 + h * 64 + nf * 8 + 2 * t) = o;
        }
    }
}

// ==================== LayerNorm: warp-per-row, fp32 in, fp16 out =============
__global__ void __launch_bounds__(256) ln_kernel(
    const float* __restrict__ x, const float* __restrict__ g,
    const float* __restrict__ b, __half* __restrict__ y)
{
    const int warp = threadIdx.x >> 5, lane = threadIdx.x & 31;
    const int row = blockIdx.x * 8 + warp;
    const float* xr = x + (size_t)row * 512;

    float4 v[4];
    #pragma unroll
    for (int i = 0; i < 4; ++i)
        v[i] = *(const float4*)(xr + i * 128 + lane * 4);

    float s = 0.f;
    #pragma unroll
    for (int i = 0; i < 4; ++i) s += v[i].x + v[i].y + v[i].z + v[i].w;
    #pragma unroll
    for (int o = 16; o > 0; o >>= 1) s += __shfl_xor_sync(0xffffffffu, s, o);
    float mean = s * (1.f / 512.f);

    float ss = 0.f;
    #pragma unroll
    for (int i = 0; i < 4; ++i) {
        v[i].x -= mean; v[i].y -= mean; v[i].z -= mean; v[i].w -= mean;
        ss += v[i].x * v[i].x + v[i].y * v[i].y + v[i].z * v[i].z + v[i].w * v[i].w;
    }
    #pragma unroll
    for (int o = 16; o > 0; o >>= 1) ss += __shfl_xor_sync(0xffffffffu, ss, o);
    float inv = rsqrtf(ss * (1.f / 512.f) + 1e-5f);

    #pragma unroll
    for (int i = 0; i < 4; ++i) {
        float4 gg = *(const float4*)(g + i * 128 + lane * 4);
        float4 bb = *(const float4*)(b + i * 128 + lane * 4);
        __half2 lo = __floats2half2_rn(v[i].x * inv * gg.x + bb.x,
                                       v[i].y * inv * gg.y + bb.y);
        __half2 hi = __floats2half2_rn(v[i].z * inv * gg.z + bb.z,
                                       v[i].w * inv * gg.w + bb.w);
        uint2 pk; pk.x = *(uint32_t*)&lo; pk.y = *(uint32_t*)&hi;
        *(uint2*)(y + (size_t)row * 512 + i * 128 + lane * 4) = pk;
    }
}

// ==================== mask compaction + memory EMA ====================
__global__ void __launch_bounds__(256) compact_kernel(
    const float* __restrict__ quality, int* __restrict__ midx, int* __restrict__ mcount)
{
    const int tid = threadIdx.x;
    const int base = tid * 32;
    int cnt = 0;
    for (int i = 0; i < 32; ++i) cnt += (quality[base + i] > 0.7f) ? 1 : 0;
    __shared__ int sc[256];
    __shared__ int offs[256];
    sc[tid] = cnt;
    __syncthreads();
    if (tid == 0) {
        int run = 0;
        for (int t = 0; t < 256; ++t) { offs[t] = run; run += sc[t]; }
        *mcount = run;
    }
    __syncthreads();
    int o = offs[tid];
    for (int i = 0; i < 32; ++i)
        if (quality[base + i] > 0.7f) midx[o++] = base + i;
}

__global__ void __launch_bounds__(128) memupd_kernel(
    const float* __restrict__ wm, const float* __restrict__ ns,
    const int* __restrict__ upd, const int* __restrict__ midx,
    const int* __restrict__ mcount, float* __restrict__ outmem)
{
    const int m = blockIdx.x;
    const int d = threadIdx.x * 4;
    float4 v = *(const float4*)(wm + (size_t)m * 512 + d);
    const int cnt = *mcount;
    for (int jj = 0; jj < cnt; ++jj) {
        int i = midx[jj];
        if (upd[i] == m) {
            float4 s = *(const float4*)(ns + (size_t)i * 512 + d);
            v.x = 0.9f * v.x + 0.1f * s.x;
            v.y = 0.9f * v.y + 0.1f * s.y;
            v.z = 0.9f * v.z + 0.1f * s.z;
            v.w = 0.9f * v.w + 0.1f * s.w;
        }
    }
    *(float4*)(outmem + (size_t)m * 512 + d) = v;
}

// ==================== host launcher ====================
extern "C" void kernel_launch(void* const* d_in, const int* in_sizes, int n_in,
                              void* d_out, int out_size)
{
    const float* obs    = (const float*)d_in[0];
    const float* ego    = (const float*)d_in[1];
    const float* wm     = (const float*)d_in[2];
    const float* enc_w1 = (const float*)d_in[3];
    const float* enc_b1 = (const float*)d_in[4];
    const float* enc_g  = (const float*)d_in[5];
    const float* enc_be = (const float*)d_in[6];
    const float* enc_w2 = (const float*)d_in[7];
    const float* enc_b2 = (const float*)d_in[8];
    const float* wq     = (const float*)d_in[9];
    const float* bq     = (const float*)d_in[10];
    const float* wk     = (const float*)d_in[11];
    const float* bk     = (const float*)d_in[12];
    const float* wv     = (const float*)d_in[13];
    const float* bv     = (const float*)d_in[14];
    const float* wo     = (const float*)d_in[15];
    const float* bo     = (const float*)d_in[16];
    const float* tr_w1  = (const float*)d_in[17];
    const float* tr_b1  = (const float*)d_in[18];
    const float* tr_g   = (const float*)d_in[19];
    const float* tr_be  = (const float*)d_in[20];
    const float* tr_w2  = (const float*)d_in[21];
    const float* tr_b2  = (const float*)d_in[22];
    const float* q_w1   = (const float*)d_in[23];
    const float* q_b1   = (const float*)d_in[24];
    const float* q_w2   = (const float*)d_in[25];
    const float* q_b2   = (const float*)d_in[26];
    const int*   uidx   = (const int*)d_in[27];

    float* out        = (float*)d_out;
    float* next_state = out;
    float* quality    = out + (size_t)BATCH * DIM;
    float* outmem     = quality + BATCH;

    float *h, *enc;
    __half *hn_h, *enc_h, *q_h, *ctx_h, *fused_h, *ns_h, *k_h, *vt_h;
    __half *obs_h, *ego_h, *wm_h, *w_h;
    int *midx, *mcount;
    cudaGetSymbolAddress((void**)&h,      g_h);
    cudaGetSymbolAddress((void**)&enc,    g_enc);
    cudaGetSymbolAddress((void**)&hn_h,   g_hn_h);
    cudaGetSymbolAddress((void**)&enc_h,  g_enc_h);
    cudaGetSymbolAddress((void**)&q_h,    g_q_h);
    cudaGetSymbolAddress((void**)&ctx_h,  g_ctx_h);
    cudaGetSymbolAddress((void**)&fused_h,g_fused_h);
    cudaGetSymbolAddress((void**)&ns_h,   g_ns_h);
    cudaGetSymbolAddress((void**)&k_h,    g_k_h);
    cudaGetSymbolAddress((void**)&vt_h,   g_vt_h);
    cudaGetSymbolAddress((void**)&obs_h,  g_obs_h);
    cudaGetSymbolAddress((void**)&ego_h,  g_ego_h);
    cudaGetSymbolAddress((void**)&wm_h,   g_wm_h);
    cudaGetSymbolAddress((void**)&w_h,    g_w_h);
    cudaGetSymbolAddress((void**)&midx,   g_midx);
    cudaGetSymbolAddress((void**)&mcount, g_mcount);

    cudaFuncSetAttribute(gemm_mma<1>, cudaFuncAttributeMaxDynamicSharedMemorySize, GEMM_SMEM);
    cudaFuncSetAttribute(gemm_mma<2>, cudaFuncAttributeMaxDynamicSharedMemorySize, GEMM_SMEM);
    cudaFuncSetAttribute(gemm_mma<3>, cudaFuncAttributeMaxDynamicSharedMemorySize, GEMM_SMEM);
    cudaFuncSetAttribute(gemm_mma<4>, cudaFuncAttributeMaxDynamicSharedMemorySize, GEMM_SMEM);
    cudaFuncSetAttribute(gemm_mma<5>, cudaFuncAttributeMaxDynamicSharedMemorySize, GEMM_SMEM);
    cudaFuncSetAttribute(gemm_mma<6>, cudaFuncAttributeMaxDynamicSharedMemorySize, GEMM_SMEM);
    cudaFuncSetAttribute(gemm_mma<7>, cudaFuncAttributeMaxDynamicSharedMemorySize, GEMM_SMEM);
    cudaFuncSetAttribute(attn_mma,    cudaFuncAttributeMaxDynamicSharedMemorySize, ATT_SMEM);

    // persistent side-stream + events (handles reused; recorded fresh each call)
    static cudaStream_t s1 = nullptr;
    static cudaEvent_t  eP = nullptr, eKV = nullptr;
    if (s1 == nullptr) {
        cudaStreamCreateWithFlags(&s1, cudaStreamNonBlocking);
        cudaEventCreateWithFlags(&eP,  cudaEventDisableTiming);
        cudaEventCreateWithFlags(&eKV, cudaEventDisableTiming);
    }

    // ---- prep: fp32 -> fp16 ----
    PrepArgs pa;
    const float* srcs[12] = {obs, ego, wm, enc_w1, enc_w2, wq, wk, wv, wo, tr_w1, tr_w2, q_w1};
    __half* dsts[12] = {obs_h, ego_h, wm_h,
                        w_h + W_ENC1, w_h + W_ENC2, w_h + W_WQ, w_h + W_WK, w_h + W_WV,
                        w_h + W_WO, w_h + W_TR1, w_h + W_TR2, w_h + W_Q1};
    int n4s[12] = {BATCH*DIM/4, BATCH*16/4, MEM*DIM/4,
                   262144/4, 262144/4, 262144/4, 262144/4, 262144/4,
                   262144/4, 270336/4, 262144/4, 65536/4};
    for (int i = 0; i < 12; ++i) { pa.src[i] = srcs[i]; pa.dst[i] = dsts[i]; pa.n4[i] = n4s[i]; }
    prep_kernel<<<dim3(512, 12), 256>>>(pa);

    dim3 gBig(4, 64), gK(4, 8), gVt(8, 4), gQual(1, 64);

    // ---- fork: K + Vt projections on side stream (depend only on prep) ----
    cudaEventRecord(eP, 0);
    cudaStreamWaitEvent(s1, eP, 0);
    gemm_mma<4><<<gK, 256, GEMM_SMEM, s1>>>(wm_h, nullptr, w_h + W_WK, bk,
        nullptr, nullptr, nullptr, k_h, nullptr, MEM, 512, 8, 512);
    gemm_mma<7><<<gVt, 256, GEMM_SMEM, s1>>>(w_h + W_WV, nullptr, wm_h, bv,
        nullptr, nullptr, nullptr, vt_h, nullptr, 512, 512, 8, MEMP);
    cudaEventRecord(eKV, s1);

    // ---- main chain on stream 0 ----
    gemm_mma<1><<<gBig, 256, GEMM_SMEM>>>(obs_h, nullptr, w_h + W_ENC1, enc_b1,
        nullptr, nullptr, nullptr, h, nullptr, BATCH, 512, 8, 512);
    ln_kernel<<<BATCH/8, 256>>>(h, enc_g, enc_be, hn_h);
    gemm_mma<5><<<gBig, 256, GEMM_SMEM>>>(hn_h, nullptr, w_h + W_ENC2, enc_b2,
        nullptr, nullptr, nullptr, enc, enc_h, BATCH, 512, 8, 512);
    gemm_mma<6><<<gBig, 256, GEMM_SMEM>>>(enc_h, nullptr, w_h + W_WQ, bq,
        nullptr, nullptr, nullptr, q_h, nullptr, BATCH, 512, 8, 512);
    // join K/V before attention
    cudaStreamWaitEvent(0, eKV, 0);
    attn_mma<<<dim3(HEADS, BATCH / 128), 256, ATT_SMEM>>>(q_h, k_h, vt_h, ctx_h);
    // out projection + fuse (F = enc fp32)
    gemm_mma<2><<<gBig, 256, GEMM_SMEM>>>(ctx_h, nullptr, w_h + W_WO, bo,
        enc, nullptr, nullptr, fused_h, nullptr, BATCH, 512, 8, 512);
    // transition (K=528, ego in 9th K-chunk)
    gemm_mma<1><<<gBig, 256, GEMM_SMEM>>>(fused_h, ego_h, w_h + W_TR1, tr_b1,
        nullptr, nullptr, nullptr, h, nullptr, BATCH, 528, 9, 512);
    ln_kernel<<<BATCH/8, 256>>>(h, tr_g, tr_be, hn_h);
    gemm_mma<5><<<gBig, 256, GEMM_SMEM>>>(hn_h, nullptr, w_h + W_TR2, tr_b2,
        nullptr, nullptr, nullptr, next_state, ns_h, BATCH, 512, 8, 512);
    // quality head
    gemm_mma<3><<<gQual, 256, GEMM_SMEM>>>(ns_h, nullptr, w_h + W_Q1, q_b1,
        nullptr, q_w2, q_b2, quality, nullptr, BATCH, 512, 8, 512);
    // memory bank update
    compact_kernel<<<1, 256>>>(quality, midx, mcount);
    memupd_kernel<<<MEM, 128>>>(wm, next_state, uidx, midx, mcount, outmem);
}

// round 15
// speedup vs baseline: 2.8893x; 1.1031x over previous
#include <cuda_runtime.h>
#include <cuda_fp16.h>
#include <math.h>
#include <stdint.h>

#define BATCH 8192
#define DIM   512
#define MEM   1000
#define MEMP  1024
#define HEADS 8
#define DH    64

// ==================== helpers ====================
__device__ __forceinline__ uint32_t smem_u32(const void* p) {
    uint32_t a;
    asm("{ .reg .u64 t; cvta.to.shared.u64 t, %1; cvt.u32.u64 %0, t; }" : "=r"(a) : "l"(p));
    return a;
}
__device__ __forceinline__ void mma_f16(float* c, uint32_t a0, uint32_t a1,
                                        uint32_t a2, uint32_t a3,
                                        uint32_t b0, uint32_t b1) {
    asm volatile(
        "mma.sync.aligned.m16n8k16.row.col.f32.f16.f16.f32 "
        "{%0,%1,%2,%3}, {%4,%5,%6,%7}, {%8,%9}, {%0,%1,%2,%3};"
        : "+f"(c[0]), "+f"(c[1]), "+f"(c[2]), "+f"(c[3])
        : "r"(a0), "r"(a1), "r"(a2), "r"(a3), "r"(b0), "r"(b1));
}
__device__ __forceinline__ void ldsm_x4(uint32_t* r, uint32_t addr) {
    asm volatile("ldmatrix.sync.aligned.m8n8.x4.shared.b16 {%0,%1,%2,%3}, [%4];"
        : "=r"(r[0]), "=r"(r[1]), "=r"(r[2]), "=r"(r[3]) : "r"(addr));
}
__device__ __forceinline__ void ldsm_x2(uint32_t& r0, uint32_t& r1, uint32_t addr) {
    asm volatile("ldmatrix.sync.aligned.m8n8.x2.shared.b16 {%0,%1}, [%2];"
        : "=r"(r0), "=r"(r1) : "r"(addr));
}
__device__ __forceinline__ void cp_async16(uint32_t dst, const void* src, int srcsize) {
    asm volatile("cp.async.cg.shared.global [%0], [%1], 16, %2;"
                 :: "r"(dst), "l"(src), "r"(srcsize));
}
#define CP_COMMIT() asm volatile("cp.async.commit_group;" ::: "memory")
#define CP_WAIT(N)  asm volatile("cp.async.wait_group %0;" :: "n"(N) : "memory")

// ==================== scratch ====================
__device__ float  g_h[BATCH*DIM];
__device__ float  g_enc[BATCH*DIM];
__device__ __half g_hn_h[BATCH*DIM];
__device__ __half g_enc_h[BATCH*DIM];
__device__ __half g_q_h[BATCH*DIM];       // pre-scaled by 0.125
__device__ __half g_ctx_h[BATCH*DIM];
__device__ __half g_fused_h[BATCH*DIM];
__device__ __half g_ns_h[BATCH*DIM];
__device__ __half g_k_h[MEMP*DIM];
__device__ __half g_vt_h[DIM*MEMP];       // V^T: [d][m]
__device__ __half g_obs_h[BATCH*DIM];
__device__ __half g_ego_h[BATCH*16];
__device__ __half g_wm_h[MEMP*DIM];
#define W_ENC1 0
#define W_ENC2 262144
#define W_WQ   524288
#define W_WK   786432
#define W_WV   1048576
#define W_WO   1310720
#define W_TR1  1572864
#define W_TR2  1843200
#define W_Q1   2105344
#define W_TOT  2170880
__device__ __half g_w_h[W_TOT];
__device__ int    g_midx[BATCH];
__device__ int    g_mcount;

// ==================== prep: fp32 -> fp16 ====================
struct PrepArgs {
    const float* src[12];
    __half*      dst[12];
    int          n4[12];
};
__global__ void __launch_bounds__(256) prep_kernel(PrepArgs p) {
    int seg = blockIdx.y;
    int n4 = p.n4[seg];
    const float4* s = (const float4*)p.src[seg];
    for (int i = blockIdx.x * 256 + threadIdx.x; i < n4; i += gridDim.x * 256) {
        float4 v = s[i];
        __half2 lo = __floats2half2_rn(v.x, v.y);
        __half2 hi = __floats2half2_rn(v.z, v.w);
        uint2 pk;
        pk.x = *(uint32_t*)&lo; pk.y = *(uint32_t*)&hi;
        *(uint2*)(p.dst[seg] + (size_t)i * 4) = pk;
    }
}

// ==================== fp16 mma GEMM, 256 thr, NT=128, BK=64, 2 CTA/SM ========
// CTA tile 128 x 128, warp tile 64 x 32, 3-stage, ldmatrix fragment loads.
// EPI: 1 relu->f32, 2 fuse->f16, 3 quality, 4 f16, 5 dual f32+f16,
//      6 f16 scaled 0.125, 7 f16 row-bias (V^T)
#define GSH 72
#define NT  128
#define NF  4
template<int EPI>
__global__ void __launch_bounds__(256, 2) gemm_mma(
    const __half* __restrict__ A, const __half* __restrict__ A2,
    const __half* __restrict__ W, const float* __restrict__ bias,
    const float* __restrict__ F, const float* __restrict__ w2,
    const float* __restrict__ b2, void* __restrict__ Cv, void* __restrict__ C2v,
    int Mrows, int Kw, int Ktiles, int ldc)
{
    constexpr int ASZ = 128 * GSH;
    constexpr int WSZ = NT * GSH;
    extern __shared__ __half smh[];
    __half* Ah = smh;
    __half* Wh = smh + 3 * ASZ;
    const uint32_t sA = smem_u32(Ah);
    const uint32_t sW = smem_u32(Wh);

    const int tid = threadIdx.x;
    const int wid = tid >> 5, lane = tid & 31;
    const int g = lane >> 2, t = lane & 3;
    const int wm = wid & 1, wn = wid >> 1;
    const int row0 = blockIdx.y * 128;
    const int col0 = blockIdx.x * NT;

    // ldmatrix per-lane byte offsets
    const int lane16 = lane & 15, laneHi = lane >> 4;
    const int lane8  = lane & 7,  laneK  = (lane >> 3) & 1;
    uint32_t aoff[4], boff[NF];
    #pragma unroll
    for (int mf = 0; mf < 4; ++mf)
        aoff[mf] = ((wm * 64 + mf * 16 + lane16) * GSH + laneHi * 8) * 2;
    #pragma unroll
    for (int nf = 0; nf < NF; ++nf)
        boff[nf] = ((wn * (NT / 4) + nf * 8 + lane8) * GSH + laneK * 8) * 2;

    float acc[4][NF][4];
    #pragma unroll
    for (int mf = 0; mf < 4; ++mf)
        #pragma unroll
        for (int nf = 0; nf < NF; ++nf)
            #pragma unroll
            for (int c = 0; c < 4; ++c) acc[mf][nf][c] = 0.f;

    auto load_chunk = [&](int ct, int buf) {
        const int kbase = ct * 64;
        #pragma unroll
        for (int it = 0; it < 8; ++it) {
            int vid = tid + it * 256;
            if (vid < 1024) {
                int r = vid >> 3, q = vid & 7;
                int kel = kbase + q * 8;
                int grow = row0 + r;
                const __half* src = A;
                int sz = 0;
                if (grow < Mrows) {
                    if (kel < 512) { src = A + (size_t)grow * 512 + kel; sz = 16; }
                    else if (A2 != nullptr && kel < 528) {
                        src = A2 + (size_t)grow * 16 + (kel - 512); sz = 16;
                    }
                }
                cp_async16(sA + (buf * ASZ + r * GSH + q * 8) * 2, src, sz);
            } else {
                int vid2 = vid - 1024;
                int r = vid2 >> 3, q = vid2 & 7;
                int kel = kbase + q * 8;
                const __half* src = W + (size_t)(col0 + r) * Kw + kel;
                int sz = (kel < Kw) ? 16 : 0;
                cp_async16(sW + (buf * WSZ + r * GSH + q * 8) * 2, src, sz);
            }
        }
        CP_COMMIT();
    };

    load_chunk(0, 0);
    if (Ktiles > 1) load_chunk(1, 1);

    for (int ct = 0; ct < Ktiles; ++ct) {
        const int buf = ct % 3;
        if (ct + 2 < Ktiles) load_chunk(ct + 2, (ct + 2) % 3);
        if (ct + 2 < Ktiles)      { CP_WAIT(2); }
        else if (ct + 1 < Ktiles) { CP_WAIT(1); }
        else                      { CP_WAIT(0); }
        __syncthreads();

        const uint32_t abase = sA + buf * ASZ * 2;
        const uint32_t bbase = sW + buf * WSZ * 2;
        #pragma unroll
        for (int ks = 0; ks < 4; ++ks) {
            const uint32_t kb = ks * 32;        // k0*2 bytes (k0 = ks*16 halves)
            uint32_t af[4][4];
            #pragma unroll
            for (int mf = 0; mf < 4; ++mf)
                ldsm_x4(af[mf], abase + aoff[mf] + kb);
            #pragma unroll
            for (int nf = 0; nf < NF; ++nf) {
                uint32_t b0, b1;
                ldsm_x2(b0, b1, bbase + boff[nf] + kb);
                #pragma unroll
                for (int mf = 0; mf < 4; ++mf)
                    mma_f16(acc[mf][nf], af[mf][0], af[mf][1], af[mf][2], af[mf][3], b0, b1);
            }
        }
        __syncthreads();
    }

    if (EPI != 3) {
        #pragma unroll
        for (int mf = 0; mf < 4; ++mf) {
            #pragma unroll
            for (int r01 = 0; r01 < 2; ++r01) {
                int grow = row0 + wm * 64 + mf * 16 + g + r01 * 8;
                if (grow >= Mrows) continue;
                #pragma unroll
                for (int nf = 0; nf < NF; ++nf) {
                    int gcol = col0 + wn * (NT / 4) + nf * 8 + 2 * t;
                    float b0 = (EPI == 7) ? bias[grow] : bias[gcol];
                    float b1 = (EPI == 7) ? bias[grow] : bias[gcol + 1];
                    float v0 = acc[mf][nf][r01 * 2 + 0] + b0;
                    float v1 = acc[mf][nf][r01 * 2 + 1] + b1;
                    if (EPI == 1) { v0 = fmaxf(v0, 0.f); v1 = fmaxf(v1, 0.f); }
                    else if (EPI == 2) {
                        const float* fp = F + (size_t)grow * 512 + gcol;
                        v0 = 0.7f * fp[0] + 0.3f * v0;
                        v1 = 0.7f * fp[1] + 0.3f * v1;
                    } else if (EPI == 6) { v0 *= 0.125f; v1 *= 0.125f; }
                    size_t off = (size_t)grow * ldc + gcol;
                    if (EPI == 1) {
                        *(float2*)((float*)Cv + off) = make_float2(v0, v1);
                    } else if (EPI == 5) {
                        *(float2*)((float*)Cv + off) = make_float2(v0, v1);
                        __half2 hv = __floats2half2_rn(v0, v1);
                        *(__half2*)((__half*)C2v + off) = hv;
                    } else {
                        __half2 hv = __floats2half2_rn(v0, v1);
                        *(__half2*)((__half*)Cv + off) = hv;
                    }
                }
            }
        }
    } else {
        // quality head (NT=128, col0=0): sigmoid(b2 + sum relu(acc+b1)*w2)
        float* qpart = (float*)smh;
        __syncthreads();
        #pragma unroll
        for (int mf = 0; mf < 4; ++mf) {
            #pragma unroll
            for (int r01 = 0; r01 < 2; ++r01) {
                float s = 0.f;
                #pragma unroll
                for (int nf = 0; nf < NF; ++nf) {
                    int c = wn * (NT / 4) + nf * 8 + 2 * t;
                    float h0 = fmaxf(acc[mf][nf][r01 * 2 + 0] + bias[c], 0.f);
                    float h1 = fmaxf(acc[mf][nf][r01 * 2 + 1] + bias[c + 1], 0.f);
                    s += h0 * w2[c] + h1 * w2[c + 1];
                }
                int rl = wm * 64 + mf * 16 + r01 * 8 + g;
                qpart[rl * 17 + wn * 4 + t] = s;
            }
        }
        __syncthreads();
        if (tid < 128) {
            float s = b2[0];
            #pragma unroll
            for (int i = 0; i < 16; ++i) s += qpart[tid * 17 + i];
            ((float*)Cv)[row0 + tid] = 1.f / (1.f + expf(-s));
        }
    }
}
#define GEMM_SMEM ((3 * 128 * GSH + 3 * NT * GSH) * 2)

// ==================== fp16 mma flash attention ==============================
// Q frags hoisted to registers; P kept in registers (C-layout == A-layout);
// K/V double-buffered; ldmatrix loads. Q pre-scaled by 0.125. Vt is V^T [d][m].
#define AS 72
#define KVSZ (64 * AS)
#define ATT_SMEM ((128*AS + 2*KVSZ + 2*KVSZ) * 2)
__global__ void __launch_bounds__(256, 2) attn_mma(
    const __half* __restrict__ Q, const __half* __restrict__ Kb,
    const __half* __restrict__ Vt, __half* __restrict__ ctx)
{
    extern __shared__ __half smh[];
    __half* Qs = smh;                      // 128 x AS (staging only)
    __half* Ks = Qs + 128 * AS;            // 2 x 64 x AS
    __half* Vs = Ks + 2 * KVSZ;            // 2 x 64 x AS (rows = d, cols = m)
    const uint32_t sQ = smem_u32(Qs);
    const uint32_t sK = smem_u32(Ks);
    const uint32_t sV = smem_u32(Vs);

    const int h = blockIdx.x;
    const int b0 = blockIdx.y * 128;
    const int tid = threadIdx.x;
    const int wid = tid >> 5, lane = tid & 31;
    const int g = lane >> 2, t = lane & 3;
    const int qr = wid * 16;

    const int lane16 = lane & 15, laneHi = lane >> 4;
    const int lane8  = lane & 7,  laneK  = (lane >> 3) & 1;
    uint32_t kvoff[8];
    #pragma unroll
    for (int nf = 0; nf < 8; ++nf)
        kvoff[nf] = ((nf * 8 + lane8) * AS + laneK * 8) * 2;

    auto load_kv = [&](int m0, int buf) {
        #pragma unroll
        for (int it = 0; it < 4; ++it) {
            int vid = tid + it * 256;
            if (vid < 512) {
                int r = vid >> 3, q = vid & 7;
                int gm = m0 + r;
                int sz = (gm < MEM) ? 16 : 0;
                cp_async16(sK + (buf * KVSZ + r * AS + q * 8) * 2,
                           Kb + (size_t)gm * 512 + h * 64 + q * 8, sz);
            } else {
                int vid2 = vid - 512;
                int r = vid2 >> 3, q = vid2 & 7;
                cp_async16(sV + (buf * KVSZ + r * AS + q * 8) * 2,
                           Vt + (size_t)(h * 64 + r) * MEMP + m0 + q * 8, 16);
            }
        }
        CP_COMMIT();
    };

    load_kv(0, 0);

    // stage Q, then hoist its fragments into registers
    #pragma unroll
    for (int it = 0; it < 4; ++it) {
        int vid = tid + it * 256;
        int r = vid >> 3, q = vid & 7;
        uint4 v = *(const uint4*)(Q + (size_t)(b0 + r) * 512 + h * 64 + q * 8);
        *(uint4*)(Qs + r * AS + q * 8) = v;
    }
    __syncthreads();
    uint32_t qa[4][4];
    #pragma unroll
    for (int ks = 0; ks < 4; ++ks)
        ldsm_x4(qa[ks], sQ + ((qr + lane16) * AS + ks * 16 + laneHi * 8) * 2);

    float oacc[8][4];
    float rsum[2] = {0.f, 0.f};
    #pragma unroll
    for (int nf = 0; nf < 8; ++nf)
        #pragma unroll
        for (int c = 0; c < 4; ++c) oacc[nf][c] = 0.f;

    for (int ci = 0; ci < MEMP / 64; ++ci) {
        const int m0 = ci * 64;
        const int buf = ci & 1;
        if (ci + 1 < MEMP / 64) { load_kv(m0 + 64, buf ^ 1); CP_WAIT(1); }
        else                    { CP_WAIT(0); }
        __syncthreads();

        const uint32_t kbase = sK + buf * KVSZ * 2;
        const uint32_t vbase = sV + buf * KVSZ * 2;

        // ---- S = Q K^T ----
        float sacc[8][4];
        #pragma unroll
        for (int nf = 0; nf < 8; ++nf)
            #pragma unroll
            for (int c = 0; c < 4; ++c) sacc[nf][c] = 0.f;
        #pragma unroll
        for (int ks = 0; ks < 4; ++ks) {
            const uint32_t kb = ks * 32;
            #pragma unroll
            for (int nf = 0; nf < 8; ++nf) {
                uint32_t b0, b1;
                ldsm_x2(b0, b1, kbase + kvoff[nf] + kb);
                mma_f16(sacc[nf], qa[ks][0], qa[ks][1], qa[ks][2], qa[ks][3], b0, b1);
            }
        }

        // ---- softmax numerator; pack P into A-fragments in registers ----
        uint32_t pa[4][4];
        #pragma unroll
        for (int nf = 0; nf < 8; ++nf) {
            float p0 = 0.f, p1 = 0.f, p2 = 0.f, p3 = 0.f;
            bool in0 = (m0 + nf * 8 + 2 * t) < MEM;
            bool in1 = (m0 + nf * 8 + 2 * t + 1) < MEM;
            if (in0) { p0 = __expf(sacc[nf][0]); p2 = __expf(sacc[nf][2]); }
            if (in1) { p1 = __expf(sacc[nf][1]); p3 = __expf(sacc[nf][3]); }
            rsum[0] += p0 + p1;
            rsum[1] += p2 + p3;
            __half2 lo = __floats2half2_rn(p0, p1);
            __half2 hi = __floats2half2_rn(p2, p3);
            pa[nf >> 1][(nf & 1) * 2 + 0] = *(uint32_t*)&lo;
            pa[nf >> 1][(nf & 1) * 2 + 1] = *(uint32_t*)&hi;
        }

        // ---- O += P V ----
        #pragma unroll
        for (int ks = 0; ks < 4; ++ks) {
            const uint32_t kb = ks * 32;
            #pragma unroll
            for (int nf = 0; nf < 8; ++nf) {
                uint32_t b0, b1;
                ldsm_x2(b0, b1, vbase + kvoff[nf] + kb);
                mma_f16(oacc[nf], pa[ks][0], pa[ks][1], pa[ks][2], pa[ks][3], b0, b1);
            }
        }
        __syncthreads();
    }

    // deferred row-sum reduction over t lanes
    #pragma unroll
    for (int r01 = 0; r01 < 2; ++r01) {
        rsum[r01] += __shfl_xor_sync(0xffffffffu, rsum[r01], 1);
        rsum[r01] += __shfl_xor_sync(0xffffffffu, rsum[r01], 2);
    }

    #pragma unroll
    for (int r01 = 0; r01 < 2; ++r01) {
        float inv = 1.f / rsum[r01];
        int grow = b0 + qr + g + r01 * 8;
        #pragma unroll
        for (int nf = 0; nf < 8; ++nf) {
            __half2 o = __floats2half2_rn(oacc[nf][r01 * 2 + 0] * inv,
                                          oacc[nf][r01 * 2 + 1] * inv);
            *(__half2*)(ctx + (size_t)grow * 512 + h * 64 + nf * 8 + 2 * t) = o;
        }
    }
}

// ==================== LayerNorm: warp-per-row, fp32 in, fp16 out =============
__global__ void __launch_bounds__(256) ln_kernel(
    const float* __restrict__ x, const float* __restrict__ g,
    const float* __restrict__ b, __half* __restrict__ y)
{
    const int warp = threadIdx.x >> 5, lane = threadIdx.x & 31;
    const int row = blockIdx.x * 8 + warp;
    const float* xr = x + (size_t)row * 512;

    float4 v[4];
    #pragma unroll
    for (int i = 0; i < 4; ++i)
        v[i] = *(const float4*)(xr + i * 128 + lane * 4);

    float s = 0.f;
    #pragma unroll
    for (int i = 0; i < 4; ++i) s += v[i].x + v[i].y + v[i].z + v[i].w;
    #pragma unroll
    for (int o = 16; o > 0; o >>= 1) s += __shfl_xor_sync(0xffffffffu, s, o);
    float mean = s * (1.f / 512.f);

    float ss = 0.f;
    #pragma unroll
    for (int i = 0; i < 4; ++i) {
        v[i].x -= mean; v[i].y -= mean; v[i].z -= mean; v[i].w -= mean;
        ss += v[i].x * v[i].x + v[i].y * v[i].y + v[i].z * v[i].z + v[i].w * v[i].w;
    }
    #pragma unroll
    for (int o = 16; o > 0; o >>= 1) ss += __shfl_xor_sync(0xffffffffu, ss, o);
    float inv = rsqrtf(ss * (1.f / 512.f) + 1e-5f);

    #pragma unroll
    for (int i = 0; i < 4; ++i) {
        float4 gg = *(const float4*)(g + i * 128 + lane * 4);
        float4 bb = *(const float4*)(b + i * 128 + lane * 4);
        __half2 lo = __floats2half2_rn(v[i].x * inv * gg.x + bb.x,
                                       v[i].y * inv * gg.y + bb.y);
        __half2 hi = __floats2half2_rn(v[i].z * inv * gg.z + bb.z,
                                       v[i].w * inv * gg.w + bb.w);
        uint2 pk; pk.x = *(uint32_t*)&lo; pk.y = *(uint32_t*)&hi;
        *(uint2*)(y + (size_t)row * 512 + i * 128 + lane * 4) = pk;
    }
}

// ==================== mask compaction + memory EMA ====================
__global__ void __launch_bounds__(256) compact_kernel(
    const float* __restrict__ quality, int* __restrict__ midx, int* __restrict__ mcount)
{
    const int tid = threadIdx.x;
    const int base = tid * 32;
    int cnt = 0;
    for (int i = 0; i < 32; ++i) cnt += (quality[base + i] > 0.7f) ? 1 : 0;
    __shared__ int sc[256];
    __shared__ int offs[256];
    sc[tid] = cnt;
    __syncthreads();
    if (tid == 0) {
        int run = 0;
        for (int t = 0; t < 256; ++t) { offs[t] = run; run += sc[t]; }
        *mcount = run;
    }
    __syncthreads();
    int o = offs[tid];
    for (int i = 0; i < 32; ++i)
        if (quality[base + i] > 0.7f) midx[o++] = base + i;
}

__global__ void __launch_bounds__(128) memupd_kernel(
    const float* __restrict__ wm, const float* __restrict__ ns,
    const int* __restrict__ upd, const int* __restrict__ midx,
    const int* __restrict__ mcount, float* __restrict__ outmem)
{
    const int m = blockIdx.x;
    const int d = threadIdx.x * 4;
    float4 v = *(const float4*)(wm + (size_t)m * 512 + d);
    const int cnt = *mcount;
    for (int jj = 0; jj < cnt; ++jj) {
        int i = midx[jj];
        if (upd[i] == m) {
            float4 s = *(const float4*)(ns + (size_t)i * 512 + d);
            v.x = 0.9f * v.x + 0.1f * s.x;
            v.y = 0.9f * v.y + 0.1f * s.y;
            v.z = 0.9f * v.z + 0.1f * s.z;
            v.w = 0.9f * v.w + 0.1f * s.w;
        }
    }
    *(float4*)(outmem + (size_t)m * 512 + d) = v;
}

// ==================== host launcher ====================
extern "C" void kernel_launch(void* const* d_in, const int* in_sizes, int n_in,
                              void* d_out, int out_size)
{
    const float* obs    = (const float*)d_in[0];
    const float* ego    = (const float*)d_in[1];
    const float* wm     = (const float*)d_in[2];
    const float* enc_w1 = (const float*)d_in[3];
    const float* enc_b1 = (const float*)d_in[4];
    const float* enc_g  = (const float*)d_in[5];
    const float* enc_be = (const float*)d_in[6];
    const float* enc_w2 = (const float*)d_in[7];
    const float* enc_b2 = (const float*)d_in[8];
    const float* wq     = (const float*)d_in[9];
    const float* bq     = (const float*)d_in[10];
    const float* wk     = (const float*)d_in[11];
    const float* bk     = (const float*)d_in[12];
    const float* wv     = (const float*)d_in[13];
    const float* bv     = (const float*)d_in[14];
    const float* wo     = (const float*)d_in[15];
    const float* bo     = (const float*)d_in[16];
    const float* tr_w1  = (const float*)d_in[17];
    const float* tr_b1  = (const float*)d_in[18];
    const float* tr_g   = (const float*)d_in[19];
    const float* tr_be  = (const float*)d_in[20];
    const float* tr_w2  = (const float*)d_in[21];
    const float* tr_b2  = (const float*)d_in[22];
    const float* q_w1   = (const float*)d_in[23];
    const float* q_b1   = (const float*)d_in[24];
    const float* q_w2   = (const float*)d_in[25];
    const float* q_b2   = (const float*)d_in[26];
    const int*   uidx   = (const int*)d_in[27];

    float* out        = (float*)d_out;
    float* next_state = out;
    float* quality    = out + (size_t)BATCH * DIM;
    float* outmem     = quality + BATCH;

    float *h, *enc;
    __half *hn_h, *enc_h, *q_h, *ctx_h, *fused_h, *ns_h, *k_h, *vt_h;
    __half *obs_h, *ego_h, *wm_h, *w_h;
    int *midx, *mcount;
    cudaGetSymbolAddress((void**)&h,      g_h);
    cudaGetSymbolAddress((void**)&enc,    g_enc);
    cudaGetSymbolAddress((void**)&hn_h,   g_hn_h);
    cudaGetSymbolAddress((void**)&enc_h,  g_enc_h);
    cudaGetSymbolAddress((void**)&q_h,    g_q_h);
    cudaGetSymbolAddress((void**)&ctx_h,  g_ctx_h);
    cudaGetSymbolAddress((void**)&fused_h,g_fused_h);
    cudaGetSymbolAddress((void**)&ns_h,   g_ns_h);
    cudaGetSymbolAddress((void**)&k_h,    g_k_h);
    cudaGetSymbolAddress((void**)&vt_h,   g_vt_h);
    cudaGetSymbolAddress((void**)&obs_h,  g_obs_h);
    cudaGetSymbolAddress((void**)&ego_h,  g_ego_h);
    cudaGetSymbolAddress((void**)&wm_h,   g_wm_h);
    cudaGetSymbolAddress((void**)&w_h,    g_w_h);
    cudaGetSymbolAddress((void**)&midx,   g_midx);
    cudaGetSymbolAddress((void**)&mcount, g_mcount);

    cudaFuncSetAttribute(gemm_mma<1>, cudaFuncAttributeMaxDynamicSharedMemorySize, GEMM_SMEM);
    cudaFuncSetAttribute(gemm_mma<2>, cudaFuncAttributeMaxDynamicSharedMemorySize, GEMM_SMEM);
    cudaFuncSetAttribute(gemm_mma<3>, cudaFuncAttributeMaxDynamicSharedMemorySize, GEMM_SMEM);
    cudaFuncSetAttribute(gemm_mma<4>, cudaFuncAttributeMaxDynamicSharedMemorySize, GEMM_SMEM);
    cudaFuncSetAttribute(gemm_mma<5>, cudaFuncAttributeMaxDynamicSharedMemorySize, GEMM_SMEM);
    cudaFuncSetAttribute(gemm_mma<6>, cudaFuncAttributeMaxDynamicSharedMemorySize, GEMM_SMEM);
    cudaFuncSetAttribute(gemm_mma<7>, cudaFuncAttributeMaxDynamicSharedMemorySize, GEMM_SMEM);
    cudaFuncSetAttribute(attn_mma,    cudaFuncAttributeMaxDynamicSharedMemorySize, ATT_SMEM);

    // persistent side-stream + events (handles reused; recorded fresh each call)
    static cudaStream_t s1 = nullptr;
    static cudaEvent_t  eP = nullptr, eKV = nullptr;
    if (s1 == nullptr) {
        cudaStreamCreateWithFlags(&s1, cudaStreamNonBlocking);
        cudaEventCreateWithFlags(&eP,  cudaEventDisableTiming);
        cudaEventCreateWithFlags(&eKV, cudaEventDisableTiming);
    }

    // ---- prep: fp32 -> fp16 ----
    PrepArgs pa;
    const float* srcs[12] = {obs, ego, wm, enc_w1, enc_w2, wq, wk, wv, wo, tr_w1, tr_w2, q_w1};
    __half* dsts[12] = {obs_h, ego_h, wm_h,
                        w_h + W_ENC1, w_h + W_ENC2, w_h + W_WQ, w_h + W_WK, w_h + W_WV,
                        w_h + W_WO, w_h + W_TR1, w_h + W_TR2, w_h + W_Q1};
    int n4s[12] = {BATCH*DIM/4, BATCH*16/4, MEM*DIM/4,
                   262144/4, 262144/4, 262144/4, 262144/4, 262144/4,
                   262144/4, 270336/4, 262144/4, 65536/4};
    for (int i = 0; i < 12; ++i) { pa.src[i] = srcs[i]; pa.dst[i] = dsts[i]; pa.n4[i] = n4s[i]; }
    prep_kernel<<<dim3(512, 12), 256>>>(pa);

    dim3 gBig(4, 64), gK(4, 8), gVt(8, 4), gQual(1, 64);

    // ---- fork: K + Vt projections on side stream (depend only on prep) ----
    cudaEventRecord(eP, 0);
    cudaStreamWaitEvent(s1, eP, 0);
    gemm_mma<4><<<gK, 256, GEMM_SMEM, s1>>>(wm_h, nullptr, w_h + W_WK, bk,
        nullptr, nullptr, nullptr, k_h, nullptr, MEM, 512, 8, 512);
    gemm_mma<7><<<gVt, 256, GEMM_SMEM, s1>>>(w_h + W_WV, nullptr, wm_h, bv,
        nullptr, nullptr, nullptr, vt_h, nullptr, 512, 512, 8, MEMP);
    cudaEventRecord(eKV, s1);

    // ---- main chain on stream 0 ----
    gemm_mma<1><<<gBig, 256, GEMM_SMEM>>>(obs_h, nullptr, w_h + W_ENC1, enc_b1,
        nullptr, nullptr, nullptr, h, nullptr, BATCH, 512, 8, 512);
    ln_kernel<<<BATCH/8, 256>>>(h, enc_g, enc_be, hn_h);
    gemm_mma<5><<<gBig, 256, GEMM_SMEM>>>(hn_h, nullptr, w_h + W_ENC2, enc_b2,
        nullptr, nullptr, nullptr, enc, enc_h, BATCH, 512, 8, 512);
    gemm_mma<6><<<gBig, 256, GEMM_SMEM>>>(enc_h, nullptr, w_h + W_WQ, bq,
        nullptr, nullptr, nullptr, q_h, nullptr, BATCH, 512, 8, 512);
    // join K/V before attention
    cudaStreamWaitEvent(0, eKV, 0);
    attn_mma<<<dim3(HEADS, BATCH / 128), 256, ATT_SMEM>>>(q_h, k_h, vt_h, ctx_h);
    // out projection + fuse (F = enc fp32)
    gemm_mma<2><<<gBig, 256, GEMM_SMEM>>>(ctx_h, nullptr, w_h + W_WO, bo,
        enc, nullptr, nullptr, fused_h, nullptr, BATCH, 512, 8, 512);
    // transition (K=528, ego in 9th K-chunk)
    gemm_mma<1><<<gBig, 256, GEMM_SMEM>>>(fused_h, ego_h, w_h + W_TR1, tr_b1,
        nullptr, nullptr, nullptr, h, nullptr, BATCH, 528, 9, 512);
    ln_kernel<<<BATCH/8, 256>>>(h, tr_g, tr_be, hn_h);
    gemm_mma<5><<<gBig, 256, GEMM_SMEM>>>(hn_h, nullptr, w_h + W_TR2, tr_b2,
        nullptr, nullptr, nullptr, next_state, ns_h, BATCH, 512, 8, 512);
    // quality head
    gemm_mma<3><<<gQual, 256, GEMM_SMEM>>>(ns_h, nullptr, w_h + W_Q1, q_b1,
        nullptr, q_w2, q_b2, quality, nullptr, BATCH, 512, 8, 512);
    // memory bank update
    compact_kernel<<<1, 256>>>(quality, midx, mcount);
    memupd_kernel<<<MEM, 128>>>(wm, next_state, uidx, midx, mcount, outmem);
}